// round 1
// baseline (speedup 1.0000x reference)
#include <cuda_runtime.h>
#include <math.h>

#define Gn 8
#define Mn 1024
#define Hn 256
#define HEADSn 8
#define HDn 32
#define FFNn 1024
#define Nn (Gn*Mn)          // 8192
#define En 131072
#define MWn (Mn/32)         // 32

// ---------------- scratch (device globals: no allocation allowed) ----------
static __device__ float g_xw[Nn*Hn];
static __device__ float g_xlocal[Nn*Hn];
static __device__ float g_dinv[Nn];
static __device__ int   g_deg[Nn];
static __device__ unsigned g_adj[Gn*Mn*MWn];
static __device__ unsigned char g_dist[(size_t)Gn*Mn*Mn];   // 8 MB
static __device__ float g_qkv[Nn*3*Hn];
static __device__ float g_attn[Nn*Hn];
static __device__ float g_buf[Nn*Hn];
static __device__ float g_h[Nn*Hn];
static __device__ float g_h2[Nn*Hn];
static __device__ float g_y[Nn*Hn];
static __device__ float g_ff[Nn*FFNn];

// ---------------- small helpers -------------------------------------------
__device__ __forceinline__ float gelu_exact(float x) {
    return 0.5f * x * (1.0f + erff(x * 0.7071067811865475f));
}

// ---------------- init: deg=1, adj=0 ---------------------------------------
__global__ void init_deg_adj_kernel() {
    int i = blockIdx.x * blockDim.x + threadIdx.x;
    if (i < Nn) g_deg[i] = 1;
    if (i < Gn*Mn*MWn) g_adj[i] = 0;
}

// ---------------- per-edge: deg count + adjacency bits ---------------------
__global__ void edge_prep_kernel(const int* __restrict__ src, const int* __restrict__ dst) {
    int e = blockIdx.x * blockDim.x + threadIdx.x;
    if (e >= En) return;
    int s = src[e], d = dst[e];
    atomicAdd(&g_deg[d], 1);
    if (s != d) {
        int g  = s >> 10;
        int ls = s & 1023, ld = d & 1023;
        atomicOr(&g_adj[(g*Mn + ls)*MWn + (ld >> 5)], 1u << (ld & 31));
        atomicOr(&g_adj[(g*Mn + ld)*MWn + (ls >> 5)], 1u << (ls & 31));
    }
}

__global__ void dinv_kernel() {
    int i = blockIdx.x * blockDim.x + threadIdx.x;
    if (i < Nn) g_dinv[i] = rsqrtf((float)g_deg[i]);
}

// ---------------- GCN: self-loop term + bias -------------------------------
__global__ void xlocal_init_kernel(const float* __restrict__ gcn_b) {
    size_t i = (size_t)blockIdx.x * blockDim.x + threadIdx.x;
    if (i >= (size_t)Nn*Hn) return;
    int n = (int)(i >> 8), f = (int)(i & 255);
    float di = g_dinv[n];
    g_xlocal[i] = g_xw[i] * di * di + gcn_b[f];
}

// ---------------- GCN: edge scatter (warp per edge) ------------------------
__global__ void gcn_scatter_kernel(const int* __restrict__ src, const int* __restrict__ dst) {
    int w = (blockIdx.x * blockDim.x + threadIdx.x) >> 5;
    int lane = threadIdx.x & 31;
    if (w >= En) return;
    int s = src[w], d = dst[w];
    float wgt = g_dinv[s] * g_dinv[d];
    const float* xr = g_xw + (size_t)s * Hn;
    float* yr = g_xlocal + (size_t)d * Hn;
#pragma unroll
    for (int f = lane; f < Hn; f += 32)
        atomicAdd(&yr[f], xr[f] * wgt);
}

// ---------------- SPD: per-row bitset BFS (warp per row) -------------------
__global__ void bfs_kernel() {
    int row = blockIdx.x * (blockDim.x >> 5) + (threadIdx.x >> 5);
    int lane = threadIdx.x & 31;
    if (row >= Gn*Mn) return;
    int g = row >> 10, i = row & 1023;
    const unsigned* arow = g_adj + (size_t)row * MWn;
    unsigned frontier = arow[lane];
    unsigned diag = ((i >> 5) == lane) ? (1u << (i & 31)) : 0u;
    unsigned visited = frontier | diag;
    unsigned char* drow = g_dist + (size_t)row * Mn;

    // dist row init: 1 where adj, 0 on diag, 6 elsewhere; packed 4B stores
#pragma unroll
    for (int p = 0; p < 8; p++) {
        unsigned word = 0;
#pragma unroll
        for (int b = 0; b < 4; b++) {
            int bi = p*4 + b;
            int k = lane*32 + bi;
            unsigned char v = ((frontier >> bi) & 1u) ? 1 : ((k == i) ? 0 : 6);
            word |= ((unsigned)v) << (8*b);
        }
        *(unsigned*)(drow + lane*32 + p*4) = word;
    }

    for (int d = 2; d <= 5; d++) {
        unsigned newf = 0;
#pragma unroll 1
        for (int ws = 0; ws < 32; ws++) {
            unsigned fw = __shfl_sync(0xffffffffu, frontier, ws);
            while (fw) {
                int b = __ffs(fw) - 1; fw &= fw - 1;
                int j = ws*32 + b;
                newf |= g_adj[((size_t)g*Mn + j)*MWn + lane];
            }
        }
        newf &= ~visited;
        visited |= newf;
        unsigned t = newf;
        while (t) {
            int b = __ffs(t) - 1; t &= t - 1;
            drow[lane*32 + b] = (unsigned char)d;
        }
        frontier = newf;
        if (!__any_sync(0xffffffffu, newf != 0u)) break;
    }
}

// ---------------- generic fp32 GEMM: C = act(A[M,K] * B[N,K]^T + bias) -----
__global__ __launch_bounds__(256) void gemm_nt_kernel(
    const float* __restrict__ A, const float* __restrict__ B,
    const float* __restrict__ bias, float* __restrict__ C,
    int Nc, int K, int act)
{
    __shared__ float As[16][64];
    __shared__ float Bs[16][64];
    int bm = blockIdx.y * 64, bn = blockIdx.x * 64;
    int tid = threadIdx.x;
    int tx = tid & 15, ty = tid >> 4;
    float acc[4][4] = {};

    int idx = tid * 4;
    int lm = idx >> 4;        // 0..63
    int lk = idx & 15;        // 0,4,8,12
    const float* Ap = A + (size_t)(bm + lm) * K + lk;
    const float* Bp = B + (size_t)(bn + lm) * K + lk;

    for (int k0 = 0; k0 < K; k0 += 16) {
        float4 av = *(const float4*)(Ap + k0);
        float4 bv = *(const float4*)(Bp + k0);
        As[lk+0][lm] = av.x; As[lk+1][lm] = av.y; As[lk+2][lm] = av.z; As[lk+3][lm] = av.w;
        Bs[lk+0][lm] = bv.x; Bs[lk+1][lm] = bv.y; Bs[lk+2][lm] = bv.z; Bs[lk+3][lm] = bv.w;
        __syncthreads();
#pragma unroll
        for (int kk = 0; kk < 16; kk++) {
            float4 a = *(const float4*)&As[kk][ty*4];
            float4 b = *(const float4*)&Bs[kk][tx*4];
            float ar[4] = {a.x, a.y, a.z, a.w};
            float br[4] = {b.x, b.y, b.z, b.w};
#pragma unroll
            for (int i = 0; i < 4; i++)
#pragma unroll
                for (int j = 0; j < 4; j++)
                    acc[i][j] += ar[i] * br[j];
        }
        __syncthreads();
    }

    float bsv[4] = {0,0,0,0};
    if (bias) {
        float4 b4 = *(const float4*)&bias[bn + tx*4];
        bsv[0]=b4.x; bsv[1]=b4.y; bsv[2]=b4.z; bsv[3]=b4.w;
    }
#pragma unroll
    for (int i = 0; i < 4; i++) {
        float4 o;
        float v0 = acc[i][0]+bsv[0], v1 = acc[i][1]+bsv[1], v2 = acc[i][2]+bsv[2], v3 = acc[i][3]+bsv[3];
        if (act) { v0=gelu_exact(v0); v1=gelu_exact(v1); v2=gelu_exact(v2); v3=gelu_exact(v3); }
        o.x=v0; o.y=v1; o.z=v2; o.w=v3;
        *(float4*)(C + (size_t)(bm + ty*4 + i) * Nc + bn + tx*4) = o;
    }
}

// ---------------- fused attention (flash-style streaming softmax) ----------
__global__ __launch_bounds__(256) void attn_kernel(const float* __restrict__ bias_emb) {
    __shared__ float Qs[64][33];
    __shared__ float Ks[64][33];
    __shared__ float Vs[64][33];
    __shared__ float Ss[64][65];
    __shared__ float m_s[64], l_s[64], f_s[64];
    __shared__ float btab[8];

    int g = blockIdx.z, head = blockIdx.y, q0 = blockIdx.x * 64;
    int tid = threadIdx.x;
    if (tid < 7) btab[tid] = bias_emb[tid];
    if (tid < 64) { m_s[tid] = -1e30f; l_s[tid] = 0.0f; }

    for (int i = tid; i < 64*32; i += 256) {
        int q = i >> 5, dd = i & 31;
        Qs[q][dd] = g_qkv[(size_t)(g*Mn + q0 + q)*768 + head*32 + dd];
    }

    float acc[8] = {};
    int d  = tid & 31;
    int qg = tid >> 5;
    const float scale = 0.17677669529663687f;   // 32^-0.5

    for (int tk = 0; tk < 16; tk++) {
        __syncthreads();
        for (int i = tid; i < 64*32; i += 256) {
            int kk = i >> 5, dd = i & 31;
            size_t base = (size_t)(g*Mn + tk*64 + kk)*768 + head*32 + dd;
            Ks[kk][dd] = g_qkv[base + 256];
            Vs[kk][dd] = g_qkv[base + 512];
        }
        __syncthreads();

        // scores
        {
            int kk = tid & 63;
            int qb = tid >> 6;
#pragma unroll
            for (int i = 0; i < 16; i++) {
                int q = qb + i*4;
                float s = 0.0f;
#pragma unroll
                for (int dd = 0; dd < 32; dd++) s += Qs[q][dd] * Ks[kk][dd];
                unsigned char dv = g_dist[(size_t)(g*Mn + q0 + q)*Mn + tk*64 + kk];
                Ss[q][kk] = s * scale + btab[dv];
            }
        }
        __syncthreads();

        // online softmax row update: 4 threads per row
        {
            int q = tid >> 2, sub = tid & 3;
            float rm = -1e30f;
#pragma unroll
            for (int k = sub*16; k < sub*16 + 16; k++) rm = fmaxf(rm, Ss[q][k]);
            rm = fmaxf(rm, __shfl_xor_sync(0xffffffffu, rm, 1));
            rm = fmaxf(rm, __shfl_xor_sync(0xffffffffu, rm, 2));
            rm = fmaxf(rm, m_s[q]);
            float rs = 0.0f;
#pragma unroll
            for (int k = sub*16; k < sub*16 + 16; k++) {
                float p = expf(Ss[q][k] - rm);
                Ss[q][k] = p; rs += p;
            }
            rs += __shfl_xor_sync(0xffffffffu, rs, 1);
            rs += __shfl_xor_sync(0xffffffffu, rs, 2);
            if (sub == 0) {
                float f = expf(m_s[q] - rm);
                f_s[q] = f;
                l_s[q] = l_s[q]*f + rs;
                m_s[q] = rm;
            }
        }
        __syncthreads();

        // accumulate P @ V
#pragma unroll
        for (int i = 0; i < 8; i++) {
            int q = qg*8 + i;
            float a = acc[i] * f_s[q];
#pragma unroll 8
            for (int k = 0; k < 64; k++) a += Ss[q][k] * Vs[k][d];
            acc[i] = a;
        }
    }
    __syncthreads();
#pragma unroll
    for (int i = 0; i < 8; i++) {
        int q = qg*8 + i;
        g_attn[(size_t)(g*Mn + q0 + q)*Hn + head*32 + d] = acc[i] / l_s[q];
    }
}

// ---------------- LayerNorm: out = LN(a [+ b] [+ c]) * gamma + beta --------
__global__ __launch_bounds__(256) void ln_kernel(
    const float* __restrict__ a, const float* __restrict__ b, const float* __restrict__ c,
    const float* __restrict__ gam, const float* __restrict__ bet, float* __restrict__ out)
{
    __shared__ float red[256];
    int row = blockIdx.x, t = threadIdx.x;
    size_t off = (size_t)row * Hn + t;
    float v = a[off];
    if (b) v += b[off];
    if (c) v += c[off];
    red[t] = v; __syncthreads();
    for (int s = 128; s > 0; s >>= 1) { if (t < s) red[t] += red[t+s]; __syncthreads(); }
    float mean = red[0] * (1.0f / Hn);
    __syncthreads();
    float dv = v - mean;
    red[t] = dv * dv; __syncthreads();
    for (int s = 128; s > 0; s >>= 1) { if (t < s) red[t] += red[t+s]; __syncthreads(); }
    float var = red[0] * (1.0f / Hn);
    out[off] = dv * rsqrtf(var + 1e-5f) * gam[t] + bet[t];
}

// ---------------- host launch ----------------------------------------------
static float* sym_addr(const void* s) {
    void* p = nullptr;
    cudaGetSymbolAddress(&p, s);
    return (float*)p;
}

extern "C" void kernel_launch(void* const* d_in, const int* in_sizes, int n_in,
                              void* d_out, int out_size) {
    const float* x      = (const float*)d_in[0];
    const float* gcn_w  = (const float*)d_in[1];
    const float* gcn_b  = (const float*)d_in[2];
    const float* qkv_w  = (const float*)d_in[3];
    const float* qkv_b  = (const float*)d_in[4];
    const float* proj_w = (const float*)d_in[5];
    const float* proj_b = (const float*)d_in[6];
    const float* ln1_g  = (const float*)d_in[7];
    const float* ln1_b  = (const float*)d_in[8];
    const float* ln2_g  = (const float*)d_in[9];
    const float* ln2_b  = (const float*)d_in[10];
    const float* ffn1_w = (const float*)d_in[11];
    const float* ffn1_b = (const float*)d_in[12];
    const float* ffn2_w = (const float*)d_in[13];
    const float* ffn2_b = (const float*)d_in[14];
    const float* bias_e = (const float*)d_in[15];
    const float* oln1_g = (const float*)d_in[16];
    const float* oln1_b = (const float*)d_in[17];
    const float* oln2_g = (const float*)d_in[18];
    const float* oln2_b = (const float*)d_in[19];
    const float* offn1_w= (const float*)d_in[20];
    const float* offn1_b= (const float*)d_in[21];
    const float* offn2_w= (const float*)d_in[22];
    const float* offn2_b= (const float*)d_in[23];
    const int*   eidx   = (const int*)d_in[24];
    const int* src = eidx;
    const int* dst = eidx + En;
    float* out = (float*)d_out;

    float* p_xw  = sym_addr(g_xw);
    float* p_xl  = sym_addr(g_xlocal);
    float* p_qkv = sym_addr(g_qkv);
    float* p_att = sym_addr(g_attn);
    float* p_buf = sym_addr(g_buf);
    float* p_h   = sym_addr(g_h);
    float* p_h2  = sym_addr(g_h2);
    float* p_y   = sym_addr(g_y);
    float* p_ff  = sym_addr(g_ff);

    // GCN + graph prep
    init_deg_adj_kernel<<<1024, 256>>>();
    edge_prep_kernel<<<En/256, 256>>>(src, dst);
    dinv_kernel<<<Nn/256, 256>>>();
    gemm_nt_kernel<<<dim3(Hn/64, Nn/64), 256>>>(x, gcn_w, nullptr, p_xw, Hn, Hn, 0);
    xlocal_init_kernel<<<(Nn*Hn)/256, 256>>>(gcn_b);
    gcn_scatter_kernel<<<(En*32)/256, 256>>>(src, dst);
    bfs_kernel<<<(Gn*Mn)/4, 128>>>();

    // transformer
    gemm_nt_kernel<<<dim3(768/64, Nn/64), 256>>>(x, qkv_w, qkv_b, p_qkv, 768, Hn, 0);
    attn_kernel<<<dim3(Mn/64, HEADSn, Gn), 256>>>(bias_e);
    gemm_nt_kernel<<<dim3(Hn/64, Nn/64), 256>>>(p_att, proj_w, proj_b, p_buf, Hn, Hn, 0);
    ln_kernel<<<Nn, 256>>>(x, p_buf, nullptr, ln1_g, ln1_b, p_h);
    gemm_nt_kernel<<<dim3(FFNn/64, Nn/64), 256>>>(p_h, ffn1_w, ffn1_b, p_ff, FFNn, Hn, 1);
    gemm_nt_kernel<<<dim3(Hn/64, Nn/64), 256>>>(p_ff, ffn2_w, ffn2_b, p_buf, Hn, FFNn, 0);
    ln_kernel<<<Nn, 256>>>(p_h, p_buf, nullptr, ln2_g, ln2_b, p_h2);

    // GPS combine + outer FFN
    ln_kernel<<<Nn, 256>>>(x, p_xl, p_h2, oln1_g, oln1_b, p_y);
    gemm_nt_kernel<<<dim3(FFNn/64, Nn/64), 256>>>(p_y, offn1_w, offn1_b, p_ff, FFNn, Hn, 1);
    gemm_nt_kernel<<<dim3(Hn/64, Nn/64), 256>>>(p_ff, offn2_w, offn2_b, p_buf, Hn, FFNn, 0);
    ln_kernel<<<Nn, 256>>>(p_y, p_buf, nullptr, oln2_g, oln2_b, out);
}

// round 2
// speedup vs baseline: 1.8888x; 1.8888x over previous
#include <cuda_runtime.h>
#include <math.h>

#define Gn 8
#define Mn 1024
#define Hn 256
#define HEADSn 8
#define HDn 32
#define FFNn 1024
#define Nn (Gn*Mn)          // 8192
#define En 131072
#define MWn (Mn/32)         // 32

// ---------------- scratch (device globals: no allocation allowed) ----------
static __device__ float g_xw[Nn*Hn];
static __device__ float g_xlocal[Nn*Hn];
static __device__ float g_dinv[Nn];
static __device__ int   g_deg[Nn];
static __device__ unsigned g_adj[Gn*Mn*MWn];
static __device__ unsigned char g_dist[(size_t)Gn*Mn*Mn];   // 8 MB
static __device__ float g_qkv[Nn*3*Hn];
static __device__ float g_attn[Nn*Hn];
static __device__ float g_buf[Nn*Hn];
static __device__ float g_h[Nn*Hn];
static __device__ float g_h2[Nn*Hn];
static __device__ float g_y[Nn*Hn];
static __device__ float g_ff[Nn*FFNn];

// ---------------- helpers ---------------------------------------------------
__device__ __forceinline__ float gelu_exact(float x) {
    return 0.5f * x * (1.0f + erff(x * 0.7071067811865475f));
}

__device__ __forceinline__ unsigned f2tf(float x) {
    unsigned r;
    asm("cvt.rna.tf32.f32 %0, %1;" : "=r"(r) : "f"(x));
    return r;
}

__device__ __forceinline__ void mma_tf32(float c[4], const unsigned a[4],
                                         unsigned b0, unsigned b1) {
    asm volatile(
        "mma.sync.aligned.m16n8k8.row.col.f32.tf32.tf32.f32 "
        "{%0,%1,%2,%3},{%4,%5,%6,%7},{%8,%9},{%0,%1,%2,%3};"
        : "+f"(c[0]), "+f"(c[1]), "+f"(c[2]), "+f"(c[3])
        : "r"(a[0]), "r"(a[1]), "r"(a[2]), "r"(a[3]), "r"(b0), "r"(b1));
}

// ---------------- init: deg=1, adj=0 ---------------------------------------
__global__ void init_deg_adj_kernel() {
    int i = blockIdx.x * blockDim.x + threadIdx.x;
    if (i < Nn) g_deg[i] = 1;
    if (i < Gn*Mn*MWn) g_adj[i] = 0;
}

__global__ void edge_prep_kernel(const int* __restrict__ src, const int* __restrict__ dst) {
    int e = blockIdx.x * blockDim.x + threadIdx.x;
    if (e >= En) return;
    int s = src[e], d = dst[e];
    atomicAdd(&g_deg[d], 1);
    if (s != d) {
        int g  = s >> 10;
        int ls = s & 1023, ld = d & 1023;
        atomicOr(&g_adj[(g*Mn + ls)*MWn + (ld >> 5)], 1u << (ld & 31));
        atomicOr(&g_adj[(g*Mn + ld)*MWn + (ls >> 5)], 1u << (ls & 31));
    }
}

__global__ void dinv_kernel() {
    int i = blockIdx.x * blockDim.x + threadIdx.x;
    if (i < Nn) g_dinv[i] = rsqrtf((float)g_deg[i]);
}

__global__ void xlocal_init_kernel(const float* __restrict__ gcn_b) {
    size_t i = (size_t)blockIdx.x * blockDim.x + threadIdx.x;
    if (i >= (size_t)Nn*Hn) return;
    int n = (int)(i >> 8), f = (int)(i & 255);
    float di = g_dinv[n];
    g_xlocal[i] = g_xw[i] * di * di + gcn_b[f];
}

__global__ void gcn_scatter_kernel(const int* __restrict__ src, const int* __restrict__ dst) {
    int w = (blockIdx.x * blockDim.x + threadIdx.x) >> 5;
    int lane = threadIdx.x & 31;
    if (w >= En) return;
    int s = src[w], d = dst[w];
    float wgt = g_dinv[s] * g_dinv[d];
    const float* xr = g_xw + (size_t)s * Hn;
    float* yr = g_xlocal + (size_t)d * Hn;
#pragma unroll
    for (int f = lane; f < Hn; f += 32)
        atomicAdd(&yr[f], xr[f] * wgt);
}

// ---------------- SPD: per-row bitset BFS (warp per row) -------------------
__global__ void bfs_kernel() {
    int row = blockIdx.x * (blockDim.x >> 5) + (threadIdx.x >> 5);
    int lane = threadIdx.x & 31;
    if (row >= Gn*Mn) return;
    int g = row >> 10, i = row & 1023;
    const unsigned* arow = g_adj + (size_t)row * MWn;
    unsigned frontier = arow[lane];
    unsigned diag = ((i >> 5) == lane) ? (1u << (i & 31)) : 0u;
    unsigned visited = frontier | diag;
    unsigned char* drow = g_dist + (size_t)row * Mn;

#pragma unroll
    for (int p = 0; p < 8; p++) {
        unsigned word = 0;
#pragma unroll
        for (int b = 0; b < 4; b++) {
            int bi = p*4 + b;
            int k = lane*32 + bi;
            unsigned char v = ((frontier >> bi) & 1u) ? 1 : ((k == i) ? 0 : 6);
            word |= ((unsigned)v) << (8*b);
        }
        *(unsigned*)(drow + lane*32 + p*4) = word;
    }

    for (int d = 2; d <= 5; d++) {
        unsigned newf = 0;
#pragma unroll 1
        for (int ws = 0; ws < 32; ws++) {
            unsigned fw = __shfl_sync(0xffffffffu, frontier, ws);
            while (fw) {
                int b = __ffs(fw) - 1; fw &= fw - 1;
                int j = ws*32 + b;
                newf |= g_adj[((size_t)g*Mn + j)*MWn + lane];
            }
        }
        newf &= ~visited;
        visited |= newf;
        unsigned t = newf;
        while (t) {
            int b = __ffs(t) - 1; t &= t - 1;
            drow[lane*32 + b] = (unsigned char)d;
        }
        frontier = newf;
        if (!__any_sync(0xffffffffu, newf != 0u)) break;
    }
}

// ---------------- tf32 tensor-core GEMM: C = act(A[M,K] * B[N,K]^T + bias) -
// 3-pass tf32 (hi/lo split) for near-fp32 accuracy.
// Block 256 threads, tile 128(M) x 64(N), K step 32. Warp grid 4x2, warp 32x32.
__global__ __launch_bounds__(256) void gemm_tc_kernel(
    const float* __restrict__ A, const float* __restrict__ B,
    const float* __restrict__ bias, float* __restrict__ C,
    int Nc, int K, int act)
{
    extern __shared__ unsigned gsm[];
    unsigned (*As_hi)[36] = (unsigned(*)[36])gsm;            // 128x36
    unsigned (*As_lo)[36] = (unsigned(*)[36])(gsm + 4608);
    unsigned (*Bs_hi)[36] = (unsigned(*)[36])(gsm + 9216);   // 64x36
    unsigned (*Bs_lo)[36] = (unsigned(*)[36])(gsm + 11520);

    int bm = blockIdx.y * 128, bn = blockIdx.x * 64;
    int tid = threadIdx.x;
    int warp = tid >> 5, lane = tid & 31;
    int wm = warp >> 1, wn = warp & 1;
    int lr = lane >> 2, lc = lane & 3;

    float acc[2][4][4];
#pragma unroll
    for (int i = 0; i < 2; i++)
#pragma unroll
        for (int j = 0; j < 4; j++)
#pragma unroll
            for (int r = 0; r < 4; r++) acc[i][j][r] = 0.0f;

    for (int k0 = 0; k0 < K; k0 += 32) {
        __syncthreads();
        // load A tile 128x32
#pragma unroll
        for (int l = 0; l < 4; l++) {
            int e = tid + l*256;           // float4 index, 1024 total
            int row = e >> 3, c4 = (e & 7) * 4;
            float4 v = *(const float4*)(A + (size_t)(bm + row) * K + k0 + c4);
            float vv[4] = {v.x, v.y, v.z, v.w};
#pragma unroll
            for (int j = 0; j < 4; j++) {
                unsigned h = f2tf(vv[j]);
                As_hi[row][c4+j] = h;
                As_lo[row][c4+j] = f2tf(vv[j] - __uint_as_float(h));
            }
        }
        // load B tile 64x32
#pragma unroll
        for (int l = 0; l < 2; l++) {
            int e = tid + l*256;           // float4 index, 512 total
            int row = e >> 3, c4 = (e & 7) * 4;
            float4 v = *(const float4*)(B + (size_t)(bn + row) * K + k0 + c4);
            float vv[4] = {v.x, v.y, v.z, v.w};
#pragma unroll
            for (int j = 0; j < 4; j++) {
                unsigned h = f2tf(vv[j]);
                Bs_hi[row][c4+j] = h;
                Bs_lo[row][c4+j] = f2tf(vv[j] - __uint_as_float(h));
            }
        }
        __syncthreads();

#pragma unroll
        for (int kk = 0; kk < 32; kk += 8) {
            unsigned ah[2][4], al[2][4];
#pragma unroll
            for (int mt = 0; mt < 2; mt++) {
                int rA = wm*32 + mt*16;
                ah[mt][0] = As_hi[rA+lr  ][kk+lc  ];
                ah[mt][1] = As_hi[rA+lr+8][kk+lc  ];
                ah[mt][2] = As_hi[rA+lr  ][kk+lc+4];
                ah[mt][3] = As_hi[rA+lr+8][kk+lc+4];
                al[mt][0] = As_lo[rA+lr  ][kk+lc  ];
                al[mt][1] = As_lo[rA+lr+8][kk+lc  ];
                al[mt][2] = As_lo[rA+lr  ][kk+lc+4];
                al[mt][3] = As_lo[rA+lr+8][kk+lc+4];
            }
#pragma unroll
            for (int nt = 0; nt < 4; nt++) {
                int cB = wn*32 + nt*8;
                unsigned bh0 = Bs_hi[cB+lr][kk+lc];
                unsigned bh1 = Bs_hi[cB+lr][kk+lc+4];
                unsigned bl0 = Bs_lo[cB+lr][kk+lc];
                unsigned bl1 = Bs_lo[cB+lr][kk+lc+4];
#pragma unroll
                for (int mt = 0; mt < 2; mt++) {
                    mma_tf32(acc[mt][nt], ah[mt], bh0, bh1);
                    mma_tf32(acc[mt][nt], al[mt], bh0, bh1);
                    mma_tf32(acc[mt][nt], ah[mt], bl0, bl1);
                }
            }
        }
    }

    // epilogue
#pragma unroll
    for (int mt = 0; mt < 2; mt++) {
#pragma unroll
        for (int nt = 0; nt < 4; nt++) {
            int m = bm + wm*32 + mt*16 + lr;
            int n = bn + wn*32 + nt*8 + lc*2;
            float b0 = 0.0f, b1 = 0.0f;
            if (bias) { b0 = bias[n]; b1 = bias[n+1]; }
            float v0 = acc[mt][nt][0] + b0;
            float v1 = acc[mt][nt][1] + b1;
            float v2 = acc[mt][nt][2] + b0;
            float v3 = acc[mt][nt][3] + b1;
            if (act) { v0 = gelu_exact(v0); v1 = gelu_exact(v1);
                       v2 = gelu_exact(v2); v3 = gelu_exact(v3); }
            float2 o0 = make_float2(v0, v1);
            float2 o1 = make_float2(v2, v3);
            *(float2*)(C + (size_t)m * Nc + n) = o0;
            *(float2*)(C + (size_t)(m+8) * Nc + n) = o1;
        }
    }
}

// ---------------- fused attention: tf32 mma + online softmax ---------------
// block = 256 threads (8 warps), q-tile 128, k-tile 64.
__global__ __launch_bounds__(256) void attn_tc_kernel(const float* __restrict__ bias_emb) {
    extern __shared__ unsigned smem_u[];
    unsigned (*Qs)[36] = (unsigned(*)[36])smem_u;               // 128x36
    unsigned (*Ks)[36] = (unsigned(*)[36])(smem_u + 4608);      // 64x36
    unsigned (*Vs)[36] = (unsigned(*)[36])(smem_u + 6912);      // 64x36
    float (*Ss)[68]    = (float(*)[68])(smem_u + 9216);         // 128x68
    float* m_s  = (float*)(smem_u + 9216 + 8704);
    float* l_s  = m_s + 128;
    float* f_s  = m_s + 256;
    float* btab = m_s + 384;

    int g = blockIdx.z, head = blockIdx.y, q0 = blockIdx.x * 128;
    int tid = threadIdx.x;
    int warp = tid >> 5, lane = tid & 31;
    int lr = lane >> 2, lc = lane & 3;
    const float scale = 0.17677669529663687f;   // 32^-0.5

    if (tid < 7) btab[tid] = bias_emb[tid];
    if (tid < 128) { m_s[tid] = -1e30f; l_s[tid] = 0.0f; }

    // load Q tile (scaled, tf32)
#pragma unroll
    for (int l = 0; l < 16; l++) {
        int e = tid + l*256;
        int row = e >> 5, col = e & 31;
        float v = g_qkv[(size_t)(g*Mn + q0 + row)*768 + head*32 + col] * scale;
        Qs[row][col] = f2tf(v);
    }

    float acc[4][4];
#pragma unroll
    for (int i = 0; i < 4; i++)
#pragma unroll
        for (int j = 0; j < 4; j++) acc[i][j] = 0.0f;

    int qb = warp * 16;

    for (int tk = 0; tk < 16; tk++) {
        __syncthreads();   // prev PV done; safe to overwrite Ks/Vs (and Ss below)
        // load K/V tile 64x32 each
#pragma unroll
        for (int l = 0; l < 8; l++) {
            int e = tid + l*256;
            int row = e >> 5, col = e & 31;
            size_t base = (size_t)(g*Mn + tk*64 + row)*768 + head*32 + col;
            Ks[row][col] = f2tf(g_qkv[base + 256]);
            Vs[row][col] = f2tf(g_qkv[base + 512]);
        }
        __syncthreads();

        // scores: warp w handles q rows [qb, qb+16), all 64 k cols
        {
            float sc[8][4];
#pragma unroll
            for (int nt = 0; nt < 8; nt++)
#pragma unroll
                for (int r = 0; r < 4; r++) sc[nt][r] = 0.0f;
#pragma unroll
            for (int kk = 0; kk < 32; kk += 8) {
                unsigned a[4];
                a[0] = Qs[qb+lr  ][kk+lc  ];
                a[1] = Qs[qb+lr+8][kk+lc  ];
                a[2] = Qs[qb+lr  ][kk+lc+4];
                a[3] = Qs[qb+lr+8][kk+lc+4];
#pragma unroll
                for (int nt = 0; nt < 8; nt++) {
                    unsigned b0 = Ks[nt*8+lr][kk+lc];
                    unsigned b1 = Ks[nt*8+lr][kk+lc+4];
                    mma_tf32(sc[nt], a, b0, b1);
                }
            }
#pragma unroll
            for (int nt = 0; nt < 8; nt++) {
                Ss[qb+lr  ][nt*8 + lc*2    ] = sc[nt][0];
                Ss[qb+lr  ][nt*8 + lc*2 + 1] = sc[nt][1];
                Ss[qb+lr+8][nt*8 + lc*2    ] = sc[nt][2];
                Ss[qb+lr+8][nt*8 + lc*2 + 1] = sc[nt][3];
            }
        }
        __syncthreads();

        // online softmax: 2 threads per row, 32 cols each; bias added here
        {
            int q = tid >> 1, sub = tid & 1;
            const uchar4* dp = (const uchar4*)(g_dist +
                (size_t)(g*Mn + q0 + q)*Mn + tk*64 + sub*32);
            float* srow = &Ss[q][sub*32];
            float rm = -1e30f;
#pragma unroll
            for (int j4 = 0; j4 < 8; j4++) {
                uchar4 dv = dp[j4];
                float s0 = srow[j4*4+0] + btab[dv.x];
                float s1 = srow[j4*4+1] + btab[dv.y];
                float s2 = srow[j4*4+2] + btab[dv.z];
                float s3 = srow[j4*4+3] + btab[dv.w];
                srow[j4*4+0] = s0; srow[j4*4+1] = s1;
                srow[j4*4+2] = s2; srow[j4*4+3] = s3;
                rm = fmaxf(rm, fmaxf(fmaxf(s0, s1), fmaxf(s2, s3)));
            }
            rm = fmaxf(rm, __shfl_xor_sync(0xffffffffu, rm, 1));
            rm = fmaxf(rm, m_s[q]);
            float rs = 0.0f;
#pragma unroll
            for (int j = 0; j < 32; j++) {
                float p = expf(srow[j] - rm);
                rs += p;
                srow[j] = __uint_as_float(f2tf(p));
            }
            rs += __shfl_xor_sync(0xffffffffu, rs, 1);
            if (sub == 0) {
                float f = expf(m_s[q] - rm);
                f_s[q] = f;
                l_s[q] = l_s[q]*f + rs;
                m_s[q] = rm;
            }
        }
        __syncthreads();

        // PV: warp w handles q rows [qb, qb+16), d cols 0..31 (4 n-tiles)
        {
            float f0 = f_s[qb+lr], f1 = f_s[qb+lr+8];
#pragma unroll
            for (int nt = 0; nt < 4; nt++) {
                acc[nt][0] *= f0; acc[nt][1] *= f0;
                acc[nt][2] *= f1; acc[nt][3] *= f1;
            }
#pragma unroll
            for (int kk = 0; kk < 64; kk += 8) {
                unsigned a[4];
                a[0] = __float_as_uint(Ss[qb+lr  ][kk+lc  ]);
                a[1] = __float_as_uint(Ss[qb+lr+8][kk+lc  ]);
                a[2] = __float_as_uint(Ss[qb+lr  ][kk+lc+4]);
                a[3] = __float_as_uint(Ss[qb+lr+8][kk+lc+4]);
#pragma unroll
                for (int nt = 0; nt < 4; nt++) {
                    unsigned b0 = Vs[kk+lc  ][nt*8+lr];
                    unsigned b1 = Vs[kk+lc+4][nt*8+lr];
                    mma_tf32(acc[nt], a, b0, b1);
                }
            }
        }
    }

    // write output
    float l0 = 1.0f / l_s[qb+lr];
    float l1 = 1.0f / l_s[qb+lr+8];
#pragma unroll
    for (int nt = 0; nt < 4; nt++) {
        int d = head*32 + nt*8 + lc*2;
        float2 o0 = make_float2(acc[nt][0]*l0, acc[nt][1]*l0);
        float2 o1 = make_float2(acc[nt][2]*l1, acc[nt][3]*l1);
        *(float2*)(g_attn + (size_t)(g*Mn + q0 + qb + lr  )*Hn + d) = o0;
        *(float2*)(g_attn + (size_t)(g*Mn + q0 + qb + lr+8)*Hn + d) = o1;
    }
}

// ---------------- LayerNorm: out = LN(a [+ b] [+ c]) * gamma + beta --------
__global__ __launch_bounds__(256) void ln_kernel(
    const float* __restrict__ a, const float* __restrict__ b, const float* __restrict__ c,
    const float* __restrict__ gam, const float* __restrict__ bet, float* __restrict__ out)
{
    __shared__ float red[256];
    int row = blockIdx.x, t = threadIdx.x;
    size_t off = (size_t)row * Hn + t;
    float v = a[off];
    if (b) v += b[off];
    if (c) v += c[off];
    red[t] = v; __syncthreads();
    for (int s = 128; s > 0; s >>= 1) { if (t < s) red[t] += red[t+s]; __syncthreads(); }
    float mean = red[0] * (1.0f / Hn);
    __syncthreads();
    float dv = v - mean;
    red[t] = dv * dv; __syncthreads();
    for (int s = 128; s > 0; s >>= 1) { if (t < s) red[t] += red[t+s]; __syncthreads(); }
    float var = red[0] * (1.0f / Hn);
    out[off] = dv * rsqrtf(var + 1e-5f) * gam[t] + bet[t];
}

// ---------------- host launch ----------------------------------------------
static float* sym_addr(const void* s) {
    void* p = nullptr;
    cudaGetSymbolAddress(&p, s);
    return (float*)p;
}

extern "C" void kernel_launch(void* const* d_in, const int* in_sizes, int n_in,
                              void* d_out, int out_size) {
    const float* x      = (const float*)d_in[0];
    const float* gcn_w  = (const float*)d_in[1];
    const float* gcn_b  = (const float*)d_in[2];
    const float* qkv_w  = (const float*)d_in[3];
    const float* qkv_b  = (const float*)d_in[4];
    const float* proj_w = (const float*)d_in[5];
    const float* proj_b = (const float*)d_in[6];
    const float* ln1_g  = (const float*)d_in[7];
    const float* ln1_b  = (const float*)d_in[8];
    const float* ln2_g  = (const float*)d_in[9];
    const float* ln2_b  = (const float*)d_in[10];
    const float* ffn1_w = (const float*)d_in[11];
    const float* ffn1_b = (const float*)d_in[12];
    const float* ffn2_w = (const float*)d_in[13];
    const float* ffn2_b = (const float*)d_in[14];
    const float* bias_e = (const float*)d_in[15];
    const float* oln1_g = (const float*)d_in[16];
    const float* oln1_b = (const float*)d_in[17];
    const float* oln2_g = (const float*)d_in[18];
    const float* oln2_b = (const float*)d_in[19];
    const float* offn1_w= (const float*)d_in[20];
    const float* offn1_b= (const float*)d_in[21];
    const float* offn2_w= (const float*)d_in[22];
    const float* offn2_b= (const float*)d_in[23];
    const int*   eidx   = (const int*)d_in[24];
    const int* src = eidx;
    const int* dst = eidx + En;
    float* out = (float*)d_out;

    float* p_xw  = sym_addr(g_xw);
    float* p_xl  = sym_addr(g_xlocal);
    float* p_qkv = sym_addr(g_qkv);
    float* p_att = sym_addr(g_attn);
    float* p_buf = sym_addr(g_buf);
    float* p_h   = sym_addr(g_h);
    float* p_h2  = sym_addr(g_h2);
    float* p_y   = sym_addr(g_y);
    float* p_ff  = sym_addr(g_ff);

    const int GEMM_SMEM = 13824 * 4;   // 55296 B
    const int ATTN_SMEM = 18312 * 4;   // 73248 B
    cudaFuncSetAttribute(gemm_tc_kernel, cudaFuncAttributeMaxDynamicSharedMemorySize, GEMM_SMEM);
    cudaFuncSetAttribute(attn_tc_kernel, cudaFuncAttributeMaxDynamicSharedMemorySize, ATTN_SMEM);

    // GCN + graph prep
    init_deg_adj_kernel<<<1024, 256>>>();
    edge_prep_kernel<<<En/256, 256>>>(src, dst);
    dinv_kernel<<<Nn/256, 256>>>();
    gemm_tc_kernel<<<dim3(Hn/64, Nn/128), 256, GEMM_SMEM>>>(x, gcn_w, nullptr, p_xw, Hn, Hn, 0);
    xlocal_init_kernel<<<(Nn*Hn)/256, 256>>>(gcn_b);
    gcn_scatter_kernel<<<(En*32)/256, 256>>>(src, dst);
    bfs_kernel<<<(Gn*Mn)/4, 128>>>();

    // transformer
    gemm_tc_kernel<<<dim3(768/64, Nn/128), 256, GEMM_SMEM>>>(x, qkv_w, qkv_b, p_qkv, 768, Hn, 0);
    attn_tc_kernel<<<dim3(Mn/128, HEADSn, Gn), 256, ATTN_SMEM>>>(bias_e);
    gemm_tc_kernel<<<dim3(Hn/64, Nn/128), 256, GEMM_SMEM>>>(p_att, proj_w, proj_b, p_buf, Hn, Hn, 0);
    ln_kernel<<<Nn, 256>>>(x, p_buf, nullptr, ln1_g, ln1_b, p_h);
    gemm_tc_kernel<<<dim3(FFNn/64, Nn/128), 256, GEMM_SMEM>>>(p_h, ffn1_w, ffn1_b, p_ff, FFNn, Hn, 1);
    gemm_tc_kernel<<<dim3(Hn/64, Nn/128), 256, GEMM_SMEM>>>(p_ff, ffn2_w, ffn2_b, p_buf, Hn, FFNn, 0);
    ln_kernel<<<Nn, 256>>>(p_h, p_buf, nullptr, ln2_g, ln2_b, p_h2);

    // GPS combine + outer FFN
    ln_kernel<<<Nn, 256>>>(x, p_xl, p_h2, oln1_g, oln1_b, p_y);
    gemm_tc_kernel<<<dim3(FFNn/64, Nn/128), 256, GEMM_SMEM>>>(p_y, offn1_w, offn1_b, p_ff, FFNn, Hn, 1);
    gemm_tc_kernel<<<dim3(Hn/64, Nn/128), 256, GEMM_SMEM>>>(p_ff, offn2_w, offn2_b, p_buf, Hn, FFNn, 0);
    ln_kernel<<<Nn, 256>>>(p_y, p_buf, nullptr, oln2_g, oln2_b, out);
}

// round 3
// speedup vs baseline: 2.0877x; 1.1053x over previous
#include <cuda_runtime.h>
#include <math.h>

#define Gn 8
#define Mn 1024
#define Hn 256
#define HEADSn 8
#define HDn 32
#define FFNn 1024
#define Nn (Gn*Mn)          // 8192
#define En 131072
#define MWn (Mn/32)         // 32

// ---------------- scratch (device globals: no allocation allowed) ----------
static __device__ float g_xw[Nn*Hn];
static __device__ float g_xlocal[Nn*Hn];
static __device__ float g_dinv[Nn];
static __device__ int   g_deg[Nn];
static __device__ unsigned g_adj[Gn*Mn*MWn];
static __device__ unsigned char g_dist[(size_t)Gn*Mn*Mn];   // 8 MB
static __device__ float g_qkv[Nn*3*Hn];
static __device__ float g_attn[Nn*Hn];
static __device__ float g_buf[Nn*Hn];
static __device__ float g_h[Nn*Hn];
static __device__ float g_h2[Nn*Hn];
static __device__ float g_y[Nn*Hn];
static __device__ float g_ff[Nn*FFNn];
static __device__ int   g_off[Nn+1];
static __device__ int   g_cursor[Nn];
static __device__ int   g_eord[En];     // src node per CSR slot (sorted by dst)

// ---------------- helpers ---------------------------------------------------
__device__ __forceinline__ float gelu_exact(float x) {
    return 0.5f * x * (1.0f + erff(x * 0.7071067811865475f));
}

__device__ __forceinline__ unsigned f2tf(float x) {
    unsigned r;
    asm("cvt.rna.tf32.f32 %0, %1;" : "=r"(r) : "f"(x));
    return r;
}

__device__ __forceinline__ unsigned packbf(float lo, float hi) {
    unsigned r;
    asm("cvt.rn.bf16x2.f32 %0, %1, %2;" : "=r"(r) : "f"(hi), "f"(lo));
    return r;
}

__device__ __forceinline__ void mma_tf32(float c[4], const unsigned a[4],
                                         unsigned b0, unsigned b1) {
    asm volatile(
        "mma.sync.aligned.m16n8k8.row.col.f32.tf32.tf32.f32 "
        "{%0,%1,%2,%3},{%4,%5,%6,%7},{%8,%9},{%0,%1,%2,%3};"
        : "+f"(c[0]), "+f"(c[1]), "+f"(c[2]), "+f"(c[3])
        : "r"(a[0]), "r"(a[1]), "r"(a[2]), "r"(a[3]), "r"(b0), "r"(b1));
}

__device__ __forceinline__ void mma_bf16(float c[4], const unsigned a[4],
                                         unsigned b0, unsigned b1) {
    asm volatile(
        "mma.sync.aligned.m16n8k16.row.col.f32.bf16.bf16.f32 "
        "{%0,%1,%2,%3},{%4,%5,%6,%7},{%8,%9},{%0,%1,%2,%3};"
        : "+f"(c[0]), "+f"(c[1]), "+f"(c[2]), "+f"(c[3])
        : "r"(a[0]), "r"(a[1]), "r"(a[2]), "r"(a[3]), "r"(b0), "r"(b1));
}

// ---------------- init: deg=1, adj=0 ---------------------------------------
__global__ void init_deg_adj_kernel() {
    int i = blockIdx.x * blockDim.x + threadIdx.x;
    if (i < Nn) g_deg[i] = 1;
    if (i < Gn*Mn*MWn) g_adj[i] = 0;
}

__global__ void edge_prep_kernel(const int* __restrict__ src, const int* __restrict__ dst) {
    int e = blockIdx.x * blockDim.x + threadIdx.x;
    if (e >= En) return;
    int s = src[e], d = dst[e];
    atomicAdd(&g_deg[d], 1);
    if (s != d) {
        int g  = s >> 10;
        int ls = s & 1023, ld = d & 1023;
        atomicOr(&g_adj[(g*Mn + ls)*MWn + (ld >> 5)], 1u << (ld & 31));
        atomicOr(&g_adj[(g*Mn + ld)*MWn + (ls >> 5)], 1u << (ls & 31));
    }
}

__global__ void dinv_kernel() {
    int i = blockIdx.x * blockDim.x + threadIdx.x;
    if (i < Nn) g_dinv[i] = rsqrtf((float)g_deg[i]);
}

// ---------------- CSR build: scan (1 block) + fill --------------------------
__global__ void scan_kernel() {
    __shared__ int ssum[256];
    int t = threadIdx.x;
    int base = t * 32;
    int s = 0;
#pragma unroll
    for (int j = 0; j < 32; j++) s += g_deg[base + j] - 1;
    ssum[t] = s; __syncthreads();
    int run = s;
    for (int d = 1; d < 256; d <<= 1) {
        int v = (t >= d) ? ssum[t - d] : 0;
        __syncthreads();
        ssum[t] += v;
        __syncthreads();
    }
    int off = ssum[t] - run;   // exclusive prefix of this chunk
#pragma unroll
    for (int j = 0; j < 32; j++) {
        g_off[base + j] = off;
        g_cursor[base + j] = off;
        off += g_deg[base + j] - 1;
    }
    if (t == 255) g_off[Nn] = off;
}

__global__ void fill_kernel(const int* __restrict__ src, const int* __restrict__ dst) {
    int e = blockIdx.x * blockDim.x + threadIdx.x;
    if (e >= En) return;
    int d = dst[e];
    int pos = atomicAdd(&g_cursor[d], 1);
    g_eord[pos] = src[e];
}

// ---------------- GCN gather: 1 block per dst node --------------------------
__global__ __launch_bounds__(256) void gcn_gather_kernel(const float* __restrict__ gcn_b) {
    int d = blockIdx.x;
    int t = threadIdx.x;
    float dinvd = g_dinv[d];
    float acc = g_xw[(size_t)d*Hn + t] * dinvd * dinvd + gcn_b[t];
    int beg = g_off[d], end = g_off[d+1];
    int e = beg;
    for (; e + 2 <= end; e += 2) {
        int s0 = g_eord[e], s1 = g_eord[e+1];
        float w0 = g_dinv[s0] * dinvd;
        float w1 = g_dinv[s1] * dinvd;
        float v0 = g_xw[(size_t)s0*Hn + t];
        float v1 = g_xw[(size_t)s1*Hn + t];
        acc += v0 * w0 + v1 * w1;
    }
    if (e < end) {
        int s0 = g_eord[e];
        acc += g_xw[(size_t)s0*Hn + t] * (g_dinv[s0] * dinvd);
    }
    g_xlocal[(size_t)d*Hn + t] = acc;
}

// ---------------- SPD: per-row bitset BFS (warp per row) -------------------
__global__ void bfs_kernel() {
    int row = blockIdx.x * (blockDim.x >> 5) + (threadIdx.x >> 5);
    int lane = threadIdx.x & 31;
    if (row >= Gn*Mn) return;
    int g = row >> 10, i = row & 1023;
    const unsigned* arow = g_adj + (size_t)row * MWn;
    unsigned frontier = arow[lane];
    unsigned diag = ((i >> 5) == lane) ? (1u << (i & 31)) : 0u;
    unsigned visited = frontier | diag;
    unsigned char* drow = g_dist + (size_t)row * Mn;

#pragma unroll
    for (int p = 0; p < 8; p++) {
        unsigned word = 0;
#pragma unroll
        for (int b = 0; b < 4; b++) {
            int bi = p*4 + b;
            int k = lane*32 + bi;
            unsigned char v = ((frontier >> bi) & 1u) ? 1 : ((k == i) ? 0 : 6);
            word |= ((unsigned)v) << (8*b);
        }
        *(unsigned*)(drow + lane*32 + p*4) = word;
    }

    for (int d = 2; d <= 5; d++) {
        unsigned newf = 0;
#pragma unroll 1
        for (int ws = 0; ws < 32; ws++) {
            unsigned fw = __shfl_sync(0xffffffffu, frontier, ws);
            while (fw) {
                int b = __ffs(fw) - 1; fw &= fw - 1;
                int j = ws*32 + b;
                newf |= g_adj[((size_t)g*Mn + j)*MWn + lane];
            }
        }
        newf &= ~visited;
        visited |= newf;
        unsigned t = newf;
        while (t) {
            int b = __ffs(t) - 1; t &= t - 1;
            drow[lane*32 + b] = (unsigned char)d;
        }
        frontier = newf;
        if (!__any_sync(0xffffffffu, newf != 0u)) break;
    }
}

// ---------------- bf16 split tensor-core GEMM -------------------------------
// C[M,Nc] = act(A[M,K] * B[Nc,K]^T + bias); 3-pass bf16 hi/lo (error ~2^-17).
// Tile BM x 64, K-step 32, double-buffered smem. 256 threads.
template<int BM>
__global__ __launch_bounds__(256) void gemm_bf16_kernel(
    const float* __restrict__ A, const float* __restrict__ B,
    const float* __restrict__ bias, float* __restrict__ C,
    int Nc, int K, int act)
{
    constexpr int WMW = (BM == 128) ? 4 : 2;   // warps along M
    constexpr int WNW = 8 / WMW;               // warps along N
    constexpr int WTN = 64 / WNW;              // warp tile N width
    constexpr int NT  = WTN / 8;               // n-subtiles per warp
    constexpr int A4  = BM / 32;               // float4 loads per thread (A)
    constexpr int STG = (2*BM + 2*64) * 20;    // uints per stage

    extern __shared__ unsigned sm[];

    int bm = blockIdx.y * BM, bn = blockIdx.x * 64;
    int tid = threadIdx.x;
    int warp = tid >> 5, lane = tid & 31;
    int wm = warp / WNW, wn = warp % WNW;
    int lr = lane >> 2, lc = lane & 3;

    float acc[2][NT][4];
#pragma unroll
    for (int i = 0; i < 2; i++)
#pragma unroll
        for (int j = 0; j < NT; j++)
#pragma unroll
            for (int r = 0; r < 4; r++) acc[i][j][r] = 0.0f;

    // ---- prologue: load + convert stage 0 ----
    {
        unsigned* AH = sm;
        unsigned* AL = AH + BM*20;
        unsigned* BH = AL + BM*20;
        unsigned* BL = BH + 64*20;
#pragma unroll
        for (int l = 0; l < A4; l++) {
            int e = tid + l*256;
            int row = e >> 3, c4 = (e & 7) * 4, p = (e & 7) * 2;
            float4 v = *(const float4*)(A + (size_t)(bm + row) * K + c4);
            unsigned h0 = packbf(v.x, v.y), h1 = packbf(v.z, v.w);
            float xh0 = __uint_as_float(h0 << 16), yh0 = __uint_as_float(h0 & 0xffff0000u);
            float xh1 = __uint_as_float(h1 << 16), yh1 = __uint_as_float(h1 & 0xffff0000u);
            *(uint2*)&AH[row*20 + p] = make_uint2(h0, h1);
            *(uint2*)&AL[row*20 + p] = make_uint2(packbf(v.x - xh0, v.y - yh0),
                                                  packbf(v.z - xh1, v.w - yh1));
        }
#pragma unroll
        for (int l = 0; l < 2; l++) {
            int e = tid + l*256;
            int row = e >> 3, c4 = (e & 7) * 4, p = (e & 7) * 2;
            float4 v = *(const float4*)(B + (size_t)(bn + row) * K + c4);
            unsigned h0 = packbf(v.x, v.y), h1 = packbf(v.z, v.w);
            float xh0 = __uint_as_float(h0 << 16), yh0 = __uint_as_float(h0 & 0xffff0000u);
            float xh1 = __uint_as_float(h1 << 16), yh1 = __uint_as_float(h1 & 0xffff0000u);
            *(uint2*)&BH[row*20 + p] = make_uint2(h0, h1);
            *(uint2*)&BL[row*20 + p] = make_uint2(packbf(v.x - xh0, v.y - yh0),
                                                  packbf(v.z - xh1, v.w - yh1));
        }
    }
    __syncthreads();

    int nk = K >> 5;
    for (int it = 0; it < nk; it++) {
        unsigned* AH = sm + (it & 1) * STG;
        unsigned* AL = AH + BM*20;
        unsigned* BH = AL + BM*20;
        unsigned* BL = BH + 64*20;

        // prefetch next k-slab into registers
        float4 pa[A4], pb2[2];
        bool has = (it + 1 < nk);
        if (has) {
            int k0 = (it + 1) << 5;
#pragma unroll
            for (int l = 0; l < A4; l++) {
                int e = tid + l*256;
                int row = e >> 3, c4 = (e & 7) * 4;
                pa[l] = *(const float4*)(A + (size_t)(bm + row) * K + k0 + c4);
            }
#pragma unroll
            for (int l = 0; l < 2; l++) {
                int e = tid + l*256;
                int row = e >> 3, c4 = (e & 7) * 4;
                pb2[l] = *(const float4*)(B + (size_t)(bn + row) * K + k0 + c4);
            }
        }

        // compute on current buffer: two k16 steps
#pragma unroll
        for (int ks = 0; ks < 2; ks++) {
            int pb = ks * 8;
            unsigned ah[2][4], al[2][4];
#pragma unroll
            for (int mt = 0; mt < 2; mt++) {
                int rA = wm*32 + mt*16;
                ah[mt][0] = AH[(rA+lr  )*20 + pb + lc];
                ah[mt][1] = AH[(rA+lr+8)*20 + pb + lc];
                ah[mt][2] = AH[(rA+lr  )*20 + pb + 4 + lc];
                ah[mt][3] = AH[(rA+lr+8)*20 + pb + 4 + lc];
                al[mt][0] = AL[(rA+lr  )*20 + pb + lc];
                al[mt][1] = AL[(rA+lr+8)*20 + pb + lc];
                al[mt][2] = AL[(rA+lr  )*20 + pb + 4 + lc];
                al[mt][3] = AL[(rA+lr+8)*20 + pb + 4 + lc];
            }
#pragma unroll
            for (int nt = 0; nt < NT; nt++) {
                int cB = wn*WTN + nt*8;
                unsigned bh0 = BH[(cB+lr)*20 + pb + lc];
                unsigned bh1 = BH[(cB+lr)*20 + pb + 4 + lc];
                unsigned bl0 = BL[(cB+lr)*20 + pb + lc];
                unsigned bl1 = BL[(cB+lr)*20 + pb + 4 + lc];
#pragma unroll
                for (int mt = 0; mt < 2; mt++) {
                    mma_bf16(acc[mt][nt], ah[mt], bh0, bh1);
                    mma_bf16(acc[mt][nt], al[mt], bh0, bh1);
                    mma_bf16(acc[mt][nt], ah[mt], bl0, bl1);
                }
            }
        }

        // convert + store next buffer
        if (has) {
            unsigned* nAH = sm + ((it + 1) & 1) * STG;
            unsigned* nAL = nAH + BM*20;
            unsigned* nBH = nAL + BM*20;
            unsigned* nBL = nBH + 64*20;
#pragma unroll
            for (int l = 0; l < A4; l++) {
                int e = tid + l*256;
                int row = e >> 3, p = (e & 7) * 2;
                float4 v = pa[l];
                unsigned h0 = packbf(v.x, v.y), h1 = packbf(v.z, v.w);
                float xh0 = __uint_as_float(h0 << 16), yh0 = __uint_as_float(h0 & 0xffff0000u);
                float xh1 = __uint_as_float(h1 << 16), yh1 = __uint_as_float(h1 & 0xffff0000u);
                *(uint2*)&nAH[row*20 + p] = make_uint2(h0, h1);
                *(uint2*)&nAL[row*20 + p] = make_uint2(packbf(v.x - xh0, v.y - yh0),
                                                       packbf(v.z - xh1, v.w - yh1));
            }
#pragma unroll
            for (int l = 0; l < 2; l++) {
                int e = tid + l*256;
                int row = e >> 3, p = (e & 7) * 2;
                float4 v = pb2[l];
                unsigned h0 = packbf(v.x, v.y), h1 = packbf(v.z, v.w);
                float xh0 = __uint_as_float(h0 << 16), yh0 = __uint_as_float(h0 & 0xffff0000u);
                float xh1 = __uint_as_float(h1 << 16), yh1 = __uint_as_float(h1 & 0xffff0000u);
                *(uint2*)&nBH[row*20 + p] = make_uint2(h0, h1);
                *(uint2*)&nBL[row*20 + p] = make_uint2(packbf(v.x - xh0, v.y - yh0),
                                                       packbf(v.z - xh1, v.w - yh1));
            }
        }
        __syncthreads();
    }

    // ---- epilogue ----
#pragma unroll
    for (int mt = 0; mt < 2; mt++) {
#pragma unroll
        for (int nt = 0; nt < NT; nt++) {
            int m = bm + wm*32 + mt*16 + lr;
            int n = bn + wn*WTN + nt*8 + lc*2;
            float b0 = 0.0f, b1 = 0.0f;
            if (bias) { b0 = bias[n]; b1 = bias[n+1]; }
            float v0 = acc[mt][nt][0] + b0;
            float v1 = acc[mt][nt][1] + b1;
            float v2 = acc[mt][nt][2] + b0;
            float v3 = acc[mt][nt][3] + b1;
            if (act) { v0 = gelu_exact(v0); v1 = gelu_exact(v1);
                       v2 = gelu_exact(v2); v3 = gelu_exact(v3); }
            *(float2*)(C + (size_t)m * Nc + n) = make_float2(v0, v1);
            *(float2*)(C + (size_t)(m+8) * Nc + n) = make_float2(v2, v3);
        }
    }
}

// ---------------- fused attention: tf32 mma + online softmax ---------------
// block = 256 threads (8 warps), q-tile 128, k-tile 64.
__global__ __launch_bounds__(256) void attn_tc_kernel(const float* __restrict__ bias_emb) {
    extern __shared__ unsigned smem_u[];
    unsigned (*Qs)[36] = (unsigned(*)[36])smem_u;               // 128x36
    unsigned (*Ks)[36] = (unsigned(*)[36])(smem_u + 4608);      // 64x36
    unsigned (*Vs)[36] = (unsigned(*)[36])(smem_u + 6912);      // 64x36
    float (*Ss)[68]    = (float(*)[68])(smem_u + 9216);         // 128x68
    float* m_s  = (float*)(smem_u + 9216 + 8704);
    float* l_s  = m_s + 128;
    float* f_s  = m_s + 256;
    float* btab = m_s + 384;

    int g = blockIdx.z, head = blockIdx.y, q0 = blockIdx.x * 128;
    int tid = threadIdx.x;
    int warp = tid >> 5, lane = tid & 31;
    int lr = lane >> 2, lc = lane & 3;
    const float scale = 0.17677669529663687f;   // 32^-0.5

    if (tid < 7) btab[tid] = bias_emb[tid];
    if (tid < 128) { m_s[tid] = -1e30f; l_s[tid] = 0.0f; }

#pragma unroll
    for (int l = 0; l < 16; l++) {
        int e = tid + l*256;
        int row = e >> 5, col = e & 31;
        float v = g_qkv[(size_t)(g*Mn + q0 + row)*768 + head*32 + col] * scale;
        Qs[row][col] = f2tf(v);
    }

    float acc[4][4];
#pragma unroll
    for (int i = 0; i < 4; i++)
#pragma unroll
        for (int j = 0; j < 4; j++) acc[i][j] = 0.0f;

    int qb = warp * 16;

    for (int tk = 0; tk < 16; tk++) {
        __syncthreads();
#pragma unroll
        for (int l = 0; l < 8; l++) {
            int e = tid + l*256;
            int row = e >> 5, col = e & 31;
            size_t base = (size_t)(g*Mn + tk*64 + row)*768 + head*32 + col;
            Ks[row][col] = f2tf(g_qkv[base + 256]);
            Vs[row][col] = f2tf(g_qkv[base + 512]);
        }
        __syncthreads();

        // scores
        {
            float sc[8][4];
#pragma unroll
            for (int nt = 0; nt < 8; nt++)
#pragma unroll
                for (int r = 0; r < 4; r++) sc[nt][r] = 0.0f;
#pragma unroll
            for (int kk = 0; kk < 32; kk += 8) {
                unsigned a[4];
                a[0] = Qs[qb+lr  ][kk+lc  ];
                a[1] = Qs[qb+lr+8][kk+lc  ];
                a[2] = Qs[qb+lr  ][kk+lc+4];
                a[3] = Qs[qb+lr+8][kk+lc+4];
#pragma unroll
                for (int nt = 0; nt < 8; nt++) {
                    unsigned b0 = Ks[nt*8+lr][kk+lc];
                    unsigned b1 = Ks[nt*8+lr][kk+lc+4];
                    mma_tf32(sc[nt], a, b0, b1);
                }
            }
#pragma unroll
            for (int nt = 0; nt < 8; nt++) {
                Ss[qb+lr  ][nt*8 + lc*2    ] = sc[nt][0];
                Ss[qb+lr  ][nt*8 + lc*2 + 1] = sc[nt][1];
                Ss[qb+lr+8][nt*8 + lc*2    ] = sc[nt][2];
                Ss[qb+lr+8][nt*8 + lc*2 + 1] = sc[nt][3];
            }
        }
        __syncthreads();

        // online softmax: 2 threads per row
        {
            int q = tid >> 1, sub = tid & 1;
            const uchar4* dp = (const uchar4*)(g_dist +
                (size_t)(g*Mn + q0 + q)*Mn + tk*64 + sub*32);
            float* srow = &Ss[q][sub*32];
            float rm = -1e30f;
#pragma unroll
            for (int j4 = 0; j4 < 8; j4++) {
                uchar4 dv = dp[j4];
                float s0 = srow[j4*4+0] + btab[dv.x];
                float s1 = srow[j4*4+1] + btab[dv.y];
                float s2 = srow[j4*4+2] + btab[dv.z];
                float s3 = srow[j4*4+3] + btab[dv.w];
                srow[j4*4+0] = s0; srow[j4*4+1] = s1;
                srow[j4*4+2] = s2; srow[j4*4+3] = s3;
                rm = fmaxf(rm, fmaxf(fmaxf(s0, s1), fmaxf(s2, s3)));
            }
            rm = fmaxf(rm, __shfl_xor_sync(0xffffffffu, rm, 1));
            rm = fmaxf(rm, m_s[q]);
            float rs = 0.0f;
#pragma unroll
            for (int j = 0; j < 32; j++) {
                float p = __expf(srow[j] - rm);
                rs += p;
                srow[j] = __uint_as_float(f2tf(p));
            }
            rs += __shfl_xor_sync(0xffffffffu, rs, 1);
            if (sub == 0) {
                float f = __expf(m_s[q] - rm);
                f_s[q] = f;
                l_s[q] = l_s[q]*f + rs;
                m_s[q] = rm;
            }
        }
        __syncthreads();

        // PV
        {
            float f0 = f_s[qb+lr], f1 = f_s[qb+lr+8];
#pragma unroll
            for (int nt = 0; nt < 4; nt++) {
                acc[nt][0] *= f0; acc[nt][1] *= f0;
                acc[nt][2] *= f1; acc[nt][3] *= f1;
            }
#pragma unroll
            for (int kk = 0; kk < 64; kk += 8) {
                unsigned a[4];
                a[0] = __float_as_uint(Ss[qb+lr  ][kk+lc  ]);
                a[1] = __float_as_uint(Ss[qb+lr+8][kk+lc  ]);
                a[2] = __float_as_uint(Ss[qb+lr  ][kk+lc+4]);
                a[3] = __float_as_uint(Ss[qb+lr+8][kk+lc+4]);
#pragma unroll
                for (int nt = 0; nt < 4; nt++) {
                    unsigned b0 = Vs[kk+lc  ][nt*8+lr];
                    unsigned b1 = Vs[kk+lc+4][nt*8+lr];
                    mma_tf32(acc[nt], a, b0, b1);
                }
            }
        }
    }

    float l0 = 1.0f / l_s[qb+lr];
    float l1 = 1.0f / l_s[qb+lr+8];
#pragma unroll
    for (int nt = 0; nt < 4; nt++) {
        int d = head*32 + nt*8 + lc*2;
        *(float2*)(g_attn + (size_t)(g*Mn + q0 + qb + lr  )*Hn + d) =
            make_float2(acc[nt][0]*l0, acc[nt][1]*l0);
        *(float2*)(g_attn + (size_t)(g*Mn + q0 + qb + lr+8)*Hn + d) =
            make_float2(acc[nt][2]*l1, acc[nt][3]*l1);
    }
}

// ---------------- LayerNorm: out = LN(a [+ b] [+ c]) * gamma + beta --------
__global__ __launch_bounds__(256) void ln_kernel(
    const float* __restrict__ a, const float* __restrict__ b, const float* __restrict__ c,
    const float* __restrict__ gam, const float* __restrict__ bet, float* __restrict__ out)
{
    __shared__ float red[256];
    int row = blockIdx.x, t = threadIdx.x;
    size_t off = (size_t)row * Hn + t;
    float v = a[off];
    if (b) v += b[off];
    if (c) v += c[off];
    red[t] = v; __syncthreads();
    for (int s = 128; s > 0; s >>= 1) { if (t < s) red[t] += red[t+s]; __syncthreads(); }
    float mean = red[0] * (1.0f / Hn);
    __syncthreads();
    float dv = v - mean;
    red[t] = dv * dv; __syncthreads();
    for (int s = 128; s > 0; s >>= 1) { if (t < s) red[t] += red[t+s]; __syncthreads(); }
    float var = red[0] * (1.0f / Hn);
    out[off] = dv * rsqrtf(var + 1e-5f) * gam[t] + bet[t];
}

// ---------------- host launch ----------------------------------------------
static float* sym_addr(const void* s) {
    void* p = nullptr;
    cudaGetSymbolAddress(&p, s);
    return (float*)p;
}

extern "C" void kernel_launch(void* const* d_in, const int* in_sizes, int n_in,
                              void* d_out, int out_size) {
    const float* x      = (const float*)d_in[0];
    const float* gcn_w  = (const float*)d_in[1];
    const float* gcn_b  = (const float*)d_in[2];
    const float* qkv_w  = (const float*)d_in[3];
    const float* qkv_b  = (const float*)d_in[4];
    const float* proj_w = (const float*)d_in[5];
    const float* proj_b = (const float*)d_in[6];
    const float* ln1_g  = (const float*)d_in[7];
    const float* ln1_b  = (const float*)d_in[8];
    const float* ln2_g  = (const float*)d_in[9];
    const float* ln2_b  = (const float*)d_in[10];
    const float* ffn1_w = (const float*)d_in[11];
    const float* ffn1_b = (const float*)d_in[12];
    const float* ffn2_w = (const float*)d_in[13];
    const float* ffn2_b = (const float*)d_in[14];
    const float* bias_e = (const float*)d_in[15];
    const float* oln1_g = (const float*)d_in[16];
    const float* oln1_b = (const float*)d_in[17];
    const float* oln2_g = (const float*)d_in[18];
    const float* oln2_b = (const float*)d_in[19];
    const float* offn1_w= (const float*)d_in[20];
    const float* offn1_b= (const float*)d_in[21];
    const float* offn2_w= (const float*)d_in[22];
    const float* offn2_b= (const float*)d_in[23];
    const int*   eidx   = (const int*)d_in[24];
    const int* src = eidx;
    const int* dst = eidx + En;
    float* out = (float*)d_out;

    float* p_xw  = sym_addr(g_xw);
    float* p_xl  = sym_addr(g_xlocal);
    float* p_qkv = sym_addr(g_qkv);
    float* p_att = sym_addr(g_attn);
    float* p_buf = sym_addr(g_buf);
    float* p_h   = sym_addr(g_h);
    float* p_h2  = sym_addr(g_h2);
    float* p_y   = sym_addr(g_y);
    float* p_ff  = sym_addr(g_ff);

    const int SM128 = (2*128 + 2*64) * 20 * 4 * 2;  // 61440
    const int SM64  = (2*64  + 2*64) * 20 * 4 * 2;  // 40960
    const int ATTN_SMEM = 18312 * 4;                // 73248
    cudaFuncSetAttribute(gemm_bf16_kernel<128>, cudaFuncAttributeMaxDynamicSharedMemorySize, SM128);
    cudaFuncSetAttribute(gemm_bf16_kernel<64>,  cudaFuncAttributeMaxDynamicSharedMemorySize, SM64);
    cudaFuncSetAttribute(attn_tc_kernel, cudaFuncAttributeMaxDynamicSharedMemorySize, ATTN_SMEM);

    // graph prep
    init_deg_adj_kernel<<<1024, 256>>>();
    edge_prep_kernel<<<En/256, 256>>>(src, dst);
    dinv_kernel<<<Nn/256, 256>>>();
    scan_kernel<<<1, 256>>>();
    fill_kernel<<<En/256, 256>>>(src, dst);
    gemm_bf16_kernel<64><<<dim3(Hn/64, Nn/64), 256, SM64>>>(x, gcn_w, nullptr, p_xw, Hn, Hn, 0);
    gcn_gather_kernel<<<Nn, 256>>>(gcn_b);
    bfs_kernel<<<(Gn*Mn)/4, 128>>>();

    // transformer
    gemm_bf16_kernel<128><<<dim3(768/64, Nn/128), 256, SM128>>>(x, qkv_w, qkv_b, p_qkv, 768, Hn, 0);
    attn_tc_kernel<<<dim3(Mn/128, HEADSn, Gn), 256, ATTN_SMEM>>>(bias_e);
    gemm_bf16_kernel<64><<<dim3(Hn/64, Nn/64), 256, SM64>>>(p_att, proj_w, proj_b, p_buf, Hn, Hn, 0);
    ln_kernel<<<Nn, 256>>>(x, p_buf, nullptr, ln1_g, ln1_b, p_h);
    gemm_bf16_kernel<128><<<dim3(FFNn/64, Nn/128), 256, SM128>>>(p_h, ffn1_w, ffn1_b, p_ff, FFNn, Hn, 1);
    gemm_bf16_kernel<64><<<dim3(Hn/64, Nn/64), 256, SM64>>>(p_ff, ffn2_w, ffn2_b, p_buf, Hn, FFNn, 0);
    ln_kernel<<<Nn, 256>>>(p_h, p_buf, nullptr, ln2_g, ln2_b, p_h2);

    // GPS combine + outer FFN
    ln_kernel<<<Nn, 256>>>(x, p_xl, p_h2, oln1_g, oln1_b, p_y);
    gemm_bf16_kernel<128><<<dim3(FFNn/64, Nn/128), 256, SM128>>>(p_y, offn1_w, offn1_b, p_ff, FFNn, Hn, 1);
    gemm_bf16_kernel<64><<<dim3(Hn/64, Nn/64), 256, SM64>>>(p_ff, offn2_w, offn2_b, p_buf, Hn, FFNn, 0);
    ln_kernel<<<Nn, 256>>>(p_y, p_buf, nullptr, oln2_g, oln2_b, out);
}

// round 4
// speedup vs baseline: 2.1746x; 1.0417x over previous
#include <cuda_runtime.h>
#include <math.h>

#define Gn 8
#define Mn 1024
#define Hn 256
#define HEADSn 8
#define HDn 32
#define FFNn 1024
#define Nn (Gn*Mn)          // 8192
#define En 131072
#define MWn (Mn/32)         // 32

// ---------------- scratch (device globals: no allocation allowed) ----------
static __device__ float g_xw[Nn*Hn];
static __device__ float g_xlocal[Nn*Hn];
static __device__ float g_dinv[Nn];
static __device__ int   g_deg[Nn];
static __device__ unsigned g_adj[Gn*Mn*MWn];
static __device__ unsigned char g_dist[(size_t)Gn*Mn*Mn];   // 8 MB
static __device__ float g_qkv[Nn*3*Hn];
static __device__ float g_attn[Nn*Hn];
static __device__ float g_buf[Nn*Hn];
static __device__ float g_h[Nn*Hn];
static __device__ float g_h2[Nn*Hn];
static __device__ float g_y[Nn*Hn];
static __device__ float g_ff[Nn*FFNn];
static __device__ int   g_off[Nn+1];
static __device__ int   g_cursor[Nn];
static __device__ int   g_eord[En];     // src node per CSR slot (sorted by dst)

// ---------------- helpers ---------------------------------------------------
__device__ __forceinline__ float gelu_exact(float x) {
    return 0.5f * x * (1.0f + erff(x * 0.7071067811865475f));
}

__device__ __forceinline__ unsigned f2tf(float x) {
    unsigned r;
    asm("cvt.rna.tf32.f32 %0, %1;" : "=r"(r) : "f"(x));
    return r;
}

__device__ __forceinline__ unsigned packbf(float lo, float hi) {
    unsigned r;
    asm("cvt.rn.bf16x2.f32 %0, %1, %2;" : "=r"(r) : "f"(hi), "f"(lo));
    return r;
}

__device__ __forceinline__ void mma_tf32(float c[4], const unsigned a[4],
                                         unsigned b0, unsigned b1) {
    asm volatile(
        "mma.sync.aligned.m16n8k8.row.col.f32.tf32.tf32.f32 "
        "{%0,%1,%2,%3},{%4,%5,%6,%7},{%8,%9},{%0,%1,%2,%3};"
        : "+f"(c[0]), "+f"(c[1]), "+f"(c[2]), "+f"(c[3])
        : "r"(a[0]), "r"(a[1]), "r"(a[2]), "r"(a[3]), "r"(b0), "r"(b1));
}

__device__ __forceinline__ void mma_bf16(float c[4], const unsigned a[4],
                                         unsigned b0, unsigned b1) {
    asm volatile(
        "mma.sync.aligned.m16n8k16.row.col.f32.bf16.bf16.f32 "
        "{%0,%1,%2,%3},{%4,%5,%6,%7},{%8,%9},{%0,%1,%2,%3};"
        : "+f"(c[0]), "+f"(c[1]), "+f"(c[2]), "+f"(c[3])
        : "r"(a[0]), "r"(a[1]), "r"(a[2]), "r"(a[3]), "r"(b0), "r"(b1));
}

// ---------------- init: deg=1, adj=0 ---------------------------------------
__global__ void init_deg_adj_kernel() {
    int i = blockIdx.x * blockDim.x + threadIdx.x;
    if (i < Nn) g_deg[i] = 1;
    if (i < Gn*Mn*MWn) g_adj[i] = 0;
}

__global__ void edge_prep_kernel(const int* __restrict__ src, const int* __restrict__ dst) {
    int e = blockIdx.x * blockDim.x + threadIdx.x;
    if (e >= En) return;
    int s = src[e], d = dst[e];
    atomicAdd(&g_deg[d], 1);
    if (s != d) {
        int g  = s >> 10;
        int ls = s & 1023, ld = d & 1023;
        atomicOr(&g_adj[(g*Mn + ls)*MWn + (ld >> 5)], 1u << (ld & 31));
        atomicOr(&g_adj[(g*Mn + ld)*MWn + (ls >> 5)], 1u << (ls & 31));
    }
}

// ---------------- scan: offsets + cursor + dinv (1 block, 1024 thr) --------
__global__ __launch_bounds__(1024) void scan_kernel() {
    __shared__ int wsum[32];
    int t = threadIdx.x, lane = t & 31, w = t >> 5;
    int base = t * 8;
    int loc[8]; int s = 0;
#pragma unroll
    for (int j = 0; j < 8; j++) {
        int dg = g_deg[base + j];
        g_dinv[base + j] = rsqrtf((float)dg);
        loc[j] = dg - 1; s += loc[j];
    }
    int inc = s;
#pragma unroll
    for (int d = 1; d < 32; d <<= 1) {
        int v = __shfl_up_sync(0xffffffffu, inc, d);
        if (lane >= d) inc += v;
    }
    if (lane == 31) wsum[w] = inc;
    __syncthreads();
    if (w == 0) {
        int v = wsum[lane];
#pragma unroll
        for (int d = 1; d < 32; d <<= 1) {
            int u = __shfl_up_sync(0xffffffffu, v, d);
            if (lane >= d) v += u;
        }
        wsum[lane] = v;
    }
    __syncthreads();
    int excl = inc - s + (w ? wsum[w-1] : 0);
#pragma unroll
    for (int j = 0; j < 8; j++) {
        g_off[base + j] = excl;
        g_cursor[base + j] = excl;
        excl += loc[j];
    }
    if (t == 1023) g_off[Nn] = excl;
}

// ---------------- body: CSR fill --------------------------------------------
__device__ __forceinline__ void fill_body(int e, const int* __restrict__ src,
                                          const int* __restrict__ dst) {
    if (e >= En) return;
    int d = dst[e];
    int pos = atomicAdd(&g_cursor[d], 1);
    g_eord[pos] = src[e];
}

// ---------------- body: GCN gather (1 block per dst node) -------------------
__device__ __forceinline__ void gather_body(int d, int t, const float* __restrict__ gcn_b) {
    float dinvd = g_dinv[d];
    float acc = g_xw[(size_t)d*Hn + t] * dinvd * dinvd + gcn_b[t];
    int beg = g_off[d], end = g_off[d+1];
    int e = beg;
    for (; e + 2 <= end; e += 2) {
        int s0 = g_eord[e], s1 = g_eord[e+1];
        float w0 = g_dinv[s0] * dinvd;
        float w1 = g_dinv[s1] * dinvd;
        float v0 = g_xw[(size_t)s0*Hn + t];
        float v1 = g_xw[(size_t)s1*Hn + t];
        acc += v0 * w0 + v1 * w1;
    }
    if (e < end) {
        int s0 = g_eord[e];
        acc += g_xw[(size_t)s0*Hn + t] * (g_dinv[s0] * dinvd);
    }
    g_xlocal[(size_t)d*Hn + t] = acc;
}

// ---------------- body: SPD bitset BFS, direction-optimal (warp per row) ---
__device__ __forceinline__ int warp_sum(int v) {
#pragma unroll
    for (int d = 16; d; d >>= 1) v += __shfl_xor_sync(0xffffffffu, v, d);
    return v;
}

__device__ __forceinline__ void bfs_body(int row, int lane) {
    int g = row >> 10, i = row & 1023;
    const unsigned* arow = g_adj + (size_t)row * MWn;
    unsigned frontier = arow[lane];
    unsigned diag = ((i >> 5) == lane) ? (1u << (i & 31)) : 0u;
    unsigned visited = frontier | diag;
    unsigned char* drow = g_dist + (size_t)row * Mn;

    // dist row init: 1 where adj, 0 on diag, 6 elsewhere; packed 4B stores
#pragma unroll
    for (int p = 0; p < 8; p++) {
        unsigned word = 0;
#pragma unroll
        for (int b = 0; b < 4; b++) {
            int bi = p*4 + b;
            int k = lane*32 + bi;
            unsigned char v = ((frontier >> bi) & 1u) ? 1 : ((k == i) ? 0 : 6);
            word |= ((unsigned)v) << (8*b);
        }
        *(unsigned*)(drow + lane*32 + p*4) = word;
    }

    for (int d = 2; d <= 5; d++) {
        int cf = warp_sum(__popc(frontier));
        if (cf == 0) break;
        int cu = 1024 - warp_sum(__popc(visited));
        if (cu == 0) break;
        unsigned newf = 0;
        if (cf <= cu) {
            // forward: expand frontier rows
#pragma unroll 1
            for (int ws = 0; ws < 32; ws++) {
                unsigned fw = __shfl_sync(0xffffffffu, frontier, ws);
                while (fw) {
                    int b = __ffs(fw) - 1; fw &= fw - 1;
                    int j = ws*32 + b;
                    newf |= g_adj[((size_t)g*Mn + j)*MWn + lane];
                }
            }
            newf &= ~visited;
        } else {
            // reverse: probe unvisited rows against frontier
            unsigned unv = ~visited;
#pragma unroll 1
            for (int ws = 0; ws < 32; ws++) {
                unsigned uw = __shfl_sync(0xffffffffu, unv, ws);
                while (uw) {
                    int b = __ffs(uw) - 1; uw &= uw - 1;
                    int j = ws*32 + b;
                    unsigned aw = g_adj[((size_t)g*Mn + j)*MWn + lane];
                    unsigned m = __ballot_sync(0xffffffffu, (aw & frontier) != 0u);
                    if (m && lane == ws) newf |= 1u << b;
                }
            }
        }
        visited |= newf;
        unsigned t = newf;
        while (t) {
            int b = __ffs(t) - 1; t &= t - 1;
            drow[lane*32 + b] = (unsigned char)d;
        }
        frontier = newf;
    }
}

// ---------------- body: bf16 split tensor-core GEMM -------------------------
// C[M,Nc] = act(A[M,K] * B[Nc,K]^T + bias); 3-pass bf16 hi/lo.
// Tile BM x 64, K-step 32, double-buffered smem. 256 threads.
template<int BM>
__device__ __forceinline__ void gemm_body(
    const float* __restrict__ A, const float* __restrict__ B,
    const float* __restrict__ bias, float* __restrict__ C,
    int Nc, int K, int act, int bx, int by, unsigned* sm)
{
    constexpr int WMW = (BM == 128) ? 4 : 2;
    constexpr int WNW = 8 / WMW;
    constexpr int WTN = 64 / WNW;
    constexpr int NT  = WTN / 8;
    constexpr int A4  = BM / 32;
    constexpr int STG = (2*BM + 2*64) * 20;

    int bm = by * BM, bn = bx * 64;
    int tid = threadIdx.x;
    int warp = tid >> 5, lane = tid & 31;
    int wm = warp / WNW, wn = warp % WNW;
    int lr = lane >> 2, lc = lane & 3;

    float acc[2][NT][4];
#pragma unroll
    for (int i = 0; i < 2; i++)
#pragma unroll
        for (int j = 0; j < NT; j++)
#pragma unroll
            for (int r = 0; r < 4; r++) acc[i][j][r] = 0.0f;

    {
        unsigned* AH = sm;
        unsigned* AL = AH + BM*20;
        unsigned* BH = AL + BM*20;
        unsigned* BL = BH + 64*20;
#pragma unroll
        for (int l = 0; l < A4; l++) {
            int e = tid + l*256;
            int row = e >> 3, c4 = (e & 7) * 4, p = (e & 7) * 2;
            float4 v = *(const float4*)(A + (size_t)(bm + row) * K + c4);
            unsigned h0 = packbf(v.x, v.y), h1 = packbf(v.z, v.w);
            float xh0 = __uint_as_float(h0 << 16), yh0 = __uint_as_float(h0 & 0xffff0000u);
            float xh1 = __uint_as_float(h1 << 16), yh1 = __uint_as_float(h1 & 0xffff0000u);
            *(uint2*)&AH[row*20 + p] = make_uint2(h0, h1);
            *(uint2*)&AL[row*20 + p] = make_uint2(packbf(v.x - xh0, v.y - yh0),
                                                  packbf(v.z - xh1, v.w - yh1));
        }
#pragma unroll
        for (int l = 0; l < 2; l++) {
            int e = tid + l*256;
            int row = e >> 3, c4 = (e & 7) * 4, p = (e & 7) * 2;
            float4 v = *(const float4*)(B + (size_t)(bn + row) * K + c4);
            unsigned h0 = packbf(v.x, v.y), h1 = packbf(v.z, v.w);
            float xh0 = __uint_as_float(h0 << 16), yh0 = __uint_as_float(h0 & 0xffff0000u);
            float xh1 = __uint_as_float(h1 << 16), yh1 = __uint_as_float(h1 & 0xffff0000u);
            *(uint2*)&BH[row*20 + p] = make_uint2(h0, h1);
            *(uint2*)&BL[row*20 + p] = make_uint2(packbf(v.x - xh0, v.y - yh0),
                                                  packbf(v.z - xh1, v.w - yh1));
        }
    }
    __syncthreads();

    int nk = K >> 5;
    for (int it = 0; it < nk; it++) {
        unsigned* AH = sm + (it & 1) * STG;
        unsigned* AL = AH + BM*20;
        unsigned* BH = AL + BM*20;
        unsigned* BL = BH + 64*20;

        float4 pa[A4], pb2[2];
        bool has = (it + 1 < nk);
        if (has) {
            int k0 = (it + 1) << 5;
#pragma unroll
            for (int l = 0; l < A4; l++) {
                int e = tid + l*256;
                int row = e >> 3, c4 = (e & 7) * 4;
                pa[l] = *(const float4*)(A + (size_t)(bm + row) * K + k0 + c4);
            }
#pragma unroll
            for (int l = 0; l < 2; l++) {
                int e = tid + l*256;
                int row = e >> 3, c4 = (e & 7) * 4;
                pb2[l] = *(const float4*)(B + (size_t)(bn + row) * K + k0 + c4);
            }
        }

#pragma unroll
        for (int ks = 0; ks < 2; ks++) {
            int pb = ks * 8;
            unsigned ah[2][4], al[2][4];
#pragma unroll
            for (int mt = 0; mt < 2; mt++) {
                int rA = wm*32 + mt*16;
                ah[mt][0] = AH[(rA+lr  )*20 + pb + lc];
                ah[mt][1] = AH[(rA+lr+8)*20 + pb + lc];
                ah[mt][2] = AH[(rA+lr  )*20 + pb + 4 + lc];
                ah[mt][3] = AH[(rA+lr+8)*20 + pb + 4 + lc];
                al[mt][0] = AL[(rA+lr  )*20 + pb + lc];
                al[mt][1] = AL[(rA+lr+8)*20 + pb + lc];
                al[mt][2] = AL[(rA+lr  )*20 + pb + 4 + lc];
                al[mt][3] = AL[(rA+lr+8)*20 + pb + 4 + lc];
            }
#pragma unroll
            for (int nt = 0; nt < NT; nt++) {
                int cB = wn*WTN + nt*8;
                unsigned bh0 = BH[(cB+lr)*20 + pb + lc];
                unsigned bh1 = BH[(cB+lr)*20 + pb + 4 + lc];
                unsigned bl0 = BL[(cB+lr)*20 + pb + lc];
                unsigned bl1 = BL[(cB+lr)*20 + pb + 4 + lc];
#pragma unroll
                for (int mt = 0; mt < 2; mt++) {
                    mma_bf16(acc[mt][nt], ah[mt], bh0, bh1);
                    mma_bf16(acc[mt][nt], al[mt], bh0, bh1);
                    mma_bf16(acc[mt][nt], ah[mt], bl0, bl1);
                }
            }
        }

        if (has) {
            unsigned* nAH = sm + ((it + 1) & 1) * STG;
            unsigned* nAL = nAH + BM*20;
            unsigned* nBH = nAL + BM*20;
            unsigned* nBL = nBH + 64*20;
#pragma unroll
            for (int l = 0; l < A4; l++) {
                int e = tid + l*256;
                int row = e >> 3, p = (e & 7) * 2;
                float4 v = pa[l];
                unsigned h0 = packbf(v.x, v.y), h1 = packbf(v.z, v.w);
                float xh0 = __uint_as_float(h0 << 16), yh0 = __uint_as_float(h0 & 0xffff0000u);
                float xh1 = __uint_as_float(h1 << 16), yh1 = __uint_as_float(h1 & 0xffff0000u);
                *(uint2*)&nAH[row*20 + p] = make_uint2(h0, h1);
                *(uint2*)&nAL[row*20 + p] = make_uint2(packbf(v.x - xh0, v.y - yh0),
                                                       packbf(v.z - xh1, v.w - yh1));
            }
#pragma unroll
            for (int l = 0; l < 2; l++) {
                int e = tid + l*256;
                int row = e >> 3, p = (e & 7) * 2;
                float4 v = pb2[l];
                unsigned h0 = packbf(v.x, v.y), h1 = packbf(v.z, v.w);
                float xh0 = __uint_as_float(h0 << 16), yh0 = __uint_as_float(h0 & 0xffff0000u);
                float xh1 = __uint_as_float(h1 << 16), yh1 = __uint_as_float(h1 & 0xffff0000u);
                *(uint2*)&nBH[row*20 + p] = make_uint2(h0, h1);
                *(uint2*)&nBL[row*20 + p] = make_uint2(packbf(v.x - xh0, v.y - yh0),
                                                       packbf(v.z - xh1, v.w - yh1));
            }
        }
        __syncthreads();
    }

#pragma unroll
    for (int mt = 0; mt < 2; mt++) {
#pragma unroll
        for (int nt = 0; nt < NT; nt++) {
            int m = bm + wm*32 + mt*16 + lr;
            int n = bn + wn*WTN + nt*8 + lc*2;
            float b0 = 0.0f, b1 = 0.0f;
            if (bias) { b0 = bias[n]; b1 = bias[n+1]; }
            float v0 = acc[mt][nt][0] + b0;
            float v1 = acc[mt][nt][1] + b1;
            float v2 = acc[mt][nt][2] + b0;
            float v3 = acc[mt][nt][3] + b1;
            if (act) { v0 = gelu_exact(v0); v1 = gelu_exact(v1);
                       v2 = gelu_exact(v2); v3 = gelu_exact(v3); }
            *(float2*)(C + (size_t)m * Nc + n) = make_float2(v0, v1);
            *(float2*)(C + (size_t)(m+8) * Nc + n) = make_float2(v2, v3);
        }
    }
}

template<int BM>
__global__ __launch_bounds__(256) void gemm_bf16_kernel(
    const float* __restrict__ A, const float* __restrict__ B,
    const float* __restrict__ bias, float* __restrict__ C,
    int Nc, int K, int act)
{
    extern __shared__ unsigned sm[];
    gemm_body<BM>(A, B, bias, C, Nc, K, act, blockIdx.x, blockIdx.y, sm);
}

// ---------------- body: fused attention (tf32 mma + online softmax) --------
__device__ __forceinline__ void attn_body(const float* __restrict__ bias_emb,
                                          int g, int head, int q0, unsigned* smem_u) {
    unsigned (*Qs)[36] = (unsigned(*)[36])smem_u;               // 128x36
    unsigned (*Ks)[36] = (unsigned(*)[36])(smem_u + 4608);      // 64x36
    unsigned (*Vs)[36] = (unsigned(*)[36])(smem_u + 6912);      // 64x36
    float (*Ss)[68]    = (float(*)[68])(smem_u + 9216);         // 128x68
    float* m_s  = (float*)(smem_u + 9216 + 8704);
    float* l_s  = m_s + 128;
    float* f_s  = m_s + 256;
    float* btab = m_s + 384;

    int tid = threadIdx.x;
    int warp = tid >> 5, lane = tid & 31;
    int lr = lane >> 2, lc = lane & 3;
    const float scale = 0.17677669529663687f;   // 32^-0.5

    if (tid < 7) btab[tid] = bias_emb[tid];
    if (tid < 128) { m_s[tid] = -1e30f; l_s[tid] = 0.0f; }

#pragma unroll
    for (int l = 0; l < 16; l++) {
        int e = tid + l*256;
        int row = e >> 5, col = e & 31;
        float v = g_qkv[(size_t)(g*Mn + q0 + row)*768 + head*32 + col] * scale;
        Qs[row][col] = f2tf(v);
    }

    float acc[4][4];
#pragma unroll
    for (int i = 0; i < 4; i++)
#pragma unroll
        for (int j = 0; j < 4; j++) acc[i][j] = 0.0f;

    int qb = warp * 16;

    for (int tk = 0; tk < 16; tk++) {
        __syncthreads();
#pragma unroll
        for (int l = 0; l < 8; l++) {
            int e = tid + l*256;
            int row = e >> 5, col = e & 31;
            size_t base = (size_t)(g*Mn + tk*64 + row)*768 + head*32 + col;
            Ks[row][col] = f2tf(g_qkv[base + 256]);
            Vs[row][col] = f2tf(g_qkv[base + 512]);
        }
        __syncthreads();

        // scores
        {
            float sc[8][4];
#pragma unroll
            for (int nt = 0; nt < 8; nt++)
#pragma unroll
                for (int r = 0; r < 4; r++) sc[nt][r] = 0.0f;
#pragma unroll
            for (int kk = 0; kk < 32; kk += 8) {
                unsigned a[4];
                a[0] = Qs[qb+lr  ][kk+lc  ];
                a[1] = Qs[qb+lr+8][kk+lc  ];
                a[2] = Qs[qb+lr  ][kk+lc+4];
                a[3] = Qs[qb+lr+8][kk+lc+4];
#pragma unroll
                for (int nt = 0; nt < 8; nt++) {
                    unsigned b0 = Ks[nt*8+lr][kk+lc];
                    unsigned b1 = Ks[nt*8+lr][kk+lc+4];
                    mma_tf32(sc[nt], a, b0, b1);
                }
            }
#pragma unroll
            for (int nt = 0; nt < 8; nt++) {
                Ss[qb+lr  ][nt*8 + lc*2    ] = sc[nt][0];
                Ss[qb+lr  ][nt*8 + lc*2 + 1] = sc[nt][1];
                Ss[qb+lr+8][nt*8 + lc*2    ] = sc[nt][2];
                Ss[qb+lr+8][nt*8 + lc*2 + 1] = sc[nt][3];
            }
        }
        __syncthreads();

        // online softmax: 2 threads per row
        {
            int q = tid >> 1, sub = tid & 1;
            const uchar4* dp = (const uchar4*)(g_dist +
                (size_t)(g*Mn + q0 + q)*Mn + tk*64 + sub*32);
            float* srow = &Ss[q][sub*32];
            float rm = -1e30f;
#pragma unroll
            for (int j4 = 0; j4 < 8; j4++) {
                uchar4 dv = dp[j4];
                float s0 = srow[j4*4+0] + btab[dv.x];
                float s1 = srow[j4*4+1] + btab[dv.y];
                float s2 = srow[j4*4+2] + btab[dv.z];
                float s3 = srow[j4*4+3] + btab[dv.w];
                srow[j4*4+0] = s0; srow[j4*4+1] = s1;
                srow[j4*4+2] = s2; srow[j4*4+3] = s3;
                rm = fmaxf(rm, fmaxf(fmaxf(s0, s1), fmaxf(s2, s3)));
            }
            rm = fmaxf(rm, __shfl_xor_sync(0xffffffffu, rm, 1));
            rm = fmaxf(rm, m_s[q]);
            float rs = 0.0f;
#pragma unroll
            for (int j = 0; j < 32; j++) {
                float p = __expf(srow[j] - rm);
                rs += p;
                srow[j] = __uint_as_float(f2tf(p));
            }
            rs += __shfl_xor_sync(0xffffffffu, rs, 1);
            if (sub == 0) {
                float f = __expf(m_s[q] - rm);
                f_s[q] = f;
                l_s[q] = l_s[q]*f + rs;
                m_s[q] = rm;
            }
        }
        __syncthreads();

        // PV
        {
            float f0 = f_s[qb+lr], f1 = f_s[qb+lr+8];
#pragma unroll
            for (int nt = 0; nt < 4; nt++) {
                acc[nt][0] *= f0; acc[nt][1] *= f0;
                acc[nt][2] *= f1; acc[nt][3] *= f1;
            }
#pragma unroll
            for (int kk = 0; kk < 64; kk += 8) {
                unsigned a[4];
                a[0] = __float_as_uint(Ss[qb+lr  ][kk+lc  ]);
                a[1] = __float_as_uint(Ss[qb+lr+8][kk+lc  ]);
                a[2] = __float_as_uint(Ss[qb+lr  ][kk+lc+4]);
                a[3] = __float_as_uint(Ss[qb+lr+8][kk+lc+4]);
#pragma unroll
                for (int nt = 0; nt < 4; nt++) {
                    unsigned b0 = Vs[kk+lc  ][nt*8+lr];
                    unsigned b1 = Vs[kk+lc+4][nt*8+lr];
                    mma_tf32(acc[nt], a, b0, b1);
                }
            }
        }
    }

    float l0 = 1.0f / l_s[qb+lr];
    float l1 = 1.0f / l_s[qb+lr+8];
#pragma unroll
    for (int nt = 0; nt < 4; nt++) {
        int d = head*32 + nt*8 + lc*2;
        *(float2*)(g_attn + (size_t)(g*Mn + q0 + qb + lr  )*Hn + d) =
            make_float2(acc[nt][0]*l0, acc[nt][1]*l0);
        *(float2*)(g_attn + (size_t)(g*Mn + q0 + qb + lr+8)*Hn + d) =
            make_float2(acc[nt][2]*l1, acc[nt][3]*l1);
    }
}

// ---------------- fused launches --------------------------------------------
__global__ __launch_bounds__(256) void k_fill_xw(
    const int* __restrict__ src, const int* __restrict__ dst,
    const float* __restrict__ x, const float* __restrict__ gcn_w,
    float* __restrict__ xw)
{
    extern __shared__ unsigned sm[];
    int bid = blockIdx.x;
    if (bid < 512) {
        gemm_body<64>(x, gcn_w, nullptr, xw, 256, 256, 0, bid & 3, bid >> 2, sm);
    } else {
        fill_body((bid - 512) * 256 + threadIdx.x, src, dst);
    }
}

__global__ __launch_bounds__(256) void k_qkv_bfs(
    const float* __restrict__ x, const float* __restrict__ qkv_w,
    const float* __restrict__ qkv_b, float* __restrict__ qkv)
{
    extern __shared__ unsigned sm[];
    int bid = blockIdx.x;
    if (bid < 768) {
        gemm_body<128>(x, qkv_w, qkv_b, qkv, 768, 256, 0, bid % 12, bid / 12, sm);
    } else {
        int row = (bid - 768) * 8 + (threadIdx.x >> 5);
        bfs_body(row, threadIdx.x & 31);
    }
}

__global__ __launch_bounds__(256) void k_attn_gather(
    const float* __restrict__ bias_emb, const float* __restrict__ gcn_b)
{
    extern __shared__ unsigned sm[];
    int bid = blockIdx.x;
    if (bid < 512) {
        attn_body(bias_emb, bid >> 6, (bid >> 3) & 7, (bid & 7) * 128, sm);
    } else {
        gather_body(bid - 512, threadIdx.x, gcn_b);
    }
}

// ---------------- LayerNorm: out = LN(a [+ b] [+ c]) * gamma + beta --------
__global__ __launch_bounds__(256) void ln_kernel(
    const float* __restrict__ a, const float* __restrict__ b, const float* __restrict__ c,
    const float* __restrict__ gam, const float* __restrict__ bet, float* __restrict__ out)
{
    __shared__ float s1[8], s2[8];
    int row = blockIdx.x, t = threadIdx.x;
    int w = t >> 5;
    size_t off = (size_t)row * Hn + t;
    float v = a[off];
    if (b) v += b[off];
    if (c) v += c[off];
    float su = v, sq = v * v;
#pragma unroll
    for (int d = 16; d; d >>= 1) {
        su += __shfl_xor_sync(0xffffffffu, su, d);
        sq += __shfl_xor_sync(0xffffffffu, sq, d);
    }
    if ((t & 31) == 0) { s1[w] = su; s2[w] = sq; }
    __syncthreads();
    su = 0.0f; sq = 0.0f;
#pragma unroll
    for (int j = 0; j < 8; j++) { su += s1[j]; sq += s2[j]; }
    float mean = su * (1.0f / Hn);
    float var = sq * (1.0f / Hn) - mean * mean;
    out[off] = (v - mean) * rsqrtf(var + 1e-5f) * gam[t] + bet[t];
}

// ---------------- host launch ----------------------------------------------
static float* sym_addr(const void* s) {
    void* p = nullptr;
    cudaGetSymbolAddress(&p, s);
    return (float*)p;
}

extern "C" void kernel_launch(void* const* d_in, const int* in_sizes, int n_in,
                              void* d_out, int out_size) {
    const float* x      = (const float*)d_in[0];
    const float* gcn_w  = (const float*)d_in[1];
    const float* gcn_b  = (const float*)d_in[2];
    const float* qkv_w  = (const float*)d_in[3];
    const float* qkv_b  = (const float*)d_in[4];
    const float* proj_w = (const float*)d_in[5];
    const float* proj_b = (const float*)d_in[6];
    const float* ln1_g  = (const float*)d_in[7];
    const float* ln1_b  = (const float*)d_in[8];
    const float* ln2_g  = (const float*)d_in[9];
    const float* ln2_b  = (const float*)d_in[10];
    const float* ffn1_w = (const float*)d_in[11];
    const float* ffn1_b = (const float*)d_in[12];
    const float* ffn2_w = (const float*)d_in[13];
    const float* ffn2_b = (const float*)d_in[14];
    const float* bias_e = (const float*)d_in[15];
    const float* oln1_g = (const float*)d_in[16];
    const float* oln1_b = (const float*)d_in[17];
    const float* oln2_g = (const float*)d_in[18];
    const float* oln2_b = (const float*)d_in[19];
    const float* offn1_w= (const float*)d_in[20];
    const float* offn1_b= (const float*)d_in[21];
    const float* offn2_w= (const float*)d_in[22];
    const float* offn2_b= (const float*)d_in[23];
    const int*   eidx   = (const int*)d_in[24];
    const int* src = eidx;
    const int* dst = eidx + En;
    float* out = (float*)d_out;

    float* p_xw  = sym_addr(g_xw);
    float* p_xl  = sym_addr(g_xlocal);
    float* p_qkv = sym_addr(g_qkv);
    float* p_att = sym_addr(g_attn);
    float* p_buf = sym_addr(g_buf);
    float* p_h   = sym_addr(g_h);
    float* p_h2  = sym_addr(g_h2);
    float* p_y   = sym_addr(g_y);
    float* p_ff  = sym_addr(g_ff);

    const int SM128 = (2*128 + 2*64) * 20 * 4 * 2;  // 61440
    const int SM64  = (2*64  + 2*64) * 20 * 4 * 2;  // 40960
    const int ATTN_SMEM = 18312 * 4;                // 73248
    cudaFuncSetAttribute(gemm_bf16_kernel<128>, cudaFuncAttributeMaxDynamicSharedMemorySize, SM128);
    cudaFuncSetAttribute(gemm_bf16_kernel<64>,  cudaFuncAttributeMaxDynamicSharedMemorySize, SM64);
    cudaFuncSetAttribute(k_fill_xw,    cudaFuncAttributeMaxDynamicSharedMemorySize, SM64);
    cudaFuncSetAttribute(k_qkv_bfs,    cudaFuncAttributeMaxDynamicSharedMemorySize, SM128);
    cudaFuncSetAttribute(k_attn_gather, cudaFuncAttributeMaxDynamicSharedMemorySize, ATTN_SMEM);

    // graph prep
    init_deg_adj_kernel<<<1024, 256>>>();
    edge_prep_kernel<<<En/256, 256>>>(src, dst);
    scan_kernel<<<1, 1024>>>();
    k_fill_xw<<<512 + En/256, 256, SM64>>>(src, dst, x, gcn_w, p_xw);

    // transformer (+ hidden bfs / gather)
    k_qkv_bfs<<<768 + Nn/8, 256, SM128>>>(x, qkv_w, qkv_b, p_qkv);
    k_attn_gather<<<512 + Nn, 256, ATTN_SMEM>>>(bias_e, gcn_b);
    gemm_bf16_kernel<64><<<dim3(Hn/64, Nn/64), 256, SM64>>>(p_att, proj_w, proj_b, p_buf, Hn, Hn, 0);
    ln_kernel<<<Nn, 256>>>(x, p_buf, nullptr, ln1_g, ln1_b, p_h);
    gemm_bf16_kernel<128><<<dim3(FFNn/64, Nn/128), 256, SM128>>>(p_h, ffn1_w, ffn1_b, p_ff, FFNn, Hn, 1);
    gemm_bf16_kernel<64><<<dim3(Hn/64, Nn/64), 256, SM64>>>(p_ff, ffn2_w, ffn2_b, p_buf, Hn, FFNn, 0);
    ln_kernel<<<Nn, 256>>>(p_h, p_buf, nullptr, ln2_g, ln2_b, p_h2);

    // GPS combine + outer FFN
    ln_kernel<<<Nn, 256>>>(x, p_xl, p_h2, oln1_g, oln1_b, p_y);
    gemm_bf16_kernel<128><<<dim3(FFNn/64, Nn/128), 256, SM128>>>(p_y, offn1_w, offn1_b, p_ff, FFNn, Hn, 1);
    gemm_bf16_kernel<64><<<dim3(Hn/64, Nn/64), 256, SM64>>>(p_ff, offn2_w, offn2_b, p_buf, Hn, FFNn, 0);
    ln_kernel<<<Nn, 256>>>(p_y, p_buf, nullptr, oln2_g, oln2_b, out);
}

// round 5
// speedup vs baseline: 2.4675x; 1.1347x over previous
#include <cuda_runtime.h>
#include <cuda_bf16.h>
#include <math.h>

#define Gn 8
#define Mn 1024
#define Hn 256
#define HEADSn 8
#define HDn 32
#define FFNn 1024
#define Nn (Gn*Mn)          // 8192
#define En 131072
#define MWn (Mn/32)         // 32

// ---------------- scratch (device globals: no allocation allowed) ----------
static __device__ float g_xw[Nn*Hn];
static __device__ float g_xlocal[Nn*Hn];
static __device__ float g_dinv[Nn];
static __device__ int   g_deg[Nn];
static __device__ unsigned g_adj[Gn*Mn*MWn];
static __device__ unsigned char g_dist[(size_t)Gn*Mn*Mn];   // 8 MB
static __device__ float g_qkv[Nn*3*Hn];
static __device__ float g_attn[Nn*Hn];
static __device__ float g_buf[Nn*Hn];
static __device__ float g_h[Nn*Hn];
static __device__ float g_h2[Nn*Hn];
static __device__ float g_y[Nn*Hn];
static __device__ float g_ff[Nn*FFNn];
static __device__ int   g_off[Nn+1];
static __device__ int   g_cursor[Nn];
static __device__ int   g_eord[En];     // src node per CSR slot (sorted by dst)

// ---------------- helpers ---------------------------------------------------
__device__ __forceinline__ float gelu_exact(float x) {
    return 0.5f * x * (1.0f + erff(x * 0.7071067811865475f));
}

__device__ __forceinline__ unsigned packbf(float lo, float hi) {
    unsigned r;
    asm("cvt.rn.bf16x2.f32 %0, %1, %2;" : "=r"(r) : "f"(hi), "f"(lo));
    return r;
}

__device__ __forceinline__ void mma_bf16(float c[4], const unsigned a[4],
                                         unsigned b0, unsigned b1) {
    asm volatile(
        "mma.sync.aligned.m16n8k16.row.col.f32.bf16.bf16.f32 "
        "{%0,%1,%2,%3},{%4,%5,%6,%7},{%8,%9},{%0,%1,%2,%3};"
        : "+f"(c[0]), "+f"(c[1]), "+f"(c[2]), "+f"(c[3])
        : "r"(a[0]), "r"(a[1]), "r"(a[2]), "r"(a[3]), "r"(b0), "r"(b1));
}

// ---------------- init: deg=1, adj=0 ---------------------------------------
__global__ void init_deg_adj_kernel() {
    int i = blockIdx.x * blockDim.x + threadIdx.x;
    if (i < Nn) g_deg[i] = 1;
    if (i < Gn*Mn*MWn) g_adj[i] = 0;
}

__global__ void edge_prep_kernel(const int* __restrict__ src, const int* __restrict__ dst) {
    int e = blockIdx.x * blockDim.x + threadIdx.x;
    if (e >= En) return;
    int s = src[e], d = dst[e];
    atomicAdd(&g_deg[d], 1);
    if (s != d) {
        int g  = s >> 10;
        int ls = s & 1023, ld = d & 1023;
        atomicOr(&g_adj[(g*Mn + ls)*MWn + (ld >> 5)], 1u << (ld & 31));
        atomicOr(&g_adj[(g*Mn + ld)*MWn + (ls >> 5)], 1u << (ls & 31));
    }
}

// ---------------- scan: offsets + cursor + dinv (1 block, 1024 thr) --------
__global__ __launch_bounds__(1024) void scan_kernel() {
    __shared__ int wsum[32];
    int t = threadIdx.x, lane = t & 31, w = t >> 5;
    int base = t * 8;
    int loc[8]; int s = 0;
#pragma unroll
    for (int j = 0; j < 8; j++) {
        int dg = g_deg[base + j];
        g_dinv[base + j] = rsqrtf((float)dg);
        loc[j] = dg - 1; s += loc[j];
    }
    int inc = s;
#pragma unroll
    for (int d = 1; d < 32; d <<= 1) {
        int v = __shfl_up_sync(0xffffffffu, inc, d);
        if (lane >= d) inc += v;
    }
    if (lane == 31) wsum[w] = inc;
    __syncthreads();
    if (w == 0) {
        int v = wsum[lane];
#pragma unroll
        for (int d = 1; d < 32; d <<= 1) {
            int u = __shfl_up_sync(0xffffffffu, v, d);
            if (lane >= d) v += u;
        }
        wsum[lane] = v;
    }
    __syncthreads();
    int excl = inc - s + (w ? wsum[w-1] : 0);
#pragma unroll
    for (int j = 0; j < 8; j++) {
        g_off[base + j] = excl;
        g_cursor[base + j] = excl;
        excl += loc[j];
    }
    if (t == 1023) g_off[Nn] = excl;
}

// ---------------- body: CSR fill --------------------------------------------
__device__ __forceinline__ void fill_body(int e, const int* __restrict__ src,
                                          const int* __restrict__ dst) {
    if (e >= En) return;
    int d = dst[e];
    int pos = atomicAdd(&g_cursor[d], 1);
    g_eord[pos] = src[e];
}

// ---------------- body: GCN gather (1 block per dst node) -------------------
__device__ __forceinline__ void gather_body(int d, int t, const float* __restrict__ gcn_b) {
    float dinvd = g_dinv[d];
    float acc = g_xw[(size_t)d*Hn + t] * dinvd * dinvd + gcn_b[t];
    int beg = g_off[d], end = g_off[d+1];
    int e = beg;
    for (; e + 2 <= end; e += 2) {
        int s0 = g_eord[e], s1 = g_eord[e+1];
        float w0 = g_dinv[s0] * dinvd;
        float w1 = g_dinv[s1] * dinvd;
        float v0 = g_xw[(size_t)s0*Hn + t];
        float v1 = g_xw[(size_t)s1*Hn + t];
        acc += v0 * w0 + v1 * w1;
    }
    if (e < end) {
        int s0 = g_eord[e];
        acc += g_xw[(size_t)s0*Hn + t] * (g_dinv[s0] * dinvd);
    }
    g_xlocal[(size_t)d*Hn + t] = acc;
}

// ---------------- body: SPD bitset BFS, direction-optimal (warp per row) ---
__device__ __forceinline__ int warp_sum(int v) {
#pragma unroll
    for (int d = 16; d; d >>= 1) v += __shfl_xor_sync(0xffffffffu, v, d);
    return v;
}

__device__ __forceinline__ void bfs_body(int row, int lane) {
    int g = row >> 10, i = row & 1023;
    const unsigned* arow = g_adj + (size_t)row * MWn;
    unsigned frontier = arow[lane];
    unsigned diag = ((i >> 5) == lane) ? (1u << (i & 31)) : 0u;
    unsigned visited = frontier | diag;
    unsigned char* drow = g_dist + (size_t)row * Mn;

#pragma unroll
    for (int p = 0; p < 8; p++) {
        unsigned word = 0;
#pragma unroll
        for (int b = 0; b < 4; b++) {
            int bi = p*4 + b;
            int k = lane*32 + bi;
            unsigned char v = ((frontier >> bi) & 1u) ? 1 : ((k == i) ? 0 : 6);
            word |= ((unsigned)v) << (8*b);
        }
        *(unsigned*)(drow + lane*32 + p*4) = word;
    }

    for (int d = 2; d <= 5; d++) {
        int cf = warp_sum(__popc(frontier));
        if (cf == 0) break;
        int cu = 1024 - warp_sum(__popc(visited));
        if (cu == 0) break;
        unsigned newf = 0;
        if (cf <= cu) {
#pragma unroll 1
            for (int ws = 0; ws < 32; ws++) {
                unsigned fw = __shfl_sync(0xffffffffu, frontier, ws);
                while (fw) {
                    int b = __ffs(fw) - 1; fw &= fw - 1;
                    int j = ws*32 + b;
                    newf |= g_adj[((size_t)g*Mn + j)*MWn + lane];
                }
            }
            newf &= ~visited;
        } else {
            unsigned unv = ~visited;
#pragma unroll 1
            for (int ws = 0; ws < 32; ws++) {
                unsigned uw = __shfl_sync(0xffffffffu, unv, ws);
                while (uw) {
                    int b = __ffs(uw) - 1; uw &= uw - 1;
                    int j = ws*32 + b;
                    unsigned aw = g_adj[((size_t)g*Mn + j)*MWn + lane];
                    unsigned m = __ballot_sync(0xffffffffu, (aw & frontier) != 0u);
                    if (m && lane == ws) newf |= 1u << b;
                }
            }
        }
        visited |= newf;
        unsigned t = newf;
        while (t) {
            int b = __ffs(t) - 1; t &= t - 1;
            drow[lane*32 + b] = (unsigned char)d;
        }
        frontier = newf;
    }
}

// ---------------- body: bf16 split tensor-core GEMM -------------------------
template<int BM>
__device__ __forceinline__ void gemm_body(
    const float* __restrict__ A, const float* __restrict__ B,
    const float* __restrict__ bias, float* __restrict__ C,
    int Nc, int K, int act, int bx, int by, unsigned* sm)
{
    constexpr int WMW = (BM == 128) ? 4 : 2;
    constexpr int WNW = 8 / WMW;
    constexpr int WTN = 64 / WNW;
    constexpr int NT  = WTN / 8;
    constexpr int A4  = BM / 32;
    constexpr int STG = (2*BM + 2*64) * 20;

    int bm = by * BM, bn = bx * 64;
    int tid = threadIdx.x;
    int warp = tid >> 5, lane = tid & 31;
    int wm = warp / WNW, wn = warp % WNW;
    int lr = lane >> 2, lc = lane & 3;

    float acc[2][NT][4];
#pragma unroll
    for (int i = 0; i < 2; i++)
#pragma unroll
        for (int j = 0; j < NT; j++)
#pragma unroll
            for (int r = 0; r < 4; r++) acc[i][j][r] = 0.0f;

    {
        unsigned* AH = sm;
        unsigned* AL = AH + BM*20;
        unsigned* BH = AL + BM*20;
        unsigned* BL = BH + 64*20;
#pragma unroll
        for (int l = 0; l < A4; l++) {
            int e = tid + l*256;
            int row = e >> 3, c4 = (e & 7) * 4, p = (e & 7) * 2;
            float4 v = *(const float4*)(A + (size_t)(bm + row) * K + c4);
            unsigned h0 = packbf(v.x, v.y), h1 = packbf(v.z, v.w);
            float xh0 = __uint_as_float(h0 << 16), yh0 = __uint_as_float(h0 & 0xffff0000u);
            float xh1 = __uint_as_float(h1 << 16), yh1 = __uint_as_float(h1 & 0xffff0000u);
            *(uint2*)&AH[row*20 + p] = make_uint2(h0, h1);
            *(uint2*)&AL[row*20 + p] = make_uint2(packbf(v.x - xh0, v.y - yh0),
                                                  packbf(v.z - xh1, v.w - yh1));
        }
#pragma unroll
        for (int l = 0; l < 2; l++) {
            int e = tid + l*256;
            int row = e >> 3, c4 = (e & 7) * 4, p = (e & 7) * 2;
            float4 v = *(const float4*)(B + (size_t)(bn + row) * K + c4);
            unsigned h0 = packbf(v.x, v.y), h1 = packbf(v.z, v.w);
            float xh0 = __uint_as_float(h0 << 16), yh0 = __uint_as_float(h0 & 0xffff0000u);
            float xh1 = __uint_as_float(h1 << 16), yh1 = __uint_as_float(h1 & 0xffff0000u);
            *(uint2*)&BH[row*20 + p] = make_uint2(h0, h1);
            *(uint2*)&BL[row*20 + p] = make_uint2(packbf(v.x - xh0, v.y - yh0),
                                                  packbf(v.z - xh1, v.w - yh1));
        }
    }
    __syncthreads();

    int nk = K >> 5;
    for (int it = 0; it < nk; it++) {
        unsigned* AH = sm + (it & 1) * STG;
        unsigned* AL = AH + BM*20;
        unsigned* BH = AL + BM*20;
        unsigned* BL = BH + 64*20;

        float4 pa[A4], pb2[2];
        bool has = (it + 1 < nk);
        if (has) {
            int k0 = (it + 1) << 5;
#pragma unroll
            for (int l = 0; l < A4; l++) {
                int e = tid + l*256;
                int row = e >> 3, c4 = (e & 7) * 4;
                pa[l] = *(const float4*)(A + (size_t)(bm + row) * K + k0 + c4);
            }
#pragma unroll
            for (int l = 0; l < 2; l++) {
                int e = tid + l*256;
                int row = e >> 3, c4 = (e & 7) * 4;
                pb2[l] = *(const float4*)(B + (size_t)(bn + row) * K + k0 + c4);
            }
        }

#pragma unroll
        for (int ks = 0; ks < 2; ks++) {
            int pb = ks * 8;
            unsigned ah[2][4], al[2][4];
#pragma unroll
            for (int mt = 0; mt < 2; mt++) {
                int rA = wm*32 + mt*16;
                ah[mt][0] = AH[(rA+lr  )*20 + pb + lc];
                ah[mt][1] = AH[(rA+lr+8)*20 + pb + lc];
                ah[mt][2] = AH[(rA+lr  )*20 + pb + 4 + lc];
                ah[mt][3] = AH[(rA+lr+8)*20 + pb + 4 + lc];
                al[mt][0] = AL[(rA+lr  )*20 + pb + lc];
                al[mt][1] = AL[(rA+lr+8)*20 + pb + lc];
                al[mt][2] = AL[(rA+lr  )*20 + pb + 4 + lc];
                al[mt][3] = AL[(rA+lr+8)*20 + pb + 4 + lc];
            }
#pragma unroll
            for (int nt = 0; nt < NT; nt++) {
                int cB = wn*WTN + nt*8;
                unsigned bh0 = BH[(cB+lr)*20 + pb + lc];
                unsigned bh1 = BH[(cB+lr)*20 + pb + 4 + lc];
                unsigned bl0 = BL[(cB+lr)*20 + pb + lc];
                unsigned bl1 = BL[(cB+lr)*20 + pb + 4 + lc];
#pragma unroll
                for (int mt = 0; mt < 2; mt++) {
                    mma_bf16(acc[mt][nt], ah[mt], bh0, bh1);
                    mma_bf16(acc[mt][nt], al[mt], bh0, bh1);
                    mma_bf16(acc[mt][nt], ah[mt], bl0, bl1);
                }
            }
        }

        if (has) {
            unsigned* nAH = sm + ((it + 1) & 1) * STG;
            unsigned* nAL = nAH + BM*20;
            unsigned* nBH = nAL + BM*20;
            unsigned* nBL = nBH + 64*20;
#pragma unroll
            for (int l = 0; l < A4; l++) {
                int e = tid + l*256;
                int row = e >> 3, p = (e & 7) * 2;
                float4 v = pa[l];
                unsigned h0 = packbf(v.x, v.y), h1 = packbf(v.z, v.w);
                float xh0 = __uint_as_float(h0 << 16), yh0 = __uint_as_float(h0 & 0xffff0000u);
                float xh1 = __uint_as_float(h1 << 16), yh1 = __uint_as_float(h1 & 0xffff0000u);
                *(uint2*)&nAH[row*20 + p] = make_uint2(h0, h1);
                *(uint2*)&nAL[row*20 + p] = make_uint2(packbf(v.x - xh0, v.y - yh0),
                                                       packbf(v.z - xh1, v.w - yh1));
            }
#pragma unroll
            for (int l = 0; l < 2; l++) {
                int e = tid + l*256;
                int row = e >> 3, p = (e & 7) * 2;
                float4 v = pb2[l];
                unsigned h0 = packbf(v.x, v.y), h1 = packbf(v.z, v.w);
                float xh0 = __uint_as_float(h0 << 16), yh0 = __uint_as_float(h0 & 0xffff0000u);
                float xh1 = __uint_as_float(h1 << 16), yh1 = __uint_as_float(h1 & 0xffff0000u);
                *(uint2*)&nBH[row*20 + p] = make_uint2(h0, h1);
                *(uint2*)&nBL[row*20 + p] = make_uint2(packbf(v.x - xh0, v.y - yh0),
                                                       packbf(v.z - xh1, v.w - yh1));
            }
        }
        __syncthreads();
    }

#pragma unroll
    for (int mt = 0; mt < 2; mt++) {
#pragma unroll
        for (int nt = 0; nt < NT; nt++) {
            int m = bm + wm*32 + mt*16 + lr;
            int n = bn + wn*WTN + nt*8 + lc*2;
            float b0 = 0.0f, b1 = 0.0f;
            if (bias) { b0 = bias[n]; b1 = bias[n+1]; }
            float v0 = acc[mt][nt][0] + b0;
            float v1 = acc[mt][nt][1] + b1;
            float v2 = acc[mt][nt][2] + b0;
            float v3 = acc[mt][nt][3] + b1;
            if (act) { v0 = gelu_exact(v0); v1 = gelu_exact(v1);
                       v2 = gelu_exact(v2); v3 = gelu_exact(v3); }
            *(float2*)(C + (size_t)m * Nc + n) = make_float2(v0, v1);
            *(float2*)(C + (size_t)(m+8) * Nc + n) = make_float2(v2, v3);
        }
    }
}

template<int BM>
__global__ __launch_bounds__(256) void gemm_bf16_kernel(
    const float* __restrict__ A, const float* __restrict__ B,
    const float* __restrict__ bias, float* __restrict__ C,
    int Nc, int K, int act)
{
    extern __shared__ unsigned sm[];
    gemm_body<BM>(A, B, bias, C, Nc, K, act, blockIdx.x, blockIdx.y, sm);
}

// ---------------- attention v2: all-bf16, register softmax, double-buffer --
// smem layout (u32 offsets):
//   Ks[2]  : 0    + s*1280  (64 rows x 20 u32)
//   VsT[2] : 2560 + s*1152  (32 rows x 36 u32)
//   ds[2]  : 4864 + s*2176  (128 rows x 17 u32)
//   btab   : 9216 (8 floats)
#define ATTN_SMEM_U32 9224

__device__ __forceinline__ void attn_body(const float* __restrict__ bias_emb,
                                          int g, int head, int q0, unsigned* sm) {
    int tid = threadIdx.x;
    int warp = tid >> 5, lane = tid & 31;
    int lr = lane >> 2, lc = lane & 3;
    int qb = warp * 16;
    const float scale = 0.17677669529663687f;   // 32^-0.5

    float* btab = (float*)(sm + 9216);
    if (tid < 7) btab[tid] = bias_emb[tid];

    // Q fragments in registers (scaled, bf16)
    unsigned aq[2][4];
    {
        size_t r0 = (size_t)(g*Mn + q0 + qb + lr)*768 + head*32;
        size_t r1 = (size_t)(g*Mn + q0 + qb + lr + 8)*768 + head*32;
#pragma unroll
        for (int ch = 0; ch < 2; ch++) {
            float2 v0 = *(const float2*)&g_qkv[r0 + 16*ch + 2*lc];
            float2 v1 = *(const float2*)&g_qkv[r1 + 16*ch + 2*lc];
            float2 v2 = *(const float2*)&g_qkv[r0 + 16*ch + 8 + 2*lc];
            float2 v3 = *(const float2*)&g_qkv[r1 + 16*ch + 8 + 2*lc];
            aq[ch][0] = packbf(v0.x*scale, v0.y*scale);
            aq[ch][1] = packbf(v1.x*scale, v1.y*scale);
            aq[ch][2] = packbf(v2.x*scale, v2.y*scale);
            aq[ch][3] = packbf(v3.x*scale, v3.y*scale);
        }
    }

    float acc[4][4];
#pragma unroll
    for (int i = 0; i < 4; i++)
#pragma unroll
        for (int j = 0; j < 4; j++) acc[i][j] = 0.0f;
    float m0 = -1e30f, m1 = -1e30f, l0 = 0.0f, l1 = 0.0f;

    // ---- coop load tile 0 into stage 0 ----
    {
        unsigned* Ks = sm;
        __nv_bfloat16* Vt16 = (__nv_bfloat16*)(sm + 2560);
        unsigned* ds = sm + 4864;
#pragma unroll
        for (int l = 0; l < 4; l++) {
            int e = tid + l*256;
            int row = e >> 4, j = e & 15;
            size_t base = (size_t)(g*Mn + row)*768 + head*32 + 2*j;
            float2 kv = *(const float2*)&g_qkv[base + 256];
            float2 vv = *(const float2*)&g_qkv[base + 512];
            Ks[row*20 + j] = packbf(kv.x, kv.y);
            Vt16[(2*j)*72 + row]   = __float2bfloat16(vv.x);
            Vt16[(2*j+1)*72 + row] = __float2bfloat16(vv.y);
        }
#pragma unroll
        for (int l = 0; l < 2; l++) {
            int e = tid + l*256;
            int row = e >> 2, qd = e & 3;
            uint4 dv = *(const uint4*)&g_dist[(size_t)(g*Mn + q0 + row)*Mn + qd*16];
            ds[row*17 + qd*4 + 0] = dv.x;
            ds[row*17 + qd*4 + 1] = dv.y;
            ds[row*17 + qd*4 + 2] = dv.z;
            ds[row*17 + qd*4 + 3] = dv.w;
        }
    }
    __syncthreads();

    for (int tk = 0; tk < 16; tk++) {
        int s = tk & 1;
        unsigned* Ks = sm + s*1280;
        unsigned* Vt = sm + 2560 + s*1152;
        const unsigned short* ds16 = (const unsigned short*)(sm + 4864 + s*2176);

        // prefetch next tile
        float2 pk[4], pv[4];
        uint4 pd[2];
        bool has = (tk + 1 < 16);
        if (has) {
            int krow0 = (tk + 1) * 64;
#pragma unroll
            for (int l = 0; l < 4; l++) {
                int e = tid + l*256;
                int row = e >> 4, j = e & 15;
                size_t base = (size_t)(g*Mn + krow0 + row)*768 + head*32 + 2*j;
                pk[l] = *(const float2*)&g_qkv[base + 256];
                pv[l] = *(const float2*)&g_qkv[base + 512];
            }
#pragma unroll
            for (int l = 0; l < 2; l++) {
                int e = tid + l*256;
                int row = e >> 2, qd = e & 3;
                pd[l] = *(const uint4*)&g_dist[(size_t)(g*Mn + q0 + row)*Mn + krow0 + qd*16];
            }
        }

        // ---- QK^T ----
        float sc[8][4];
#pragma unroll
        for (int nt = 0; nt < 8; nt++)
#pragma unroll
            for (int r = 0; r < 4; r++) sc[nt][r] = 0.0f;
#pragma unroll
        for (int ch = 0; ch < 2; ch++) {
#pragma unroll
            for (int nt = 0; nt < 8; nt++) {
                unsigned b0 = Ks[(nt*8+lr)*20 + 8*ch + lc];
                unsigned b1 = Ks[(nt*8+lr)*20 + 8*ch + 4 + lc];
                mma_bf16(sc[nt], aq[ch], b0, b1);
            }
        }

        // ---- bias + row max (registers) ----
        float mn0 = m0, mn1 = m1;
#pragma unroll
        for (int nt = 0; nt < 8; nt++) {
            unsigned short w0 = ds16[(qb+lr)*34 + nt*4 + lc];
            unsigned short w1 = ds16[(qb+lr+8)*34 + nt*4 + lc];
            sc[nt][0] += btab[w0 & 255]; sc[nt][1] += btab[w0 >> 8];
            sc[nt][2] += btab[w1 & 255]; sc[nt][3] += btab[w1 >> 8];
            mn0 = fmaxf(mn0, fmaxf(sc[nt][0], sc[nt][1]));
            mn1 = fmaxf(mn1, fmaxf(sc[nt][2], sc[nt][3]));
        }
        mn0 = fmaxf(mn0, __shfl_xor_sync(0xffffffffu, mn0, 1));
        mn0 = fmaxf(mn0, __shfl_xor_sync(0xffffffffu, mn0, 2));
        mn1 = fmaxf(mn1, __shfl_xor_sync(0xffffffffu, mn1, 1));
        mn1 = fmaxf(mn1, __shfl_xor_sync(0xffffffffu, mn1, 2));
        float f0 = __expf(m0 - mn0);
        float f1 = __expf(m1 - mn1);

        // ---- exp + sum + pack P ----
        float rs0 = 0.0f, rs1 = 0.0f;
#pragma unroll
        for (int nt = 0; nt < 8; nt++) {
            float e0 = __expf(sc[nt][0] - mn0);
            float e1 = __expf(sc[nt][1] - mn0);
            float e2 = __expf(sc[nt][2] - mn1);
            float e3 = __expf(sc[nt][3] - mn1);
            rs0 += e0 + e1; rs1 += e2 + e3;
            sc[nt][0] = e0; sc[nt][1] = e1; sc[nt][2] = e2; sc[nt][3] = e3;
        }
        unsigned P[4][4];
#pragma unroll
        for (int ch = 0; ch < 4; ch++) {
            P[ch][0] = packbf(sc[2*ch][0],   sc[2*ch][1]);
            P[ch][1] = packbf(sc[2*ch][2],   sc[2*ch][3]);
            P[ch][2] = packbf(sc[2*ch+1][0], sc[2*ch+1][1]);
            P[ch][3] = packbf(sc[2*ch+1][2], sc[2*ch+1][3]);
        }
        rs0 += __shfl_xor_sync(0xffffffffu, rs0, 1);
        rs0 += __shfl_xor_sync(0xffffffffu, rs0, 2);
        rs1 += __shfl_xor_sync(0xffffffffu, rs1, 1);
        rs1 += __shfl_xor_sync(0xffffffffu, rs1, 2);
        l0 = l0*f0 + rs0; l1 = l1*f1 + rs1;
        m0 = mn0; m1 = mn1;

        // ---- rescale + PV ----
#pragma unroll
        for (int dt = 0; dt < 4; dt++) {
            acc[dt][0] *= f0; acc[dt][1] *= f0;
            acc[dt][2] *= f1; acc[dt][3] *= f1;
        }
#pragma unroll
        for (int ch = 0; ch < 4; ch++) {
#pragma unroll
            for (int dt = 0; dt < 4; dt++) {
                unsigned b0 = Vt[(dt*8+lr)*36 + 8*ch + lc];
                unsigned b1 = Vt[(dt*8+lr)*36 + 8*ch + 4 + lc];
                mma_bf16(acc[dt], P[ch], b0, b1);
            }
        }

        // ---- store prefetched tile into other stage ----
        if (has) {
            unsigned* nKs = sm + (s^1)*1280;
            __nv_bfloat16* nVt16 = (__nv_bfloat16*)(sm + 2560 + (s^1)*1152);
            unsigned* nds = sm + 4864 + (s^1)*2176;
#pragma unroll
            for (int l = 0; l < 4; l++) {
                int e = tid + l*256;
                int row = e >> 4, j = e & 15;
                nKs[row*20 + j] = packbf(pk[l].x, pk[l].y);
                nVt16[(2*j)*72 + row]   = __float2bfloat16(pv[l].x);
                nVt16[(2*j+1)*72 + row] = __float2bfloat16(pv[l].y);
            }
#pragma unroll
            for (int l = 0; l < 2; l++) {
                int e = tid + l*256;
                int row = e >> 2, qd = e & 3;
                nds[row*17 + qd*4 + 0] = pd[l].x;
                nds[row*17 + qd*4 + 1] = pd[l].y;
                nds[row*17 + qd*4 + 2] = pd[l].z;
                nds[row*17 + qd*4 + 3] = pd[l].w;
            }
        }
        __syncthreads();
    }

    // ---- epilogue ----
    float il0 = 1.0f / l0, il1 = 1.0f / l1;
#pragma unroll
    for (int dt = 0; dt < 4; dt++) {
        int d = head*32 + dt*8 + 2*lc;
        *(float2*)(g_attn + (size_t)(g*Mn + q0 + qb + lr  )*Hn + d) =
            make_float2(acc[dt][0]*il0, acc[dt][1]*il0);
        *(float2*)(g_attn + (size_t)(g*Mn + q0 + qb + lr+8)*Hn + d) =
            make_float2(acc[dt][2]*il1, acc[dt][3]*il1);
    }
}

// ---------------- fused launches --------------------------------------------
__global__ __launch_bounds__(256) void k_fill_xw(
    const int* __restrict__ src, const int* __restrict__ dst,
    const float* __restrict__ x, const float* __restrict__ gcn_w,
    float* __restrict__ xw)
{
    extern __shared__ unsigned sm[];
    int bid = blockIdx.x;
    if (bid < 512) {
        gemm_body<64>(x, gcn_w, nullptr, xw, 256, 256, 0, bid & 3, bid >> 2, sm);
    } else {
        fill_body((bid - 512) * 256 + threadIdx.x, src, dst);
    }
}

__global__ __launch_bounds__(256) void k_qkv_bfs(
    const float* __restrict__ x, const float* __restrict__ qkv_w,
    const float* __restrict__ qkv_b, float* __restrict__ qkv)
{
    extern __shared__ unsigned sm[];
    int bid = blockIdx.x;
    if (bid < 768) {
        gemm_body<128>(x, qkv_w, qkv_b, qkv, 768, 256, 0, bid % 12, bid / 12, sm);
    } else {
        int row = (bid - 768) * 8 + (threadIdx.x >> 5);
        bfs_body(row, threadIdx.x & 31);
    }
}

__global__ __launch_bounds__(256) void k_attn_gather(
    const float* __restrict__ bias_emb, const float* __restrict__ gcn_b)
{
    extern __shared__ unsigned sm[];
    int bid = blockIdx.x;
    if (bid < 512) {
        attn_body(bias_emb, bid >> 6, (bid >> 3) & 7, (bid & 7) * 128, sm);
    } else {
        gather_body(bid - 512, threadIdx.x, gcn_b);
    }
}

// ---------------- LayerNorm: out = LN(a [+ b] [+ c]) * gamma + beta --------
__global__ __launch_bounds__(256) void ln_kernel(
    const float* __restrict__ a, const float* __restrict__ b, const float* __restrict__ c,
    const float* __restrict__ gam, const float* __restrict__ bet, float* __restrict__ out)
{
    __shared__ float s1[8], s2[8];
    int row = blockIdx.x, t = threadIdx.x;
    int w = t >> 5;
    size_t off = (size_t)row * Hn + t;
    float v = a[off];
    if (b) v += b[off];
    if (c) v += c[off];
    float su = v, sq = v * v;
#pragma unroll
    for (int d = 16; d; d >>= 1) {
        su += __shfl_xor_sync(0xffffffffu, su, d);
        sq += __shfl_xor_sync(0xffffffffu, sq, d);
    }
    if ((t & 31) == 0) { s1[w] = su; s2[w] = sq; }
    __syncthreads();
    su = 0.0f; sq = 0.0f;
#pragma unroll
    for (int j = 0; j < 8; j++) { su += s1[j]; sq += s2[j]; }
    float mean = su * (1.0f / Hn);
    float var = sq * (1.0f / Hn) - mean * mean;
    out[off] = (v - mean) * rsqrtf(var + 1e-5f) * gam[t] + bet[t];
}

// ---------------- host launch ----------------------------------------------
static float* sym_addr(const void* s) {
    void* p = nullptr;
    cudaGetSymbolAddress(&p, s);
    return (float*)p;
}

extern "C" void kernel_launch(void* const* d_in, const int* in_sizes, int n_in,
                              void* d_out, int out_size) {
    const float* x      = (const float*)d_in[0];
    const float* gcn_w  = (const float*)d_in[1];
    const float* gcn_b  = (const float*)d_in[2];
    const float* qkv_w  = (const float*)d_in[3];
    const float* qkv_b  = (const float*)d_in[4];
    const float* proj_w = (const float*)d_in[5];
    const float* proj_b = (const float*)d_in[6];
    const float* ln1_g  = (const float*)d_in[7];
    const float* ln1_b  = (const float*)d_in[8];
    const float* ln2_g  = (const float*)d_in[9];
    const float* ln2_b  = (const float*)d_in[10];
    const float* ffn1_w = (const float*)d_in[11];
    const float* ffn1_b = (const float*)d_in[12];
    const float* ffn2_w = (const float*)d_in[13];
    const float* ffn2_b = (const float*)d_in[14];
    const float* bias_e = (const float*)d_in[15];
    const float* oln1_g = (const float*)d_in[16];
    const float* oln1_b = (const float*)d_in[17];
    const float* oln2_g = (const float*)d_in[18];
    const float* oln2_b = (const float*)d_in[19];
    const float* offn1_w= (const float*)d_in[20];
    const float* offn1_b= (const float*)d_in[21];
    const float* offn2_w= (const float*)d_in[22];
    const float* offn2_b= (const float*)d_in[23];
    const int*   eidx   = (const int*)d_in[24];
    const int* src = eidx;
    const int* dst = eidx + En;
    float* out = (float*)d_out;

    float* p_xw  = sym_addr(g_xw);
    float* p_xl  = sym_addr(g_xlocal);
    float* p_qkv = sym_addr(g_qkv);
    float* p_att = sym_addr(g_attn);
    float* p_buf = sym_addr(g_buf);
    float* p_h   = sym_addr(g_h);
    float* p_h2  = sym_addr(g_h2);
    float* p_y   = sym_addr(g_y);
    float* p_ff  = sym_addr(g_ff);

    const int SM128 = (2*128 + 2*64) * 20 * 4 * 2;  // 61440
    const int SM64  = (2*64  + 2*64) * 20 * 4 * 2;  // 40960
    const int ATTN_SMEM = ATTN_SMEM_U32 * 4;        // 36896
    cudaFuncSetAttribute(gemm_bf16_kernel<128>, cudaFuncAttributeMaxDynamicSharedMemorySize, SM128);
    cudaFuncSetAttribute(gemm_bf16_kernel<64>,  cudaFuncAttributeMaxDynamicSharedMemorySize, SM64);
    cudaFuncSetAttribute(k_fill_xw,    cudaFuncAttributeMaxDynamicSharedMemorySize, SM64);
    cudaFuncSetAttribute(k_qkv_bfs,    cudaFuncAttributeMaxDynamicSharedMemorySize, SM128);
    cudaFuncSetAttribute(k_attn_gather, cudaFuncAttributeMaxDynamicSharedMemorySize, ATTN_SMEM);

    // graph prep
    init_deg_adj_kernel<<<1024, 256>>>();
    edge_prep_kernel<<<En/256, 256>>>(src, dst);
    scan_kernel<<<1, 1024>>>();
    k_fill_xw<<<512 + En/256, 256, SM64>>>(src, dst, x, gcn_w, p_xw);

    // transformer (+ hidden bfs / gather)
    k_qkv_bfs<<<768 + Nn/8, 256, SM128>>>(x, qkv_w, qkv_b, p_qkv);
    k_attn_gather<<<512 + Nn, 256, ATTN_SMEM>>>(bias_e, gcn_b);
    gemm_bf16_kernel<64><<<dim3(Hn/64, Nn/64), 256, SM64>>>(p_att, proj_w, proj_b, p_buf, Hn, Hn, 0);
    ln_kernel<<<Nn, 256>>>(x, p_buf, nullptr, ln1_g, ln1_b, p_h);
    gemm_bf16_kernel<128><<<dim3(FFNn/64, Nn/128), 256, SM128>>>(p_h, ffn1_w, ffn1_b, p_ff, FFNn, Hn, 1);
    gemm_bf16_kernel<64><<<dim3(Hn/64, Nn/64), 256, SM64>>>(p_ff, ffn2_w, ffn2_b, p_buf, Hn, FFNn, 0);
    ln_kernel<<<Nn, 256>>>(p_h, p_buf, nullptr, ln2_g, ln2_b, p_h2);

    // GPS combine + outer FFN
    ln_kernel<<<Nn, 256>>>(x, p_xl, p_h2, oln1_g, oln1_b, p_y);
    gemm_bf16_kernel<128><<<dim3(FFNn/64, Nn/128), 256, SM128>>>(p_y, offn1_w, offn1_b, p_ff, FFNn, Hn, 1);
    gemm_bf16_kernel<64><<<dim3(Hn/64, Nn/64), 256, SM64>>>(p_ff, offn2_w, offn2_b, p_buf, Hn, FFNn, 0);
    ln_kernel<<<Nn, 256>>>(p_y, p_buf, nullptr, oln2_g, oln2_b, out);
}

// round 6
// speedup vs baseline: 3.2482x; 1.3164x over previous
#include <cuda_runtime.h>
#include <cuda_bf16.h>
#include <math.h>

#define Gn 8
#define Mn 1024
#define Hn 256
#define HEADSn 8
#define HDn 32
#define FFNn 1024
#define Nn (Gn*Mn)          // 8192
#define En 131072
#define MWn (Mn/32)         // 32

// ---------------- scratch (device globals: no allocation allowed) ----------
static __device__ float g_xw[Nn*Hn];
static __device__ float g_xlocal[Nn*Hn];
static __device__ float g_dinv[Nn];
static __device__ int   g_deg[Nn];
static __device__ unsigned g_adj[Gn*Mn*MWn];
static __device__ unsigned char g_dist[(size_t)Gn*Mn*Mn];   // 8 MB
static __device__ float g_qkv[Nn*3*Hn];
static __device__ float g_attn[Nn*Hn];
static __device__ float g_buf[Nn*Hn];
static __device__ float g_h[Nn*Hn];
static __device__ float g_h2[Nn*Hn];
static __device__ float g_y[Nn*Hn];
static __device__ float g_ff[Nn*FFNn];
static __device__ int   g_off[Nn+1];
static __device__ int   g_cursor[Nn];
static __device__ int   g_eord[En];     // src node per CSR slot (sorted by dst)

// ---------------- helpers ---------------------------------------------------
__device__ __forceinline__ float gelu_exact(float x) {
    return 0.5f * x * (1.0f + erff(x * 0.7071067811865475f));
}

__device__ __forceinline__ unsigned packbf(float lo, float hi) {
    unsigned r;
    asm("cvt.rn.bf16x2.f32 %0, %1, %2;" : "=r"(r) : "f"(hi), "f"(lo));
    return r;
}

__device__ __forceinline__ void mma_bf16(float c[4], const unsigned a[4],
                                         unsigned b0, unsigned b1) {
    asm volatile(
        "mma.sync.aligned.m16n8k16.row.col.f32.bf16.bf16.f32 "
        "{%0,%1,%2,%3},{%4,%5,%6,%7},{%8,%9},{%0,%1,%2,%3};"
        : "+f"(c[0]), "+f"(c[1]), "+f"(c[2]), "+f"(c[3])
        : "r"(a[0]), "r"(a[1]), "r"(a[2]), "r"(a[3]), "r"(b0), "r"(b1));
}

// ---------------- init: deg=1, adj=0 ---------------------------------------
__global__ void init_deg_adj_kernel() {
    int i = blockIdx.x * blockDim.x + threadIdx.x;
    if (i < Nn) g_deg[i] = 1;
    if (i < Gn*Mn*MWn) g_adj[i] = 0;
}

__global__ void edge_prep_kernel(const int* __restrict__ src, const int* __restrict__ dst) {
    int e = blockIdx.x * blockDim.x + threadIdx.x;
    if (e >= En) return;
    int s = src[e], d = dst[e];
    atomicAdd(&g_deg[d], 1);
    if (s != d) {
        int g  = s >> 10;
        int ls = s & 1023, ld = d & 1023;
        atomicOr(&g_adj[(g*Mn + ls)*MWn + (ld >> 5)], 1u << (ld & 31));
        atomicOr(&g_adj[(g*Mn + ld)*MWn + (ls >> 5)], 1u << (ls & 31));
    }
}

// ---------------- scan: offsets + cursor + dinv (1 block, 1024 thr) --------
__global__ __launch_bounds__(1024) void scan_kernel() {
    __shared__ int wsum[32];
    int t = threadIdx.x, lane = t & 31, w = t >> 5;
    int base = t * 8;
    int loc[8]; int s = 0;
#pragma unroll
    for (int j = 0; j < 8; j++) {
        int dg = g_deg[base + j];
        g_dinv[base + j] = rsqrtf((float)dg);
        loc[j] = dg - 1; s += loc[j];
    }
    int inc = s;
#pragma unroll
    for (int d = 1; d < 32; d <<= 1) {
        int v = __shfl_up_sync(0xffffffffu, inc, d);
        if (lane >= d) inc += v;
    }
    if (lane == 31) wsum[w] = inc;
    __syncthreads();
    if (w == 0) {
        int v = wsum[lane];
#pragma unroll
        for (int d = 1; d < 32; d <<= 1) {
            int u = __shfl_up_sync(0xffffffffu, v, d);
            if (lane >= d) v += u;
        }
        wsum[lane] = v;
    }
    __syncthreads();
    int excl = inc - s + (w ? wsum[w-1] : 0);
#pragma unroll
    for (int j = 0; j < 8; j++) {
        g_off[base + j] = excl;
        g_cursor[base + j] = excl;
        excl += loc[j];
    }
    if (t == 1023) g_off[Nn] = excl;
}

// ---------------- body: CSR fill --------------------------------------------
__device__ __forceinline__ void fill_body(int e, const int* __restrict__ src,
                                          const int* __restrict__ dst) {
    if (e >= En) return;
    int d = dst[e];
    int pos = atomicAdd(&g_cursor[d], 1);
    g_eord[pos] = src[e];
}

// ---------------- body: GCN gather (1 block per dst node) -------------------
__device__ __forceinline__ void gather_body(int d, int t, const float* __restrict__ gcn_b) {
    float dinvd = g_dinv[d];
    float acc = g_xw[(size_t)d*Hn + t] * dinvd * dinvd + gcn_b[t];
    int beg = g_off[d], end = g_off[d+1];
    int e = beg;
    for (; e + 2 <= end; e += 2) {
        int s0 = g_eord[e], s1 = g_eord[e+1];
        float w0 = g_dinv[s0] * dinvd;
        float w1 = g_dinv[s1] * dinvd;
        float v0 = g_xw[(size_t)s0*Hn + t];
        float v1 = g_xw[(size_t)s1*Hn + t];
        acc += v0 * w0 + v1 * w1;
    }
    if (e < end) {
        int s0 = g_eord[e];
        acc += g_xw[(size_t)s0*Hn + t] * (g_dinv[s0] * dinvd);
    }
    g_xlocal[(size_t)d*Hn + t] = acc;
}

// ---------------- body: SPD bitset BFS, direction-optimal (warp per row) ---
__device__ __forceinline__ int warp_sum(int v) {
#pragma unroll
    for (int d = 16; d; d >>= 1) v += __shfl_xor_sync(0xffffffffu, v, d);
    return v;
}

__device__ __forceinline__ void bfs_body(int row, int lane) {
    int g = row >> 10, i = row & 1023;
    const unsigned* arow = g_adj + (size_t)row * MWn;
    unsigned frontier = arow[lane];
    unsigned diag = ((i >> 5) == lane) ? (1u << (i & 31)) : 0u;
    unsigned visited = frontier | diag;
    unsigned char* drow = g_dist + (size_t)row * Mn;

#pragma unroll
    for (int p = 0; p < 8; p++) {
        unsigned word = 0;
#pragma unroll
        for (int b = 0; b < 4; b++) {
            int bi = p*4 + b;
            int k = lane*32 + bi;
            unsigned char v = ((frontier >> bi) & 1u) ? 1 : ((k == i) ? 0 : 6);
            word |= ((unsigned)v) << (8*b);
        }
        *(unsigned*)(drow + lane*32 + p*4) = word;
    }

    for (int d = 2; d <= 5; d++) {
        int cf = warp_sum(__popc(frontier));
        if (cf == 0) break;
        int cu = 1024 - warp_sum(__popc(visited));
        if (cu == 0) break;
        unsigned newf = 0;
        if (cf <= cu) {
#pragma unroll 1
            for (int ws = 0; ws < 32; ws++) {
                unsigned fw = __shfl_sync(0xffffffffu, frontier, ws);
                while (fw) {
                    int b = __ffs(fw) - 1; fw &= fw - 1;
                    int j = ws*32 + b;
                    newf |= g_adj[((size_t)g*Mn + j)*MWn + lane];
                }
            }
            newf &= ~visited;
        } else {
            unsigned unv = ~visited;
#pragma unroll 1
            for (int ws = 0; ws < 32; ws++) {
                unsigned uw = __shfl_sync(0xffffffffu, unv, ws);
                while (uw) {
                    int b = __ffs(uw) - 1; uw &= uw - 1;
                    int j = ws*32 + b;
                    unsigned aw = g_adj[((size_t)g*Mn + j)*MWn + lane];
                    unsigned m = __ballot_sync(0xffffffffu, (aw & frontier) != 0u);
                    if (m && lane == ws) newf |= 1u << b;
                }
            }
        }
        visited |= newf;
        unsigned t = newf;
        while (t) {
            int b = __ffs(t) - 1; t &= t - 1;
            drow[lane*32 + b] = (unsigned char)d;
        }
        frontier = newf;
    }
}

// ---------------- body: single-pass bf16 tensor-core GEMM -------------------
// C[M,Nc] = act(A[M,K] * B[Nc,K]^T + bias). Tile BM x 64, K-step 32,
// double-buffered smem. 256 threads.
template<int BM>
__device__ __forceinline__ void gemm_body(
    const float* __restrict__ A, const float* __restrict__ B,
    const float* __restrict__ bias, float* __restrict__ C,
    int Nc, int K, int act, int bx, int by, unsigned* sm)
{
    constexpr int WMW = (BM == 128) ? 4 : 2;
    constexpr int WNW = 8 / WMW;
    constexpr int WTN = 64 / WNW;
    constexpr int NT  = WTN / 8;
    constexpr int A4  = BM / 32;
    constexpr int STG = (BM + 64) * 20;

    int bm = by * BM, bn = bx * 64;
    int tid = threadIdx.x;
    int warp = tid >> 5, lane = tid & 31;
    int wm = warp / WNW, wn = warp % WNW;
    int lr = lane >> 2, lc = lane & 3;

    float acc[2][NT][4];
#pragma unroll
    for (int i = 0; i < 2; i++)
#pragma unroll
        for (int j = 0; j < NT; j++)
#pragma unroll
            for (int r = 0; r < 4; r++) acc[i][j][r] = 0.0f;

    // ---- prologue: load + convert stage 0 ----
    {
        unsigned* AH = sm;
        unsigned* BH = AH + BM*20;
#pragma unroll
        for (int l = 0; l < A4; l++) {
            int e = tid + l*256;
            int row = e >> 3, c4 = (e & 7) * 4, p = (e & 7) * 2;
            float4 v = *(const float4*)(A + (size_t)(bm + row) * K + c4);
            *(uint2*)&AH[row*20 + p] = make_uint2(packbf(v.x, v.y), packbf(v.z, v.w));
        }
#pragma unroll
        for (int l = 0; l < 2; l++) {
            int e = tid + l*256;
            int row = e >> 3, c4 = (e & 7) * 4, p = (e & 7) * 2;
            float4 v = *(const float4*)(B + (size_t)(bn + row) * K + c4);
            *(uint2*)&BH[row*20 + p] = make_uint2(packbf(v.x, v.y), packbf(v.z, v.w));
        }
    }
    __syncthreads();

    int nk = K >> 5;
    for (int it = 0; it < nk; it++) {
        unsigned* AH = sm + (it & 1) * STG;
        unsigned* BH = AH + BM*20;

        // prefetch next k-slab into registers
        float4 pa[A4], pb2[2];
        bool has = (it + 1 < nk);
        if (has) {
            int k0 = (it + 1) << 5;
#pragma unroll
            for (int l = 0; l < A4; l++) {
                int e = tid + l*256;
                int row = e >> 3, c4 = (e & 7) * 4;
                pa[l] = *(const float4*)(A + (size_t)(bm + row) * K + k0 + c4);
            }
#pragma unroll
            for (int l = 0; l < 2; l++) {
                int e = tid + l*256;
                int row = e >> 3, c4 = (e & 7) * 4;
                pb2[l] = *(const float4*)(B + (size_t)(bn + row) * K + k0 + c4);
            }
        }

        // compute on current buffer: two k16 steps
#pragma unroll
        for (int ks = 0; ks < 2; ks++) {
            int pb = ks * 8;
            unsigned ah[2][4];
#pragma unroll
            for (int mt = 0; mt < 2; mt++) {
                int rA = wm*32 + mt*16;
                ah[mt][0] = AH[(rA+lr  )*20 + pb + lc];
                ah[mt][1] = AH[(rA+lr+8)*20 + pb + lc];
                ah[mt][2] = AH[(rA+lr  )*20 + pb + 4 + lc];
                ah[mt][3] = AH[(rA+lr+8)*20 + pb + 4 + lc];
            }
#pragma unroll
            for (int nt = 0; nt < NT; nt++) {
                int cB = wn*WTN + nt*8;
                unsigned bh0 = BH[(cB+lr)*20 + pb + lc];
                unsigned bh1 = BH[(cB+lr)*20 + pb + 4 + lc];
#pragma unroll
                for (int mt = 0; mt < 2; mt++)
                    mma_bf16(acc[mt][nt], ah[mt], bh0, bh1);
            }
        }

        // convert + store next buffer
        if (has) {
            unsigned* nAH = sm + ((it + 1) & 1) * STG;
            unsigned* nBH = nAH + BM*20;
#pragma unroll
            for (int l = 0; l < A4; l++) {
                int e = tid + l*256;
                int row = e >> 3, p = (e & 7) * 2;
                float4 v = pa[l];
                *(uint2*)&nAH[row*20 + p] = make_uint2(packbf(v.x, v.y), packbf(v.z, v.w));
            }
#pragma unroll
            for (int l = 0; l < 2; l++) {
                int e = tid + l*256;
                int row = e >> 3, p = (e & 7) * 2;
                float4 v = pb2[l];
                *(uint2*)&nBH[row*20 + p] = make_uint2(packbf(v.x, v.y), packbf(v.z, v.w));
            }
        }
        __syncthreads();
    }

    // ---- epilogue ----
#pragma unroll
    for (int mt = 0; mt < 2; mt++) {
#pragma unroll
        for (int nt = 0; nt < NT; nt++) {
            int m = bm + wm*32 + mt*16 + lr;
            int n = bn + wn*WTN + nt*8 + lc*2;
            float b0 = 0.0f, b1 = 0.0f;
            if (bias) { b0 = bias[n]; b1 = bias[n+1]; }
            float v0 = acc[mt][nt][0] + b0;
            float v1 = acc[mt][nt][1] + b1;
            float v2 = acc[mt][nt][2] + b0;
            float v3 = acc[mt][nt][3] + b1;
            if (act) { v0 = gelu_exact(v0); v1 = gelu_exact(v1);
                       v2 = gelu_exact(v2); v3 = gelu_exact(v3); }
            *(float2*)(C + (size_t)m * Nc + n) = make_float2(v0, v1);
            *(float2*)(C + (size_t)(m+8) * Nc + n) = make_float2(v2, v3);
        }
    }
}

template<int BM>
__global__ __launch_bounds__(256) void gemm_bf16_kernel(
    const float* __restrict__ A, const float* __restrict__ B,
    const float* __restrict__ bias, float* __restrict__ C,
    int Nc, int K, int act)
{
    extern __shared__ unsigned sm[];
    gemm_body<BM>(A, B, bias, C, Nc, K, act, blockIdx.x, blockIdx.y, sm);
}

// ---------------- attention: all-bf16, register softmax, double-buffer -----
// smem layout (u32 offsets):
//   Ks[2]  : 0    + s*1280  (64 rows x 20 u32)
//   VsT[2] : 2560 + s*1152  (32 rows x 36 u32)
//   ds[2]  : 4864 + s*2176  (128 rows x 17 u32)
//   btab   : 9216 (8 floats)
#define ATTN_SMEM_U32 9224

__device__ __forceinline__ void attn_body(const float* __restrict__ bias_emb,
                                          int g, int head, int q0, unsigned* sm) {
    int tid = threadIdx.x;
    int warp = tid >> 5, lane = tid & 31;
    int lr = lane >> 2, lc = lane & 3;
    int qb = warp * 16;
    const float scale = 0.17677669529663687f;   // 32^-0.5

    float* btab = (float*)(sm + 9216);
    if (tid < 7) btab[tid] = bias_emb[tid];

    // Q fragments in registers (scaled, bf16)
    unsigned aq[2][4];
    {
        size_t r0 = (size_t)(g*Mn + q0 + qb + lr)*768 + head*32;
        size_t r1 = (size_t)(g*Mn + q0 + qb + lr + 8)*768 + head*32;
#pragma unroll
        for (int ch = 0; ch < 2; ch++) {
            float2 v0 = *(const float2*)&g_qkv[r0 + 16*ch + 2*lc];
            float2 v1 = *(const float2*)&g_qkv[r1 + 16*ch + 2*lc];
            float2 v2 = *(const float2*)&g_qkv[r0 + 16*ch + 8 + 2*lc];
            float2 v3 = *(const float2*)&g_qkv[r1 + 16*ch + 8 + 2*lc];
            aq[ch][0] = packbf(v0.x*scale, v0.y*scale);
            aq[ch][1] = packbf(v1.x*scale, v1.y*scale);
            aq[ch][2] = packbf(v2.x*scale, v2.y*scale);
            aq[ch][3] = packbf(v3.x*scale, v3.y*scale);
        }
    }

    float acc[4][4];
#pragma unroll
    for (int i = 0; i < 4; i++)
#pragma unroll
        for (int j = 0; j < 4; j++) acc[i][j] = 0.0f;
    float m0 = -1e30f, m1 = -1e30f, l0 = 0.0f, l1 = 0.0f;

    // ---- coop load tile 0 into stage 0 ----
    {
        unsigned* Ks = sm;
        __nv_bfloat16* Vt16 = (__nv_bfloat16*)(sm + 2560);
        unsigned* ds = sm + 4864;
#pragma unroll
        for (int l = 0; l < 4; l++) {
            int e = tid + l*256;
            int row = e >> 4, j = e & 15;
            size_t base = (size_t)(g*Mn + row)*768 + head*32 + 2*j;
            float2 kv = *(const float2*)&g_qkv[base + 256];
            float2 vv = *(const float2*)&g_qkv[base + 512];
            Ks[row*20 + j] = packbf(kv.x, kv.y);
            Vt16[(2*j)*72 + row]   = __float2bfloat16(vv.x);
            Vt16[(2*j+1)*72 + row] = __float2bfloat16(vv.y);
        }
#pragma unroll
        for (int l = 0; l < 2; l++) {
            int e = tid + l*256;
            int row = e >> 2, qd = e & 3;
            uint4 dv = *(const uint4*)&g_dist[(size_t)(g*Mn + q0 + row)*Mn + qd*16];
            ds[row*17 + qd*4 + 0] = dv.x;
            ds[row*17 + qd*4 + 1] = dv.y;
            ds[row*17 + qd*4 + 2] = dv.z;
            ds[row*17 + qd*4 + 3] = dv.w;
        }
    }
    __syncthreads();

    for (int tk = 0; tk < 16; tk++) {
        int s = tk & 1;
        unsigned* Ks = sm + s*1280;
        unsigned* Vt = sm + 2560 + s*1152;
        const unsigned short* ds16 = (const unsigned short*)(sm + 4864 + s*2176);

        // prefetch next tile
        float2 pk[4], pv[4];
        uint4 pd[2];
        bool has = (tk + 1 < 16);
        if (has) {
            int krow0 = (tk + 1) * 64;
#pragma unroll
            for (int l = 0; l < 4; l++) {
                int e = tid + l*256;
                int row = e >> 4, j = e & 15;
                size_t base = (size_t)(g*Mn + krow0 + row)*768 + head*32 + 2*j;
                pk[l] = *(const float2*)&g_qkv[base + 256];
                pv[l] = *(const float2*)&g_qkv[base + 512];
            }
#pragma unroll
            for (int l = 0; l < 2; l++) {
                int e = tid + l*256;
                int row = e >> 2, qd = e & 3;
                pd[l] = *(const uint4*)&g_dist[(size_t)(g*Mn + q0 + row)*Mn + krow0 + qd*16];
            }
        }

        // ---- QK^T ----
        float sc[8][4];
#pragma unroll
        for (int nt = 0; nt < 8; nt++)
#pragma unroll
            for (int r = 0; r < 4; r++) sc[nt][r] = 0.0f;
#pragma unroll
        for (int ch = 0; ch < 2; ch++) {
#pragma unroll
            for (int nt = 0; nt < 8; nt++) {
                unsigned b0 = Ks[(nt*8+lr)*20 + 8*ch + lc];
                unsigned b1 = Ks[(nt*8+lr)*20 + 8*ch + 4 + lc];
                mma_bf16(sc[nt], aq[ch], b0, b1);
            }
        }

        // ---- bias + row max (registers) ----
        float mn0 = m0, mn1 = m1;
#pragma unroll
        for (int nt = 0; nt < 8; nt++) {
            unsigned short w0 = ds16[(qb+lr)*34 + nt*4 + lc];
            unsigned short w1 = ds16[(qb+lr+8)*34 + nt*4 + lc];
            sc[nt][0] += btab[w0 & 255]; sc[nt][1] += btab[w0 >> 8];
            sc[nt][2] += btab[w1 & 255]; sc[nt][3] += btab[w1 >> 8];
            mn0 = fmaxf(mn0, fmaxf(sc[nt][0], sc[nt][1]));
            mn1 = fmaxf(mn1, fmaxf(sc[nt][2], sc[nt][3]));
        }
        mn0 = fmaxf(mn0, __shfl_xor_sync(0xffffffffu, mn0, 1));
        mn0 = fmaxf(mn0, __shfl_xor_sync(0xffffffffu, mn0, 2));
        mn1 = fmaxf(mn1, __shfl_xor_sync(0xffffffffu, mn1, 1));
        mn1 = fmaxf(mn1, __shfl_xor_sync(0xffffffffu, mn1, 2));
        float f0 = __expf(m0 - mn0);
        float f1 = __expf(m1 - mn1);

        // ---- exp + sum + pack P ----
        float rs0 = 0.0f, rs1 = 0.0f;
#pragma unroll
        for (int nt = 0; nt < 8; nt++) {
            float e0 = __expf(sc[nt][0] - mn0);
            float e1 = __expf(sc[nt][1] - mn0);
            float e2 = __expf(sc[nt][2] - mn1);
            float e3 = __expf(sc[nt][3] - mn1);
            rs0 += e0 + e1; rs1 += e2 + e3;
            sc[nt][0] = e0; sc[nt][1] = e1; sc[nt][2] = e2; sc[nt][3] = e3;
        }
        unsigned P[4][4];
#pragma unroll
        for (int ch = 0; ch < 4; ch++) {
            P[ch][0] = packbf(sc[2*ch][0],   sc[2*ch][1]);
            P[ch][1] = packbf(sc[2*ch][2],   sc[2*ch][3]);
            P[ch][2] = packbf(sc[2*ch+1][0], sc[2*ch+1][1]);
            P[ch][3] = packbf(sc[2*ch+1][2], sc[2*ch+1][3]);
        }
        rs0 += __shfl_xor_sync(0xffffffffu, rs0, 1);
        rs0 += __shfl_xor_sync(0xffffffffu, rs0, 2);
        rs1 += __shfl_xor_sync(0xffffffffu, rs1, 1);
        rs1 += __shfl_xor_sync(0xffffffffu, rs1, 2);
        l0 = l0*f0 + rs0; l1 = l1*f1 + rs1;
        m0 = mn0; m1 = mn1;

        // ---- rescale + PV ----
#pragma unroll
        for (int dt = 0; dt < 4; dt++) {
            acc[dt][0] *= f0; acc[dt][1] *= f0;
            acc[dt][2] *= f1; acc[dt][3] *= f1;
        }
#pragma unroll
        for (int ch = 0; ch < 4; ch++) {
#pragma unroll
            for (int dt = 0; dt < 4; dt++) {
                unsigned b0 = Vt[(dt*8+lr)*36 + 8*ch + lc];
                unsigned b1 = Vt[(dt*8+lr)*36 + 8*ch + 4 + lc];
                mma_bf16(acc[dt], P[ch], b0, b1);
            }
        }

        // ---- store prefetched tile into other stage ----
        if (has) {
            unsigned* nKs = sm + (s^1)*1280;
            __nv_bfloat16* nVt16 = (__nv_bfloat16*)(sm + 2560 + (s^1)*1152);
            unsigned* nds = sm + 4864 + (s^1)*2176;
#pragma unroll
            for (int l = 0; l < 4; l++) {
                int e = tid + l*256;
                int row = e >> 4, j = e & 15;
                nKs[row*20 + j] = packbf(pk[l].x, pk[l].y);
                nVt16[(2*j)*72 + row]   = __float2bfloat16(pv[l].x);
                nVt16[(2*j+1)*72 + row] = __float2bfloat16(pv[l].y);
            }
#pragma unroll
            for (int l = 0; l < 2; l++) {
                int e = tid + l*256;
                int row = e >> 2, qd = e & 3;
                nds[row*17 + qd*4 + 0] = pd[l].x;
                nds[row*17 + qd*4 + 1] = pd[l].y;
                nds[row*17 + qd*4 + 2] = pd[l].z;
                nds[row*17 + qd*4 + 3] = pd[l].w;
            }
        }
        __syncthreads();
    }

    // ---- epilogue ----
    float il0 = 1.0f / l0, il1 = 1.0f / l1;
#pragma unroll
    for (int dt = 0; dt < 4; dt++) {
        int d = head*32 + dt*8 + 2*lc;
        *(float2*)(g_attn + (size_t)(g*Mn + q0 + qb + lr  )*Hn + d) =
            make_float2(acc[dt][0]*il0, acc[dt][1]*il0);
        *(float2*)(g_attn + (size_t)(g*Mn + q0 + qb + lr+8)*Hn + d) =
            make_float2(acc[dt][2]*il1, acc[dt][3]*il1);
    }
}

// ---------------- fused launches --------------------------------------------
__global__ __launch_bounds__(256) void k_fill_xw(
    const int* __restrict__ src, const int* __restrict__ dst,
    const float* __restrict__ x, const float* __restrict__ gcn_w,
    float* __restrict__ xw)
{
    extern __shared__ unsigned sm[];
    int bid = blockIdx.x;
    if (bid < 512) {
        gemm_body<64>(x, gcn_w, nullptr, xw, 256, 256, 0, bid & 3, bid >> 2, sm);
    } else {
        fill_body((bid - 512) * 256 + threadIdx.x, src, dst);
    }
}

__global__ __launch_bounds__(256) void k_qkv_bfs(
    const float* __restrict__ x, const float* __restrict__ qkv_w,
    const float* __restrict__ qkv_b, float* __restrict__ qkv)
{
    extern __shared__ unsigned sm[];
    int bid = blockIdx.x;
    if (bid < 768) {
        gemm_body<128>(x, qkv_w, qkv_b, qkv, 768, 256, 0, bid % 12, bid / 12, sm);
    } else {
        int row = (bid - 768) * 8 + (threadIdx.x >> 5);
        bfs_body(row, threadIdx.x & 31);
    }
}

__global__ __launch_bounds__(256) void k_attn_gather(
    const float* __restrict__ bias_emb, const float* __restrict__ gcn_b)
{
    extern __shared__ unsigned sm[];
    int bid = blockIdx.x;
    if (bid < 512) {
        attn_body(bias_emb, bid >> 6, (bid >> 3) & 7, (bid & 7) * 128, sm);
    } else {
        gather_body(bid - 512, threadIdx.x, gcn_b);
    }
}

// ---------------- LayerNorm: out = LN(a [+ b] [+ c]) * gamma + beta --------
__global__ __launch_bounds__(256) void ln_kernel(
    const float* __restrict__ a, const float* __restrict__ b, const float* __restrict__ c,
    const float* __restrict__ gam, const float* __restrict__ bet, float* __restrict__ out)
{
    __shared__ float s1[8], s2[8];
    int row = blockIdx.x, t = threadIdx.x;
    int w = t >> 5;
    size_t off = (size_t)row * Hn + t;
    float v = a[off];
    if (b) v += b[off];
    if (c) v += c[off];
    float su = v, sq = v * v;
#pragma unroll
    for (int d = 16; d; d >>= 1) {
        su += __shfl_xor_sync(0xffffffffu, su, d);
        sq += __shfl_xor_sync(0xffffffffu, sq, d);
    }
    if ((t & 31) == 0) { s1[w] = su; s2[w] = sq; }
    __syncthreads();
    su = 0.0f; sq = 0.0f;
#pragma unroll
    for (int j = 0; j < 8; j++) { su += s1[j]; sq += s2[j]; }
    float mean = su * (1.0f / Hn);
    float var = sq * (1.0f / Hn) - mean * mean;
    out[off] = (v - mean) * rsqrtf(var + 1e-5f) * gam[t] + bet[t];
}

// ---------------- host launch ----------------------------------------------
static float* sym_addr(const void* s) {
    void* p = nullptr;
    cudaGetSymbolAddress(&p, s);
    return (float*)p;
}

extern "C" void kernel_launch(void* const* d_in, const int* in_sizes, int n_in,
                              void* d_out, int out_size) {
    const float* x      = (const float*)d_in[0];
    const float* gcn_w  = (const float*)d_in[1];
    const float* gcn_b  = (const float*)d_in[2];
    const float* qkv_w  = (const float*)d_in[3];
    const float* qkv_b  = (const float*)d_in[4];
    const float* proj_w = (const float*)d_in[5];
    const float* proj_b = (const float*)d_in[6];
    const float* ln1_g  = (const float*)d_in[7];
    const float* ln1_b  = (const float*)d_in[8];
    const float* ln2_g  = (const float*)d_in[9];
    const float* ln2_b  = (const float*)d_in[10];
    const float* ffn1_w = (const float*)d_in[11];
    const float* ffn1_b = (const float*)d_in[12];
    const float* ffn2_w = (const float*)d_in[13];
    const float* ffn2_b = (const float*)d_in[14];
    const float* bias_e = (const float*)d_in[15];
    const float* oln1_g = (const float*)d_in[16];
    const float* oln1_b = (const float*)d_in[17];
    const float* oln2_g = (const float*)d_in[18];
    const float* oln2_b = (const float*)d_in[19];
    const float* offn1_w= (const float*)d_in[20];
    const float* offn1_b= (const float*)d_in[21];
    const float* offn2_w= (const float*)d_in[22];
    const float* offn2_b= (const float*)d_in[23];
    const int*   eidx   = (const int*)d_in[24];
    const int* src = eidx;
    const int* dst = eidx + En;
    float* out = (float*)d_out;

    float* p_xw  = sym_addr(g_xw);
    float* p_xl  = sym_addr(g_xlocal);
    float* p_qkv = sym_addr(g_qkv);
    float* p_att = sym_addr(g_attn);
    float* p_buf = sym_addr(g_buf);
    float* p_h   = sym_addr(g_h);
    float* p_h2  = sym_addr(g_h2);
    float* p_y   = sym_addr(g_y);
    float* p_ff  = sym_addr(g_ff);

    const int SM128 = (128 + 64) * 20 * 4 * 2;   // 30720
    const int SM64  = (64  + 64) * 20 * 4 * 2;   // 20480
    const int ATTN_SMEM = ATTN_SMEM_U32 * 4;     // 36896
    cudaFuncSetAttribute(gemm_bf16_kernel<128>, cudaFuncAttributeMaxDynamicSharedMemorySize, SM128);
    cudaFuncSetAttribute(gemm_bf16_kernel<64>,  cudaFuncAttributeMaxDynamicSharedMemorySize, SM64);
    cudaFuncSetAttribute(k_fill_xw,    cudaFuncAttributeMaxDynamicSharedMemorySize, SM64);
    cudaFuncSetAttribute(k_qkv_bfs,    cudaFuncAttributeMaxDynamicSharedMemorySize, SM128);
    cudaFuncSetAttribute(k_attn_gather, cudaFuncAttributeMaxDynamicSharedMemorySize, ATTN_SMEM);

    // graph prep
    init_deg_adj_kernel<<<1024, 256>>>();
    edge_prep_kernel<<<En/256, 256>>>(src, dst);
    scan_kernel<<<1, 1024>>>();
    k_fill_xw<<<512 + En/256, 256, SM64>>>(src, dst, x, gcn_w, p_xw);

    // transformer (+ hidden bfs / gather)
    k_qkv_bfs<<<768 + Nn/8, 256, SM128>>>(x, qkv_w, qkv_b, p_qkv);
    k_attn_gather<<<512 + Nn, 256, ATTN_SMEM>>>(bias_e, gcn_b);
    gemm_bf16_kernel<64><<<dim3(Hn/64, Nn/64), 256, SM64>>>(p_att, proj_w, proj_b, p_buf, Hn, Hn, 0);
    ln_kernel<<<Nn, 256>>>(x, p_buf, nullptr, ln1_g, ln1_b, p_h);
    gemm_bf16_kernel<128><<<dim3(FFNn/64, Nn/128), 256, SM128>>>(p_h, ffn1_w, ffn1_b, p_ff, FFNn, Hn, 1);
    gemm_bf16_kernel<64><<<dim3(Hn/64, Nn/64), 256, SM64>>>(p_ff, ffn2_w, ffn2_b, p_buf, Hn, FFNn, 0);
    ln_kernel<<<Nn, 256>>>(p_h, p_buf, nullptr, ln2_g, ln2_b, p_h2);

    // GPS combine + outer FFN
    ln_kernel<<<Nn, 256>>>(x, p_xl, p_h2, oln1_g, oln1_b, p_y);
    gemm_bf16_kernel<128><<<dim3(FFNn/64, Nn/128), 256, SM128>>>(p_y, offn1_w, offn1_b, p_ff, FFNn, Hn, 1);
    gemm_bf16_kernel<64><<<dim3(Hn/64, Nn/64), 256, SM64>>>(p_ff, offn2_w, offn2_b, p_buf, Hn, FFNn, 0);
    ln_kernel<<<Nn, 256>>>(p_y, p_buf, nullptr, oln2_g, oln2_b, out);
}

// round 7
// speedup vs baseline: 3.2947x; 1.0143x over previous
#include <cuda_runtime.h>
#include <cuda_bf16.h>
#include <math.h>

#define Gn 8
#define Mn 1024
#define Hn 256
#define HEADSn 8
#define HDn 32
#define FFNn 1024
#define Nn (Gn*Mn)          // 8192
#define En 131072
#define MWn (Mn/32)         // 32

typedef __nv_bfloat16 bf16;

// ---------------- scratch (device globals: no allocation allowed) ----------
static __device__ float g_xw[Nn*Hn];
static __device__ float g_xlocal[Nn*Hn];
static __device__ float g_dinv[Nn];
static __device__ int   g_deg[Nn];
static __device__ unsigned g_adj[Gn*Mn*MWn];
static __device__ unsigned char g_dist[(size_t)Gn*Mn*Mn];   // 8 MB
static __device__ float g_buf[Nn*Hn];
static __device__ float g_h[Nn*Hn];
static __device__ float g_h2[Nn*Hn];
static __device__ float g_y[Nn*Hn];
static __device__ int   g_off[Nn+1];
static __device__ int   g_cursor[Nn];
static __device__ int   g_eord[En];     // src node per CSR slot (sorted by dst)
// bf16 operand buffers
static __device__ bf16  g_x_bf[Nn*Hn];
static __device__ bf16  g_qkv_bf[Nn*3*Hn];
static __device__ bf16  g_attn_bf[Nn*Hn];
static __device__ bf16  g_h_bf[Nn*Hn];
static __device__ bf16  g_y_bf[Nn*Hn];
static __device__ bf16  g_ff_bf[Nn*FFNn];
// bf16 weights
static __device__ bf16  g_wgcn[Hn*Hn];
static __device__ bf16  g_wqkv[3*Hn*Hn];
static __device__ bf16  g_wproj[Hn*Hn];
static __device__ bf16  g_wf1[FFNn*Hn];
static __device__ bf16  g_wf2[Hn*FFNn];
static __device__ bf16  g_wo1[FFNn*Hn];
static __device__ bf16  g_wo2[Hn*FFNn];

// ---------------- helpers ---------------------------------------------------
__device__ __forceinline__ float gelu_exact(float x) {
    return 0.5f * x * (1.0f + erff(x * 0.7071067811865475f));
}

__device__ __forceinline__ unsigned packbf(float lo, float hi) {
    unsigned r;
    asm("cvt.rn.bf16x2.f32 %0, %1, %2;" : "=r"(r) : "f"(hi), "f"(lo));
    return r;
}

__device__ __forceinline__ void mma_bf16(float c[4], const unsigned a[4],
                                         unsigned b0, unsigned b1) {
    asm volatile(
        "mma.sync.aligned.m16n8k16.row.col.f32.bf16.bf16.f32 "
        "{%0,%1,%2,%3},{%4,%5,%6,%7},{%8,%9},{%0,%1,%2,%3};"
        : "+f"(c[0]), "+f"(c[1]), "+f"(c[2]), "+f"(c[3])
        : "r"(a[0]), "r"(a[1]), "r"(a[2]), "r"(a[3]), "r"(b0), "r"(b1));
}

// ---------------- init: deg=1, adj=0, convert weights+x to bf16 -------------
__device__ __forceinline__ void cvt4seg(const float* __restrict__ s,
                                        bf16* __restrict__ d, int q) {
    float4 v = *(const float4*)(s + (size_t)q*4);
    *(uint2*)(d + (size_t)q*4) = make_uint2(packbf(v.x, v.y), packbf(v.z, v.w));
}

__global__ void init_cvt_kernel(
    const float* __restrict__ x, const float* __restrict__ gcn_w,
    const float* __restrict__ qkv_w, const float* __restrict__ proj_w,
    const float* __restrict__ ffn1_w, const float* __restrict__ ffn2_w,
    const float* __restrict__ offn1_w, const float* __restrict__ offn2_w)
{
    int i = blockIdx.x * blockDim.x + threadIdx.x;
    if (i < Nn) g_deg[i] = 1;
    if (i < Gn*Mn*MWn) g_adj[i] = 0;
    int q = i;
    if (q < 524288) { cvt4seg(x, g_x_bf, q); return; }        q -= 524288;
    if (q < 16384)  { cvt4seg(gcn_w, g_wgcn, q); return; }    q -= 16384;
    if (q < 49152)  { cvt4seg(qkv_w, g_wqkv, q); return; }    q -= 49152;
    if (q < 16384)  { cvt4seg(proj_w, g_wproj, q); return; }  q -= 16384;
    if (q < 65536)  { cvt4seg(ffn1_w, g_wf1, q); return; }    q -= 65536;
    if (q < 65536)  { cvt4seg(ffn2_w, g_wf2, q); return; }    q -= 65536;
    if (q < 65536)  { cvt4seg(offn1_w, g_wo1, q); return; }   q -= 65536;
    if (q < 65536)  { cvt4seg(offn2_w, g_wo2, q); return; }
}

__global__ void edge_prep_kernel(const int* __restrict__ src, const int* __restrict__ dst) {
    int e = blockIdx.x * blockDim.x + threadIdx.x;
    if (e >= En) return;
    int s = src[e], d = dst[e];
    atomicAdd(&g_deg[d], 1);
    if (s != d) {
        int g  = s >> 10;
        int ls = s & 1023, ld = d & 1023;
        atomicOr(&g_adj[(g*Mn + ls)*MWn + (ld >> 5)], 1u << (ld & 31));
        atomicOr(&g_adj[(g*Mn + ld)*MWn + (ls >> 5)], 1u << (ls & 31));
    }
}

// ---------------- scan: offsets + cursor + dinv (1 block, 1024 thr) --------
__global__ __launch_bounds__(1024) void scan_kernel() {
    __shared__ int wsum[32];
    int t = threadIdx.x, lane = t & 31, w = t >> 5;
    int base = t * 8;
    int loc[8]; int s = 0;
#pragma unroll
    for (int j = 0; j < 8; j++) {
        int dg = g_deg[base + j];
        g_dinv[base + j] = rsqrtf((float)dg);
        loc[j] = dg - 1; s += loc[j];
    }
    int inc = s;
#pragma unroll
    for (int d = 1; d < 32; d <<= 1) {
        int v = __shfl_up_sync(0xffffffffu, inc, d);
        if (lane >= d) inc += v;
    }
    if (lane == 31) wsum[w] = inc;
    __syncthreads();
    if (w == 0) {
        int v = wsum[lane];
#pragma unroll
        for (int d = 1; d < 32; d <<= 1) {
            int u = __shfl_up_sync(0xffffffffu, v, d);
            if (lane >= d) v += u;
        }
        wsum[lane] = v;
    }
    __syncthreads();
    int excl = inc - s + (w ? wsum[w-1] : 0);
#pragma unroll
    for (int j = 0; j < 8; j++) {
        g_off[base + j] = excl;
        g_cursor[base + j] = excl;
        excl += loc[j];
    }
    if (t == 1023) g_off[Nn] = excl;
}

// ---------------- body: CSR fill --------------------------------------------
__device__ __forceinline__ void fill_body(int e, const int* __restrict__ src,
                                          const int* __restrict__ dst) {
    if (e >= En) return;
    int d = dst[e];
    int pos = atomicAdd(&g_cursor[d], 1);
    g_eord[pos] = src[e];
}

// ---------------- body: GCN gather (1 block per dst node) -------------------
__device__ __forceinline__ void gather_body(int d, int t, const float* __restrict__ gcn_b) {
    float dinvd = g_dinv[d];
    float acc = g_xw[(size_t)d*Hn + t] * dinvd * dinvd + gcn_b[t];
    int beg = g_off[d], end = g_off[d+1];
    int e = beg;
    for (; e + 2 <= end; e += 2) {
        int s0 = g_eord[e], s1 = g_eord[e+1];
        float w0 = g_dinv[s0] * dinvd;
        float w1 = g_dinv[s1] * dinvd;
        float v0 = g_xw[(size_t)s0*Hn + t];
        float v1 = g_xw[(size_t)s1*Hn + t];
        acc += v0 * w0 + v1 * w1;
    }
    if (e < end) {
        int s0 = g_eord[e];
        acc += g_xw[(size_t)s0*Hn + t] * (g_dinv[s0] * dinvd);
    }
    g_xlocal[(size_t)d*Hn + t] = acc;
}

// ---------------- body: SPD bitset BFS, direction-optimal (warp per row) ---
__device__ __forceinline__ int warp_sum(int v) {
#pragma unroll
    for (int d = 16; d; d >>= 1) v += __shfl_xor_sync(0xffffffffu, v, d);
    return v;
}

__device__ __forceinline__ void bfs_body(int row, int lane) {
    int g = row >> 10, i = row & 1023;
    const unsigned* arow = g_adj + (size_t)row * MWn;
    unsigned frontier = arow[lane];
    unsigned diag = ((i >> 5) == lane) ? (1u << (i & 31)) : 0u;
    unsigned visited = frontier | diag;
    unsigned char* drow = g_dist + (size_t)row * Mn;

#pragma unroll
    for (int p = 0; p < 8; p++) {
        unsigned word = 0;
#pragma unroll
        for (int b = 0; b < 4; b++) {
            int bi = p*4 + b;
            int k = lane*32 + bi;
            unsigned char v = ((frontier >> bi) & 1u) ? 1 : ((k == i) ? 0 : 6);
            word |= ((unsigned)v) << (8*b);
        }
        *(unsigned*)(drow + lane*32 + p*4) = word;
    }

    for (int d = 2; d <= 5; d++) {
        int cf = warp_sum(__popc(frontier));
        if (cf == 0) break;
        int cu = 1024 - warp_sum(__popc(visited));
        if (cu == 0) break;
        unsigned newf = 0;
        if (cf <= cu) {
#pragma unroll 1
            for (int ws = 0; ws < 32; ws++) {
                unsigned fw = __shfl_sync(0xffffffffu, frontier, ws);
                while (fw) {
                    int b = __ffs(fw) - 1; fw &= fw - 1;
                    int j = ws*32 + b;
                    newf |= g_adj[((size_t)g*Mn + j)*MWn + lane];
                }
            }
            newf &= ~visited;
        } else {
            unsigned unv = ~visited;
#pragma unroll 1
            for (int ws = 0; ws < 32; ws++) {
                unsigned uw = __shfl_sync(0xffffffffu, unv, ws);
                while (uw) {
                    int b = __ffs(uw) - 1; uw &= uw - 1;
                    int j = ws*32 + b;
                    unsigned aw = g_adj[((size_t)g*Mn + j)*MWn + lane];
                    unsigned m = __ballot_sync(0xffffffffu, (aw & frontier) != 0u);
                    if (m && lane == ws) newf |= 1u << b;
                }
            }
        }
        visited |= newf;
        unsigned t = newf;
        while (t) {
            int b = __ffs(t) - 1; t &= t - 1;
            drow[lane*32 + b] = (unsigned char)d;
        }
        frontier = newf;
    }
}

// ---------------- body: bf16-source tensor-core GEMM ------------------------
// C[M,Nc] = act(A[M,K] * B[Nc,K]^T + bias). A,B bf16 in gmem; C fp32 or bf16.
// Tile BM x 64, K-step 32, double-buffered smem. 256 threads.
template<int BM>
__device__ __forceinline__ void gemm_body(
    const bf16* __restrict__ A, const bf16* __restrict__ B,
    const float* __restrict__ bias, void* __restrict__ Cv,
    int Nc, int K, int act, int obf, int bx, int by, unsigned* sm)
{
    constexpr int WMW = (BM == 128) ? 4 : 2;
    constexpr int WNW = 8 / WMW;
    constexpr int WTN = 64 / WNW;
    constexpr int NT  = WTN / 8;
    constexpr int A4  = BM / 32;
    constexpr int STG = (BM + 64) * 20;

    int bm = by * BM, bn = bx * 64;
    int tid = threadIdx.x;
    int warp = tid >> 5, lane = tid & 31;
    int wm = warp / WNW, wn = warp % WNW;
    int lr = lane >> 2, lc = lane & 3;

    float acc[2][NT][4];
#pragma unroll
    for (int i = 0; i < 2; i++)
#pragma unroll
        for (int j = 0; j < NT; j++)
#pragma unroll
            for (int r = 0; r < 4; r++) acc[i][j][r] = 0.0f;

    // ---- prologue: load stage 0 ----
    {
        unsigned* AH = sm;
        unsigned* BH = AH + BM*20;
#pragma unroll
        for (int l = 0; l < A4; l++) {
            int e = tid + l*256;
            int row = e >> 3, c4 = (e & 7) * 4, p = (e & 7) * 2;
            *(uint2*)&AH[row*20 + p] = *(const uint2*)(A + (size_t)(bm + row) * K + c4);
        }
#pragma unroll
        for (int l = 0; l < 2; l++) {
            int e = tid + l*256;
            int row = e >> 3, c4 = (e & 7) * 4, p = (e & 7) * 2;
            *(uint2*)&BH[row*20 + p] = *(const uint2*)(B + (size_t)(bn + row) * K + c4);
        }
    }
    __syncthreads();

    int nk = K >> 5;
    for (int it = 0; it < nk; it++) {
        unsigned* AH = sm + (it & 1) * STG;
        unsigned* BH = AH + BM*20;

        // prefetch next k-slab into registers
        uint2 pa[A4], pb2[2];
        bool has = (it + 1 < nk);
        if (has) {
            int k0 = (it + 1) << 5;
#pragma unroll
            for (int l = 0; l < A4; l++) {
                int e = tid + l*256;
                int row = e >> 3, c4 = (e & 7) * 4;
                pa[l] = *(const uint2*)(A + (size_t)(bm + row) * K + k0 + c4);
            }
#pragma unroll
            for (int l = 0; l < 2; l++) {
                int e = tid + l*256;
                int row = e >> 3, c4 = (e & 7) * 4;
                pb2[l] = *(const uint2*)(B + (size_t)(bn + row) * K + k0 + c4);
            }
        }

        // compute on current buffer: two k16 steps
#pragma unroll
        for (int ks = 0; ks < 2; ks++) {
            int pb = ks * 8;
            unsigned ah[2][4];
#pragma unroll
            for (int mt = 0; mt < 2; mt++) {
                int rA = wm*32 + mt*16;
                ah[mt][0] = AH[(rA+lr  )*20 + pb + lc];
                ah[mt][1] = AH[(rA+lr+8)*20 + pb + lc];
                ah[mt][2] = AH[(rA+lr  )*20 + pb + 4 + lc];
                ah[mt][3] = AH[(rA+lr+8)*20 + pb + 4 + lc];
            }
#pragma unroll
            for (int nt = 0; nt < NT; nt++) {
                int cB = wn*WTN + nt*8;
                unsigned bh0 = BH[(cB+lr)*20 + pb + lc];
                unsigned bh1 = BH[(cB+lr)*20 + pb + 4 + lc];
#pragma unroll
                for (int mt = 0; mt < 2; mt++)
                    mma_bf16(acc[mt][nt], ah[mt], bh0, bh1);
            }
        }

        // store next buffer
        if (has) {
            unsigned* nAH = sm + ((it + 1) & 1) * STG;
            unsigned* nBH = nAH + BM*20;
#pragma unroll
            for (int l = 0; l < A4; l++) {
                int e = tid + l*256;
                int row = e >> 3, p = (e & 7) * 2;
                *(uint2*)&nAH[row*20 + p] = pa[l];
            }
#pragma unroll
            for (int l = 0; l < 2; l++) {
                int e = tid + l*256;
                int row = e >> 3, p = (e & 7) * 2;
                *(uint2*)&nBH[row*20 + p] = pb2[l];
            }
        }
        __syncthreads();
    }

    // ---- epilogue ----
#pragma unroll
    for (int mt = 0; mt < 2; mt++) {
#pragma unroll
        for (int nt = 0; nt < NT; nt++) {
            int m = bm + wm*32 + mt*16 + lr;
            int n = bn + wn*WTN + nt*8 + lc*2;
            float b0 = 0.0f, b1 = 0.0f;
            if (bias) { b0 = bias[n]; b1 = bias[n+1]; }
            float v0 = acc[mt][nt][0] + b0;
            float v1 = acc[mt][nt][1] + b1;
            float v2 = acc[mt][nt][2] + b0;
            float v3 = acc[mt][nt][3] + b1;
            if (act) { v0 = gelu_exact(v0); v1 = gelu_exact(v1);
                       v2 = gelu_exact(v2); v3 = gelu_exact(v3); }
            if (obf) {
                bf16* C = (bf16*)Cv;
                *(unsigned*)(C + (size_t)m * Nc + n)     = packbf(v0, v1);
                *(unsigned*)(C + (size_t)(m+8) * Nc + n) = packbf(v2, v3);
            } else {
                float* C = (float*)Cv;
                *(float2*)(C + (size_t)m * Nc + n)     = make_float2(v0, v1);
                *(float2*)(C + (size_t)(m+8) * Nc + n) = make_float2(v2, v3);
            }
        }
    }
}

template<int BM>
__global__ __launch_bounds__(256) void gemm_bf16_kernel(
    const bf16* __restrict__ A, const bf16* __restrict__ B,
    const float* __restrict__ bias, void* __restrict__ C,
    int Nc, int K, int act, int obf)
{
    extern __shared__ unsigned sm[];
    gemm_body<BM>(A, B, bias, C, Nc, K, act, obf, blockIdx.x, blockIdx.y, sm);
}

// ---------------- attention: all-bf16 src, register softmax, double-buffer -
// smem layout (u32 offsets):
//   Ks[2]  : 0    + s*1280  (64 rows x 20 u32)
//   VsT[2] : 2560 + s*1152  (32 rows x 36 u32)
//   ds[2]  : 4864 + s*2176  (128 rows x 17 u32)
//   btab   : 9216 (8 floats)
#define ATTN_SMEM_U32 9224

__device__ __forceinline__ void attn_body(const float* __restrict__ bias_emb,
                                          int g, int head, int q0, unsigned* sm) {
    int tid = threadIdx.x;
    int warp = tid >> 5, lane = tid & 31;
    int lr = lane >> 2, lc = lane & 3;
    int qb = warp * 16;
    const float scale = 0.17677669529663687f;   // 32^-0.5

    float* btab = (float*)(sm + 9216);
    if (tid < 7) btab[tid] = bias_emb[tid];

    // Q fragments in registers (bf16; scale folded into post-MMA FMA)
    unsigned aq[2][4];
    {
        size_t r0 = (size_t)(g*Mn + q0 + qb + lr)*768 + head*32;
        size_t r1 = (size_t)(g*Mn + q0 + qb + lr + 8)*768 + head*32;
#pragma unroll
        for (int ch = 0; ch < 2; ch++) {
            aq[ch][0] = *(const unsigned*)(g_qkv_bf + r0 + 16*ch + 2*lc);
            aq[ch][1] = *(const unsigned*)(g_qkv_bf + r1 + 16*ch + 2*lc);
            aq[ch][2] = *(const unsigned*)(g_qkv_bf + r0 + 16*ch + 8 + 2*lc);
            aq[ch][3] = *(const unsigned*)(g_qkv_bf + r1 + 16*ch + 8 + 2*lc);
        }
    }

    float acc[4][4];
#pragma unroll
    for (int i = 0; i < 4; i++)
#pragma unroll
        for (int j = 0; j < 4; j++) acc[i][j] = 0.0f;
    float m0 = -1e30f, m1 = -1e30f, l0 = 0.0f, l1 = 0.0f;

    // ---- coop load tile 0 into stage 0 ----
    {
        unsigned* Ks = sm;
        bf16* Vt16 = (bf16*)(sm + 2560);
        unsigned* ds = sm + 4864;
#pragma unroll
        for (int l = 0; l < 4; l++) {
            int e = tid + l*256;
            int row = e >> 4, j = e & 15;
            size_t base = (size_t)(g*Mn + row)*768 + head*32 + 2*j;
            Ks[row*20 + j] = *(const unsigned*)(g_qkv_bf + base + 256);
            __nv_bfloat162 vv = *(const __nv_bfloat162*)(g_qkv_bf + base + 512);
            Vt16[(2*j)*72 + row]   = vv.x;
            Vt16[(2*j+1)*72 + row] = vv.y;
        }
#pragma unroll
        for (int l = 0; l < 2; l++) {
            int e = tid + l*256;
            int row = e >> 2, qd = e & 3;
            uint4 dv = *(const uint4*)&g_dist[(size_t)(g*Mn + q0 + row)*Mn + qd*16];
            ds[row*17 + qd*4 + 0] = dv.x;
            ds[row*17 + qd*4 + 1] = dv.y;
            ds[row*17 + qd*4 + 2] = dv.z;
            ds[row*17 + qd*4 + 3] = dv.w;
        }
    }
    __syncthreads();

    for (int tk = 0; tk < 16; tk++) {
        int s = tk & 1;
        unsigned* Ks = sm + s*1280;
        unsigned* Vt = sm + 2560 + s*1152;
        const unsigned short* ds16 = (const unsigned short*)(sm + 4864 + s*2176);

        // prefetch next tile
        unsigned pk[4];
        __nv_bfloat162 pv[4];
        uint4 pd[2];
        bool has = (tk + 1 < 16);
        if (has) {
            int krow0 = (tk + 1) * 64;
#pragma unroll
            for (int l = 0; l < 4; l++) {
                int e = tid + l*256;
                int row = e >> 4, j = e & 15;
                size_t base = (size_t)(g*Mn + krow0 + row)*768 + head*32 + 2*j;
                pk[l] = *(const unsigned*)(g_qkv_bf + base + 256);
                pv[l] = *(const __nv_bfloat162*)(g_qkv_bf + base + 512);
            }
#pragma unroll
            for (int l = 0; l < 2; l++) {
                int e = tid + l*256;
                int row = e >> 2, qd = e & 3;
                pd[l] = *(const uint4*)&g_dist[(size_t)(g*Mn + q0 + row)*Mn + krow0 + qd*16];
            }
        }

        // ---- QK^T ----
        float sc[8][4];
#pragma unroll
        for (int nt = 0; nt < 8; nt++)
#pragma unroll
            for (int r = 0; r < 4; r++) sc[nt][r] = 0.0f;
#pragma unroll
        for (int ch = 0; ch < 2; ch++) {
#pragma unroll
            for (int nt = 0; nt < 8; nt++) {
                unsigned b0 = Ks[(nt*8+lr)*20 + 8*ch + lc];
                unsigned b1 = Ks[(nt*8+lr)*20 + 8*ch + 4 + lc];
                mma_bf16(sc[nt], aq[ch], b0, b1);
            }
        }

        // ---- scale + bias + row max (registers) ----
        float mn0 = m0, mn1 = m1;
#pragma unroll
        for (int nt = 0; nt < 8; nt++) {
            unsigned short w0 = ds16[(qb+lr)*34 + nt*4 + lc];
            unsigned short w1 = ds16[(qb+lr+8)*34 + nt*4 + lc];
            sc[nt][0] = fmaf(sc[nt][0], scale, btab[w0 & 255]);
            sc[nt][1] = fmaf(sc[nt][1], scale, btab[w0 >> 8]);
            sc[nt][2] = fmaf(sc[nt][2], scale, btab[w1 & 255]);
            sc[nt][3] = fmaf(sc[nt][3], scale, btab[w1 >> 8]);
            mn0 = fmaxf(mn0, fmaxf(sc[nt][0], sc[nt][1]));
            mn1 = fmaxf(mn1, fmaxf(sc[nt][2], sc[nt][3]));
        }
        mn0 = fmaxf(mn0, __shfl_xor_sync(0xffffffffu, mn0, 1));
        mn0 = fmaxf(mn0, __shfl_xor_sync(0xffffffffu, mn0, 2));
        mn1 = fmaxf(mn1, __shfl_xor_sync(0xffffffffu, mn1, 1));
        mn1 = fmaxf(mn1, __shfl_xor_sync(0xffffffffu, mn1, 2));
        float f0 = __expf(m0 - mn0);
        float f1 = __expf(m1 - mn1);

        // ---- exp + sum + pack P ----
        float rs0 = 0.0f, rs1 = 0.0f;
#pragma unroll
        for (int nt = 0; nt < 8; nt++) {
            float e0 = __expf(sc[nt][0] - mn0);
            float e1 = __expf(sc[nt][1] - mn0);
            float e2 = __expf(sc[nt][2] - mn1);
            float e3 = __expf(sc[nt][3] - mn1);
            rs0 += e0 + e1; rs1 += e2 + e3;
            sc[nt][0] = e0; sc[nt][1] = e1; sc[nt][2] = e2; sc[nt][3] = e3;
        }
        unsigned P[4][4];
#pragma unroll
        for (int ch = 0; ch < 4; ch++) {
            P[ch][0] = packbf(sc[2*ch][0],   sc[2*ch][1]);
            P[ch][1] = packbf(sc[2*ch][2],   sc[2*ch][3]);
            P[ch][2] = packbf(sc[2*ch+1][0], sc[2*ch+1][1]);
            P[ch][3] = packbf(sc[2*ch+1][2], sc[2*ch+1][3]);
        }
        rs0 += __shfl_xor_sync(0xffffffffu, rs0, 1);
        rs0 += __shfl_xor_sync(0xffffffffu, rs0, 2);
        rs1 += __shfl_xor_sync(0xffffffffu, rs1, 1);
        rs1 += __shfl_xor_sync(0xffffffffu, rs1, 2);
        l0 = l0*f0 + rs0; l1 = l1*f1 + rs1;
        m0 = mn0; m1 = mn1;

        // ---- rescale + PV ----
#pragma unroll
        for (int dt = 0; dt < 4; dt++) {
            acc[dt][0] *= f0; acc[dt][1] *= f0;
            acc[dt][2] *= f1; acc[dt][3] *= f1;
        }
#pragma unroll
        for (int ch = 0; ch < 4; ch++) {
#pragma unroll
            for (int dt = 0; dt < 4; dt++) {
                unsigned b0 = Vt[(dt*8+lr)*36 + 8*ch + lc];
                unsigned b1 = Vt[(dt*8+lr)*36 + 8*ch + 4 + lc];
                mma_bf16(acc[dt], P[ch], b0, b1);
            }
        }

        // ---- store prefetched tile into other stage ----
        if (has) {
            unsigned* nKs = sm + (s^1)*1280;
            bf16* nVt16 = (bf16*)(sm + 2560 + (s^1)*1152);
            unsigned* nds = sm + 4864 + (s^1)*2176;
#pragma unroll
            for (int l = 0; l < 4; l++) {
                int e = tid + l*256;
                int row = e >> 4, j = e & 15;
                nKs[row*20 + j] = pk[l];
                nVt16[(2*j)*72 + row]   = pv[l].x;
                nVt16[(2*j+1)*72 + row] = pv[l].y;
            }
#pragma unroll
            for (int l = 0; l < 2; l++) {
                int e = tid + l*256;
                int row = e >> 2, qd = e & 3;
                nds[row*17 + qd*4 + 0] = pd[l].x;
                nds[row*17 + qd*4 + 1] = pd[l].y;
                nds[row*17 + qd*4 + 2] = pd[l].z;
                nds[row*17 + qd*4 + 3] = pd[l].w;
            }
        }
        __syncthreads();
    }

    // ---- epilogue: write bf16 for proj GEMM ----
    float il0 = 1.0f / l0, il1 = 1.0f / l1;
#pragma unroll
    for (int dt = 0; dt < 4; dt++) {
        int d = head*32 + dt*8 + 2*lc;
        *(unsigned*)(g_attn_bf + (size_t)(g*Mn + q0 + qb + lr  )*Hn + d) =
            packbf(acc[dt][0]*il0, acc[dt][1]*il0);
        *(unsigned*)(g_attn_bf + (size_t)(g*Mn + q0 + qb + lr+8)*Hn + d) =
            packbf(acc[dt][2]*il1, acc[dt][3]*il1);
    }
}

// ---------------- fused launches --------------------------------------------
__global__ __launch_bounds__(256) void k_fill_xw(
    const int* __restrict__ src, const int* __restrict__ dst,
    float* __restrict__ xw)
{
    extern __shared__ unsigned sm[];
    int bid = blockIdx.x;
    if (bid < 512) {
        gemm_body<64>(g_x_bf, g_wgcn, nullptr, xw, 256, 256, 0, 0, bid & 3, bid >> 2, sm);
    } else {
        fill_body((bid - 512) * 256 + threadIdx.x, src, dst);
    }
}

__global__ __launch_bounds__(256) void k_qkv_bfs(const float* __restrict__ qkv_b)
{
    extern __shared__ unsigned sm[];
    int bid = blockIdx.x;
    if (bid < 768) {
        gemm_body<128>(g_x_bf, g_wqkv, qkv_b, g_qkv_bf, 768, 256, 0, 1, bid % 12, bid / 12, sm);
    } else {
        int row = (bid - 768) * 8 + (threadIdx.x >> 5);
        bfs_body(row, threadIdx.x & 31);
    }
}

__global__ __launch_bounds__(256) void k_attn_gather(
    const float* __restrict__ bias_emb, const float* __restrict__ gcn_b)
{
    extern __shared__ unsigned sm[];
    int bid = blockIdx.x;
    if (bid < 512) {
        attn_body(bias_emb, bid >> 6, (bid >> 3) & 7, (bid & 7) * 128, sm);
    } else {
        gather_body(bid - 512, threadIdx.x, gcn_b);
    }
}

// ---------------- LayerNorm: out = LN(a [+ b] [+ c]) * gamma + beta --------
__global__ __launch_bounds__(256) void ln_kernel(
    const float* __restrict__ a, const float* __restrict__ b, const float* __restrict__ c,
    const float* __restrict__ gam, const float* __restrict__ bet,
    float* __restrict__ out, bf16* __restrict__ outb)
{
    __shared__ float s1[8], s2[8];
    int row = blockIdx.x, t = threadIdx.x;
    int w = t >> 5;
    size_t off = (size_t)row * Hn + t;
    float v = a[off];
    if (b) v += b[off];
    if (c) v += c[off];
    float su = v, sq = v * v;
#pragma unroll
    for (int d = 16; d; d >>= 1) {
        su += __shfl_xor_sync(0xffffffffu, su, d);
        sq += __shfl_xor_sync(0xffffffffu, sq, d);
    }
    if ((t & 31) == 0) { s1[w] = su; s2[w] = sq; }
    __syncthreads();
    su = 0.0f; sq = 0.0f;
#pragma unroll
    for (int j = 0; j < 8; j++) { su += s1[j]; sq += s2[j]; }
    float mean = su * (1.0f / Hn);
    float var = sq * (1.0f / Hn) - mean * mean;
    float r = (v - mean) * rsqrtf(var + 1e-5f) * gam[t] + bet[t];
    out[off] = r;
    if (outb) outb[off] = __float2bfloat16(r);
}

// ---------------- host launch ----------------------------------------------
static void* sym_addr(const void* s) {
    void* p = nullptr;
    cudaGetSymbolAddress(&p, s);
    return p;
}

extern "C" void kernel_launch(void* const* d_in, const int* in_sizes, int n_in,
                              void* d_out, int out_size) {
    const float* x      = (const float*)d_in[0];
    const float* gcn_w  = (const float*)d_in[1];
    const float* gcn_b  = (const float*)d_in[2];
    const float* qkv_w  = (const float*)d_in[3];
    const float* qkv_b  = (const float*)d_in[4];
    const float* proj_w = (const float*)d_in[5];
    const float* proj_b = (const float*)d_in[6];
    const float* ln1_g  = (const float*)d_in[7];
    const float* ln1_b  = (const float*)d_in[8];
    const float* ln2_g  = (const float*)d_in[9];
    const float* ln2_b  = (const float*)d_in[10];
    const float* ffn1_w = (const float*)d_in[11];
    const float* ffn1_b = (const float*)d_in[12];
    const float* ffn2_w = (const float*)d_in[13];
    const float* ffn2_b = (const float*)d_in[14];
    const float* bias_e = (const float*)d_in[15];
    const float* oln1_g = (const float*)d_in[16];
    const float* oln1_b = (const float*)d_in[17];
    const float* oln2_g = (const float*)d_in[18];
    const float* oln2_b = (const float*)d_in[19];
    const float* offn1_w= (const float*)d_in[20];
    const float* offn1_b= (const float*)d_in[21];
    const float* offn2_w= (const float*)d_in[22];
    const float* offn2_b= (const float*)d_in[23];
    const int*   eidx   = (const int*)d_in[24];
    const int* src = eidx;
    const int* dst = eidx + En;
    float* out = (float*)d_out;

    float* p_xw  = (float*)sym_addr(g_xw);
    float* p_xl  = (float*)sym_addr(g_xlocal);
    float* p_buf = (float*)sym_addr(g_buf);
    float* p_h   = (float*)sym_addr(g_h);
    float* p_h2  = (float*)sym_addr(g_h2);
    float* p_y   = (float*)sym_addr(g_y);
    bf16* p_attb = (bf16*)sym_addr(g_attn_bf);
    bf16* p_hb   = (bf16*)sym_addr(g_h_bf);
    bf16* p_yb   = (bf16*)sym_addr(g_y_bf);
    bf16* p_ffb  = (bf16*)sym_addr(g_ff_bf);
    bf16* p_wproj= (bf16*)sym_addr(g_wproj);
    bf16* p_wf1  = (bf16*)sym_addr(g_wf1);
    bf16* p_wf2  = (bf16*)sym_addr(g_wf2);
    bf16* p_wo1  = (bf16*)sym_addr(g_wo1);
    bf16* p_wo2  = (bf16*)sym_addr(g_wo2);

    const int SM128 = (128 + 64) * 20 * 4 * 2;   // 30720
    const int SM64  = (64  + 64) * 20 * 4 * 2;   // 20480
    const int ATTN_SMEM = ATTN_SMEM_U32 * 4;     // 36896
    cudaFuncSetAttribute(gemm_bf16_kernel<128>, cudaFuncAttributeMaxDynamicSharedMemorySize, SM128);
    cudaFuncSetAttribute(gemm_bf16_kernel<64>,  cudaFuncAttributeMaxDynamicSharedMemorySize, SM64);
    cudaFuncSetAttribute(k_fill_xw,    cudaFuncAttributeMaxDynamicSharedMemorySize, SM64);
    cudaFuncSetAttribute(k_qkv_bfs,    cudaFuncAttributeMaxDynamicSharedMemorySize, SM128);
    cudaFuncSetAttribute(k_attn_gather, cudaFuncAttributeMaxDynamicSharedMemorySize, ATTN_SMEM);

    // graph prep + bf16 conversion
    init_cvt_kernel<<<3392, 256>>>(x, gcn_w, qkv_w, proj_w, ffn1_w, ffn2_w, offn1_w, offn2_w);
    edge_prep_kernel<<<En/256, 256>>>(src, dst);
    scan_kernel<<<1, 1024>>>();
    k_fill_xw<<<512 + En/256, 256, SM64>>>(src, dst, p_xw);

    // transformer (+ hidden bfs / gather)
    k_qkv_bfs<<<768 + Nn/8, 256, SM128>>>(qkv_b);
    k_attn_gather<<<512 + Nn, 256, ATTN_SMEM>>>(bias_e, gcn_b);
    gemm_bf16_kernel<64><<<dim3(4, 128), 256, SM64>>>(p_attb, p_wproj, proj_b, p_buf, Hn, Hn, 0, 0);
    ln_kernel<<<Nn, 256>>>(x, p_buf, nullptr, ln1_g, ln1_b, p_h, p_hb);
    gemm_bf16_kernel<128><<<dim3(16, 64), 256, SM128>>>(p_hb, p_wf1, ffn1_b, p_ffb, FFNn, Hn, 1, 1);
    gemm_bf16_kernel<64><<<dim3(4, 128), 256, SM64>>>(p_ffb, p_wf2, ffn2_b, p_buf, Hn, FFNn, 0, 0);
    ln_kernel<<<Nn, 256>>>(p_h, p_buf, nullptr, ln2_g, ln2_b, p_h2, nullptr);

    // GPS combine + outer FFN
    ln_kernel<<<Nn, 256>>>(x, p_xl, p_h2, oln1_g, oln1_b, p_y, p_yb);
    gemm_bf16_kernel<128><<<dim3(16, 64), 256, SM128>>>(p_yb, p_wo1, offn1_b, p_ffb, FFNn, Hn, 1, 1);
    gemm_bf16_kernel<64><<<dim3(4, 128), 256, SM64>>>(p_ffb, p_wo2, offn2_b, p_buf, Hn, FFNn, 0, 0);
    ln_kernel<<<Nn, 256>>>(p_y, p_buf, nullptr, oln2_g, oln2_b, out, nullptr);
}